// round 2
// baseline (speedup 1.0000x reference)
#include <cuda_runtime.h>

// ---------------------------------------------------------------------------
// TransformerLayer: B=4, S=2048, D=1024, H=16, HD=64, FF=4096, fp32.
// Round 1: correct fp32 baseline. SGEMM 128x128x8 tiles (FMA-bound),
// flash-attention 64x64 tiles with online softmax.
// ---------------------------------------------------------------------------

constexpr int Bb = 4, Ss = 2048, Dd = 1024, Hh = 16, HDd = 64, FFf = 4096;
constexpr int Mm = Bb * Ss;            // 8192 rows
constexpr float EPS = 1e-5f;
constexpr float SCALE = 0.125f;        // 1/sqrt(64)

// Scratch (module-load allocated; no runtime alloc)
__device__ float g_h  [Mm * Dd];
__device__ float g_q  [Mm * Dd];
__device__ float g_k  [Mm * Dd];
__device__ float g_v  [Mm * Dd];
__device__ float g_o  [Mm * Dd];
__device__ float g_x2 [Mm * Dd];
__device__ float g_ff1[(size_t)Mm * FFf];

// ---------------------------------------------------------------------------
// LayerNorm: one block per row (D=1024), 256 threads, float4 per thread.
// ---------------------------------------------------------------------------
__global__ void __launch_bounds__(256) ln_kernel(
    const float* __restrict__ x, const float* __restrict__ g,
    const float* __restrict__ b, float* __restrict__ out)
{
    int row = blockIdx.x;
    int t = threadIdx.x;
    const float4 v = reinterpret_cast<const float4*>(x + (size_t)row * Dd)[t];
    float s  = v.x + v.y + v.z + v.w;
    float ss = v.x * v.x + v.y * v.y + v.z * v.z + v.w * v.w;
#pragma unroll
    for (int o = 16; o > 0; o >>= 1) {
        s  += __shfl_xor_sync(0xffffffffu, s,  o);
        ss += __shfl_xor_sync(0xffffffffu, ss, o);
    }
    __shared__ float red[16];
    int w = t >> 5;
    if ((t & 31) == 0) { red[w] = s; red[8 + w] = ss; }
    __syncthreads();
    float st = 0.f, sst = 0.f;
#pragma unroll
    for (int i = 0; i < 8; i++) { st += red[i]; sst += red[8 + i]; }
    float mu  = st  * (1.0f / Dd);
    float var = sst * (1.0f / Dd) - mu * mu;
    float inv = rsqrtf(var + EPS);
    float4 gg = reinterpret_cast<const float4*>(g)[t];
    float4 bb = reinterpret_cast<const float4*>(b)[t];
    float4 o4;
    o4.x = (v.x - mu) * inv * gg.x + bb.x;
    o4.y = (v.y - mu) * inv * gg.y + bb.y;
    o4.z = (v.z - mu) * inv * gg.z + bb.z;
    o4.w = (v.w - mu) * inv * gg.w + bb.w;
    reinterpret_cast<float4*>(out + (size_t)row * Dd)[t] = o4;
}

// ---------------------------------------------------------------------------
// SGEMM: C[M,N] = A[M,K] @ B[K,N] (row-major), 128x128x8 tile, 256 thr, 8x8/thr.
// MODE bits: 1=bias, 2=relu, 4=residual-add (after relu), 8=qkv layout remap.
// ---------------------------------------------------------------------------
constexpr int MD_BIAS = 1, MD_RELU = 2, MD_RES = 4, MD_QKV = 8;

template <int MODE>
__global__ void __launch_bounds__(256) sgemm_kernel(
    const float* __restrict__ A, const float* __restrict__ Bm,
    const float* __restrict__ bias, const float* __restrict__ res,
    float* __restrict__ C, int M, int N, int K)
{
    constexpr int BM = 128, BN = 128, BK = 8;
    __shared__ float As[BK][BM];
    __shared__ float Bs[BK][BN];

    int tid = threadIdx.x;
    int tr = tid >> 4, tc = tid & 15;
    int m0 = blockIdx.y * BM, n0 = blockIdx.x * BN;

    float acc[8][8];
#pragma unroll
    for (int i = 0; i < 8; i++)
#pragma unroll
        for (int j = 0; j < 8; j++) acc[i][j] = 0.f;

    int arow = tid >> 1, acol = (tid & 1) << 2;       // A: 128 rows x 8 cols
    int brw  = tid >> 5, bcl  = (tid & 31) << 2;      // B: 8 rows x 128 cols

    const float* Ap = A + (size_t)(m0 + arow) * K + acol;
    const float* Bp = Bm + (size_t)brw * N + n0 + bcl;

    for (int k0 = 0; k0 < K; k0 += BK) {
        float4 a4 = *reinterpret_cast<const float4*>(Ap + k0);
        As[acol + 0][arow] = a4.x;
        As[acol + 1][arow] = a4.y;
        As[acol + 2][arow] = a4.z;
        As[acol + 3][arow] = a4.w;
        float4 b4 = *reinterpret_cast<const float4*>(Bp + (size_t)k0 * N);
        *reinterpret_cast<float4*>(&Bs[brw][bcl]) = b4;
        __syncthreads();

#pragma unroll
        for (int kk = 0; kk < BK; kk++) {
            float a[8], bb[8];
            *reinterpret_cast<float4*>(&a[0])  = *reinterpret_cast<const float4*>(&As[kk][tr * 4]);
            *reinterpret_cast<float4*>(&a[4])  = *reinterpret_cast<const float4*>(&As[kk][64 + tr * 4]);
            *reinterpret_cast<float4*>(&bb[0]) = *reinterpret_cast<const float4*>(&Bs[kk][tc * 4]);
            *reinterpret_cast<float4*>(&bb[4]) = *reinterpret_cast<const float4*>(&Bs[kk][64 + tc * 4]);
#pragma unroll
            for (int i = 0; i < 8; i++)
#pragma unroll
                for (int j = 0; j < 8; j++)
                    acc[i][j] = fmaf(a[i], bb[j], acc[i][j]);
        }
        __syncthreads();
    }

    // Epilogue
#pragma unroll
    for (int i = 0; i < 8; i++) {
        int row = m0 + tr * 4 + (i & 3) + ((i >> 2) << 6);
#pragma unroll
        for (int jh = 0; jh < 2; jh++) {
            int col = n0 + tc * 4 + jh * 64;
            float4 r4;
            r4.x = acc[i][jh * 4 + 0];
            r4.y = acc[i][jh * 4 + 1];
            r4.z = acc[i][jh * 4 + 2];
            r4.w = acc[i][jh * 4 + 3];
            if (MODE & MD_BIAS) {
                float4 bb = *reinterpret_cast<const float4*>(bias + col);
                r4.x += bb.x; r4.y += bb.y; r4.z += bb.z; r4.w += bb.w;
            }
            if (MODE & MD_RELU) {
                r4.x = fmaxf(r4.x, 0.f); r4.y = fmaxf(r4.y, 0.f);
                r4.z = fmaxf(r4.z, 0.f); r4.w = fmaxf(r4.w, 0.f);
            }
            if (MODE & MD_RES) {
                float4 rr = *reinterpret_cast<const float4*>(res + (size_t)row * N + col);
                r4.x += rr.x; r4.y += rr.y; r4.z += rr.z; r4.w += rr.w;
            }
            if (MODE & MD_QKV) {
                // row = b*S + s ; col = head*64 + d -> out[((b*H+head)*S+s)*64+d]
                int b_ = row >> 11, s_ = row & (Ss - 1);
                int h_ = col >> 6, d_ = col & 63;
                *reinterpret_cast<float4*>(C +
                    ((size_t)(b_ * Hh + h_) * Ss + s_) * HDd + d_) = r4;
            } else {
                *reinterpret_cast<float4*>(C + (size_t)row * N + col) = r4;
            }
        }
    }
}

// ---------------------------------------------------------------------------
// Flash attention: q,k,v in [B*H, S, 64]; o written as [B, S, D].
// Block = 256 thr handles one (bh, 64-row q-tile); loops 32 k-tiles of 64.
// Smem: QsT (d-major, scaled), KP (K d-major, then reused for P row-major), Vs.
// ---------------------------------------------------------------------------
__global__ void __launch_bounds__(256) attn_kernel(
    const float* __restrict__ q, const float* __restrict__ k,
    const float* __restrict__ v, float* __restrict__ o)
{
    __shared__ float QsT[64][64];   // [d][row]
    __shared__ float KP [64][64];   // KsT [d][col], then Ps [row][col]
    __shared__ float Vs [64][64];   // [key][d]

    int tid = threadIdx.x;
    int tr = tid >> 4, tc = tid & 15;
    int bh = blockIdx.y;
    int q0 = blockIdx.x * 64;

    const float* qb = q + ((size_t)bh * Ss + q0) * HDd;
    const float* kb = k + (size_t)bh * Ss * HDd;
    const float* vb = v + (size_t)bh * Ss * HDd;

    // Load Q transposed, pre-scaled
    {
        int r = tid >> 2;
        const float4* qr = reinterpret_cast<const float4*>(qb + r * HDd);
#pragma unroll
        for (int c4 = 0; c4 < 4; c4++) {
            int dc = (tid & 3) + c4 * 4;
            float4 a = qr[dc];
            int d = dc * 4;
            QsT[d + 0][r] = a.x * SCALE;
            QsT[d + 1][r] = a.y * SCALE;
            QsT[d + 2][r] = a.z * SCALE;
            QsT[d + 3][r] = a.w * SCALE;
        }
    }

    float accO[4][4];
    float m_i[4], l_i[4];
#pragma unroll
    for (int i = 0; i < 4; i++) {
        m_i[i] = -1e30f; l_i[i] = 0.f;
#pragma unroll
        for (int c = 0; c < 4; c++) accO[i][c] = 0.f;
    }

    for (int kt = 0; kt < Ss; kt += 64) {
        // Load K (transposed) and V (natural)
        {
            int r = tid >> 2;
            const float4* kr = reinterpret_cast<const float4*>(kb + (size_t)(kt + r) * HDd);
            const float4* vr = reinterpret_cast<const float4*>(vb + (size_t)(kt + r) * HDd);
#pragma unroll
            for (int c4 = 0; c4 < 4; c4++) {
                int dc = (tid & 3) + c4 * 4;
                float4 a = kr[dc];
                int d = dc * 4;
                KP[d + 0][r] = a.x;
                KP[d + 1][r] = a.y;
                KP[d + 2][r] = a.z;
                KP[d + 3][r] = a.w;
                *reinterpret_cast<float4*>(&Vs[r][dc * 4]) = vr[dc];
            }
        }
        __syncthreads();

        // Scores: sc[i][j] = sum_d QsT[d][4tr+i] * KsT[d][4tc+j]
        float sc[4][4];
#pragma unroll
        for (int i = 0; i < 4; i++)
#pragma unroll
            for (int j = 0; j < 4; j++) sc[i][j] = 0.f;

#pragma unroll 8
        for (int d = 0; d < 64; d++) {
            float aq[4], ak[4];
            *reinterpret_cast<float4*>(&aq[0]) = *reinterpret_cast<const float4*>(&QsT[d][tr * 4]);
            *reinterpret_cast<float4*>(&ak[0]) = *reinterpret_cast<const float4*>(&KP[d][tc * 4]);
#pragma unroll
            for (int i = 0; i < 4; i++)
#pragma unroll
                for (int j = 0; j < 4; j++)
                    sc[i][j] = fmaf(aq[i], ak[j], sc[i][j]);
        }

        // Online softmax (row groups = 16 consecutive lanes; xor shuffles stay in group)
        float pr[4][4];
#pragma unroll
        for (int i = 0; i < 4; i++) {
            float tm = fmaxf(fmaxf(sc[i][0], sc[i][1]), fmaxf(sc[i][2], sc[i][3]));
#pragma unroll
            for (int off = 1; off < 16; off <<= 1)
                tm = fmaxf(tm, __shfl_xor_sync(0xffffffffu, tm, off));
            float nm = fmaxf(m_i[i], tm);
            float corr = __expf(m_i[i] - nm);
            m_i[i] = nm;
            float ps = 0.f;
#pragma unroll
            for (int j = 0; j < 4; j++) {
                pr[i][j] = __expf(sc[i][j] - nm);
                ps += pr[i][j];
            }
#pragma unroll
            for (int off = 1; off < 16; off <<= 1)
                ps += __shfl_xor_sync(0xffffffffu, ps, off);
            l_i[i] = l_i[i] * corr + ps;
#pragma unroll
            for (int c = 0; c < 4; c++) accO[i][c] *= corr;
        }

        __syncthreads();   // everyone done reading KP as K
#pragma unroll
        for (int i = 0; i < 4; i++) {
            float4 p4;
            p4.x = pr[i][0]; p4.y = pr[i][1]; p4.z = pr[i][2]; p4.w = pr[i][3];
            *reinterpret_cast<float4*>(&KP[tr * 4 + i][tc * 4]) = p4;
        }
        __syncthreads();   // P visible to all

        // O += P @ V
#pragma unroll 4
        for (int j = 0; j < 64; j += 4) {
            float pv[4][4], vv[4][4];
#pragma unroll
            for (int i = 0; i < 4; i++)
                *reinterpret_cast<float4*>(&pv[i][0]) =
                    *reinterpret_cast<const float4*>(&KP[tr * 4 + i][j]);
#pragma unroll
            for (int jj = 0; jj < 4; jj++)
                *reinterpret_cast<float4*>(&vv[jj][0]) =
                    *reinterpret_cast<const float4*>(&Vs[j + jj][tc * 4]);
#pragma unroll
            for (int i = 0; i < 4; i++)
#pragma unroll
                for (int c = 0; c < 4; c++) {
#pragma unroll
                    for (int jj = 0; jj < 4; jj++)
                        accO[i][c] = fmaf(pv[i][jj], vv[jj][c], accO[i][c]);
                }
        }
        __syncthreads();   // safe to overwrite KP/Vs next iter
    }

    // Epilogue: normalize and write into [B,S,D] layout
    int b_ = bh >> 4, h_ = bh & 15;
#pragma unroll
    for (int i = 0; i < 4; i++) {
        float invl = 1.0f / l_i[i];
        int srow = q0 + tr * 4 + i;
        float4 r4;
        r4.x = accO[i][0] * invl;
        r4.y = accO[i][1] * invl;
        r4.z = accO[i][2] * invl;
        r4.w = accO[i][3] * invl;
        *reinterpret_cast<float4*>(o + ((size_t)(b_ * Ss + srow)) * Dd + h_ * HDd + tc * 4) = r4;
    }
}

// ---------------------------------------------------------------------------
// Launch sequence (graph-capturable: plain launches only)
// ---------------------------------------------------------------------------
extern "C" void kernel_launch(void* const* d_in, const int* in_sizes, int n_in,
                              void* d_out, int out_size)
{
    const float* x     = (const float*)d_in[0];
    const float* ln1_g = (const float*)d_in[1];
    const float* ln1_b = (const float*)d_in[2];
    const float* ln2_g = (const float*)d_in[3];
    const float* ln2_b = (const float*)d_in[4];
    const float* Wq    = (const float*)d_in[5];
    const float* Wk    = (const float*)d_in[6];
    const float* Wv    = (const float*)d_in[7];
    const float* Wo    = (const float*)d_in[8];
    const float* W1    = (const float*)d_in[9];
    const float* b1    = (const float*)d_in[10];
    const float* W2    = (const float*)d_in[11];
    const float* b2    = (const float*)d_in[12];
    float* out = (float*)d_out;

    float *h, *q, *k, *v, *o, *x2, *ff1;
    cudaGetSymbolAddress((void**)&h,   g_h);
    cudaGetSymbolAddress((void**)&q,   g_q);
    cudaGetSymbolAddress((void**)&k,   g_k);
    cudaGetSymbolAddress((void**)&v,   g_v);
    cudaGetSymbolAddress((void**)&o,   g_o);
    cudaGetSymbolAddress((void**)&x2,  g_x2);
    cudaGetSymbolAddress((void**)&ff1, g_ff1);

    dim3 blk(256);
    dim3 gp(Dd / 128, Mm / 128);     // (8, 64) for N=1024 GEMMs
    dim3 gf(FFf / 128, Mm / 128);    // (32, 64) for N=4096

    // h = LN1(x)
    ln_kernel<<<Mm, blk>>>(x, ln1_g, ln1_b, h);
    // q,k,v = h @ W{q,k,v}  (remapped to [B,H,S,HD])
    sgemm_kernel<MD_QKV><<<gp, blk>>>(h, Wq, nullptr, nullptr, q, Mm, Dd, Dd);
    sgemm_kernel<MD_QKV><<<gp, blk>>>(h, Wk, nullptr, nullptr, k, Mm, Dd, Dd);
    sgemm_kernel<MD_QKV><<<gp, blk>>>(h, Wv, nullptr, nullptr, v, Mm, Dd, Dd);
    // o = softmax(q kT / 8) v   -> [B,S,D]
    attn_kernel<<<dim3(Ss / 64, Bb * Hh), blk>>>(q, k, v, o);
    // x2 = x + o @ Wo
    sgemm_kernel<MD_RES><<<gp, blk>>>(o, Wo, nullptr, x, x2, Mm, Dd, Dd);
    // h = LN2(x2)
    ln_kernel<<<Mm, blk>>>(x2, ln2_g, ln2_b, h);
    // ff1 = relu(h @ W1 + b1)
    sgemm_kernel<MD_BIAS | MD_RELU><<<gf, blk>>>(h, W1, b1, nullptr, ff1, Mm, FFf, Dd);
    // out = x2 + relu(ff1 @ W2 + b2)
    sgemm_kernel<MD_BIAS | MD_RELU | MD_RES><<<gp, blk>>>(ff1, W2, b2, x2, out, Mm, Dd, FFf);
}

// round 4
// speedup vs baseline: 1.4697x; 1.4697x over previous
#include <cuda_runtime.h>
#include <cuda_bf16.h>
#include <cstdint>

// ---------------------------------------------------------------------------
// TransformerLayer: B=4, S=2048, D=1024, H=16, HD=64, FF=4096, fp32 I/O.
// Round 3: GEMMs via mma.sync bf16 (hi/lo split, 3-pass) — base sm_103 ISA
// only (no tcgen05: ptxas target is sm_103, not sm_103a).
// Attention/LN stay fp32 (known good from R1).
// ---------------------------------------------------------------------------

constexpr int Bb = 4, Ss = 2048, Dd = 1024, Hh = 16, HDd = 64, FFf = 4096;
constexpr int Mm = Bb * Ss;            // 8192 rows
constexpr float EPS = 1e-5f;
constexpr float SCALE = 0.125f;        // 1/sqrt(64)

// fp32 scratch (module-load allocated; no runtime alloc)
__device__ float g_h  [Mm * Dd];
__device__ float g_q  [Mm * Dd];
__device__ float g_k  [Mm * Dd];
__device__ float g_v  [Mm * Dd];
__device__ float g_o  [Mm * Dd];
__device__ float g_x2 [Mm * Dd];
__device__ float g_ff1[(size_t)Mm * FFf];

// ========================= small PTX helpers ===========================
__device__ __forceinline__ uint32_t smem_u32(const void* p) {
    uint32_t a;
    asm("{ .reg .u64 t; cvta.to.shared.u64 t, %1; cvt.u32.u64 %0, t; }" : "=r"(a) : "l"(p));
    return a;
}
__device__ __forceinline__ void ldsm_x4(uint32_t (&r)[4], uint32_t addr) {
    asm volatile("ldmatrix.sync.aligned.m8n8.x4.shared.b16 {%0,%1,%2,%3}, [%4];"
        : "=r"(r[0]), "=r"(r[1]), "=r"(r[2]), "=r"(r[3]) : "r"(addr));
}
__device__ __forceinline__ void ldsm_x2_t(uint32_t (&r)[2], uint32_t addr) {
    asm volatile("ldmatrix.sync.aligned.m8n8.x2.trans.shared.b16 {%0,%1}, [%2];"
        : "=r"(r[0]), "=r"(r[1]) : "r"(addr));
}
__device__ __forceinline__ void mma16816(float (&c)[4], const uint32_t (&a)[4],
                                         const uint32_t (&b)[2]) {
    asm volatile("mma.sync.aligned.m16n8k16.row.col.f32.bf16.bf16.f32 "
        "{%0,%1,%2,%3}, {%4,%5,%6,%7}, {%8,%9}, {%0,%1,%2,%3};"
        : "+f"(c[0]), "+f"(c[1]), "+f"(c[2]), "+f"(c[3])
        : "r"(a[0]), "r"(a[1]), "r"(a[2]), "r"(a[3]), "r"(b[0]), "r"(b[1]));
}
__device__ __forceinline__ uint32_t pack_bf2(float a, float b) {
    __nv_bfloat162 h = __floats2bfloat162_rn(a, b);
    return *reinterpret_cast<uint32_t*>(&h);
}

// ========================= LayerNorm ===========================
__global__ void __launch_bounds__(256) ln_kernel(
    const float* __restrict__ x, const float* __restrict__ g,
    const float* __restrict__ b, float* __restrict__ out)
{
    int row = blockIdx.x;
    int t = threadIdx.x;
    const float4 v = reinterpret_cast<const float4*>(x + (size_t)row * Dd)[t];
    float s  = v.x + v.y + v.z + v.w;
    float ss = v.x * v.x + v.y * v.y + v.z * v.z + v.w * v.w;
#pragma unroll
    for (int o = 16; o > 0; o >>= 1) {
        s  += __shfl_xor_sync(0xffffffffu, s,  o);
        ss += __shfl_xor_sync(0xffffffffu, ss, o);
    }
    __shared__ float red[16];
    int w = t >> 5;
    if ((t & 31) == 0) { red[w] = s; red[8 + w] = ss; }
    __syncthreads();
    float st = 0.f, sst = 0.f;
#pragma unroll
    for (int i = 0; i < 8; i++) { st += red[i]; sst += red[8 + i]; }
    float mu  = st  * (1.0f / Dd);
    float var = sst * (1.0f / Dd) - mu * mu;
    float inv = rsqrtf(var + EPS);
    float4 gg = reinterpret_cast<const float4*>(g)[t];
    float4 bb = reinterpret_cast<const float4*>(b)[t];
    float4 o4;
    o4.x = (v.x - mu) * inv * gg.x + bb.x;
    o4.y = (v.y - mu) * inv * gg.y + bb.y;
    o4.z = (v.z - mu) * inv * gg.z + bb.z;
    o4.w = (v.w - mu) * inv * gg.w + bb.w;
    reinterpret_cast<float4*>(out + (size_t)row * Dd)[t] = o4;
}

// ========================= mma.sync split-bf16 GEMM ===========================
// C[M,N] = A[M,K] @ W[K,N], fp32 in/out. 3-pass split: AhBh + AhBl + AlBh.
// CTA tile 128x128x32; 8 warps in 2(m) x 4(n); warp tile 64x32.
// Smem per stage: A hi/lo 128 rows x stride 40 bf16; B hi/lo 32 rows x stride 136.
constexpr int MD_BIAS = 1, MD_RELU = 2, MD_RES = 4, MD_QKV = 8;

constexpr int LDA = 40;                       // bf16 elems (80 B rows)
constexpr int LDB = 136;                      // bf16 elems (272 B rows)
constexpr int A_BYTES = 128 * LDA * 2;        // 10240 per matrix
constexpr int B_BYTES = 32 * LDB * 2;         // 8704 per matrix
constexpr int B_OFF   = 2 * A_BYTES;          // 20480
constexpr int STAGE   = 2 * A_BYTES + 2 * B_BYTES;   // 37888
constexpr int GEMM_SMEM = 2 * STAGE;          // 75776

template <int MODE>
__global__ void __launch_bounds__(256, 1) gemm_mma(
    const float* __restrict__ A, const float* __restrict__ W,
    const float* __restrict__ bias, const float* __restrict__ res,
    float* __restrict__ C, int N, int K)
{
    extern __shared__ char dsm[];
    const uint32_t smemU = smem_u32(dsm);

    const int tid  = threadIdx.x;
    const int lane = tid & 31;
    const int wid  = tid >> 5;
    const int wm   = wid >> 2;          // 0..1
    const int wn   = wid & 3;           // 0..3
    const int m0   = blockIdx.y * 128;
    const int n0   = blockIdx.x * 128;

    // -------- staging addressing --------
    const int arow = tid >> 1, akb = (tid & 1) * 16;   // A: 2 thr/row, 16 k each
    const int brow = tid >> 3, bnb = (tid & 7) * 16;   // B: 8 thr/row, 16 n each
    const float* Aptr = A + (size_t)(m0 + arow) * K + akb;
    const float* Wptr = W + (size_t)brow * N + n0 + bnb;

    const int NC = K >> 5;              // k-chunks of 32

    float4 ra[4], rb[4];
#pragma unroll
    for (int j = 0; j < 4; j++) {
        ra[j] = *reinterpret_cast<const float4*>(Aptr + 4 * j);
        rb[j] = *reinterpret_cast<const float4*>(Wptr + 4 * j);
    }

    float acc[4][4][4];
#pragma unroll
    for (int mt = 0; mt < 4; mt++)
#pragma unroll
        for (int nt = 0; nt < 4; nt++)
#pragma unroll
            for (int e = 0; e < 4; e++) acc[mt][nt][e] = 0.f;

    // compute-side smem base addrs (stage 0)
    const uint32_t aCmp0 = smemU + ((uint32_t)(wm * 64 + (lane & 15)) * LDA +
                                    (uint32_t)(lane >> 4) * 8) * 2u;
    const uint32_t bCmp0 = smemU + (uint32_t)B_OFF +
                           ((uint32_t)(lane & 15) * LDB + (uint32_t)(wn * 32)) * 2u;

    for (int c = 0; c < NC; c++) {
        const int s = c & 1;
        char* st = dsm + (size_t)s * STAGE;

        // -------- convert + store stage --------
        {
            uint32_t hw[8], lw[8];
#pragma unroll
            for (int j = 0; j < 4; j++) {
                float f[4] = {ra[j].x, ra[j].y, ra[j].z, ra[j].w};
#pragma unroll
                for (int e = 0; e < 2; e++) {
                    float a = f[2 * e], b = f[2 * e + 1];
                    __nv_bfloat16 ha = __float2bfloat16(a);
                    __nv_bfloat16 hb = __float2bfloat16(b);
                    hw[j * 2 + e] = pack_bf2(a, b);  // rn-packed hi
                    lw[j * 2 + e] = pack_bf2(a - __bfloat162float(ha),
                                             b - __bfloat162float(hb));
                }
            }
            // NOTE: hi must be the same value whose residual we stored.
            // pack_bf2 uses rn, __float2bfloat16 is rn -> identical. OK.
            uint4* dAh = reinterpret_cast<uint4*>(st + ((size_t)arow * LDA + akb) * 2);
            uint4* dAl = reinterpret_cast<uint4*>(st + A_BYTES + ((size_t)arow * LDA + akb) * 2);
            dAh[0] = make_uint4(hw[0], hw[1], hw[2], hw[3]);
            dAh[1] = make_uint4(hw[4], hw[5], hw[6], hw[7]);
            dAl[0] = make_uint4(lw[0], lw[1], lw[2], lw[3]);
            dAl[1] = make_uint4(lw[4], lw[5], lw[6], lw[7]);

#pragma unroll
            for (int j = 0; j < 4; j++) {
                float f[4] = {rb[j].x, rb[j].y, rb[j].z, rb[j].w};
#pragma unroll
                for (int e = 0; e < 2; e++) {
                    float a = f[2 * e], b = f[2 * e + 1];
                    __nv_bfloat16 ha = __float2bfloat16(a);
                    __nv_bfloat16 hb = __float2bfloat16(b);
                    hw[j * 2 + e] = pack_bf2(a, b);
                    lw[j * 2 + e] = pack_bf2(a - __bfloat162float(ha),
                                             b - __bfloat162float(hb));
                }
            }
            uint4* dBh = reinterpret_cast<uint4*>(st + B_OFF + ((size_t)brow * LDB + bnb) * 2);
            uint4* dBl = reinterpret_cast<uint4*>(st + B_OFF + B_BYTES + ((size_t)brow * LDB + bnb) * 2);
            dBh[0] = make_uint4(hw[0], hw[1], hw[2], hw[3]);
            dBh[1] = make_uint4(hw[4], hw[5], hw[6], hw[7]);
            dBl[0] = make_uint4(lw[0], lw[1], lw[2], lw[3]);
            dBl[1] = make_uint4(lw[4], lw[5], lw[6], lw[7]);
        }
        __syncthreads();

        // -------- prefetch next chunk --------
        if (c + 1 < NC) {
            const float* An = Aptr + (c + 1) * 32;
            const float* Wn = Wptr + (size_t)(c + 1) * 32 * N;
#pragma unroll
            for (int j = 0; j < 4; j++) {
                ra[j] = *reinterpret_cast<const float4*>(An + 4 * j);
                rb[j] = *reinterpret_cast<const float4*>(Wn + 4 * j);
            }
        }

        // -------- compute from stage s --------
        const uint32_t aC = aCmp0 + (uint32_t)s * STAGE;
        const uint32_t bC = bCmp0 + (uint32_t)s * STAGE;
#pragma unroll
        for (int ks = 0; ks < 2; ks++) {
            uint32_t Ah[4][4], Al[4][4], Bh[4][2], Bl[4][2];
#pragma unroll
            for (int mt = 0; mt < 4; mt++) {
                uint32_t ad = aC + (uint32_t)mt * (16 * LDA * 2) + (uint32_t)ks * 32;
                ldsm_x4(Ah[mt], ad);
                ldsm_x4(Al[mt], ad + A_BYTES);
            }
#pragma unroll
            for (int nt = 0; nt < 4; nt++) {
                uint32_t bd = bC + (uint32_t)ks * (16 * LDB * 2) + (uint32_t)nt * 16;
                ldsm_x2_t(Bh[nt], bd);
                ldsm_x2_t(Bl[nt], bd + B_BYTES);
            }
#pragma unroll
            for (int mt = 0; mt < 4; mt++)
#pragma unroll
                for (int nt = 0; nt < 4; nt++) {
                    mma16816(acc[mt][nt], Ah[mt], Bh[nt]);
                    mma16816(acc[mt][nt], Ah[mt], Bl[nt]);
                    mma16816(acc[mt][nt], Al[mt], Bh[nt]);
                }
        }
        __syncthreads();
    }

    // -------- epilogue --------
    const int rbase = m0 + wm * 64;
    const int cbase = n0 + wn * 32;
#pragma unroll
    for (int mt = 0; mt < 4; mt++)
#pragma unroll
        for (int nt = 0; nt < 4; nt++) {
#pragma unroll
            for (int half = 0; half < 2; half++) {
                int r = rbase + mt * 16 + (lane >> 2) + half * 8;
                int cc = cbase + nt * 8 + (lane & 3) * 2;
                float2 v;
                v.x = acc[mt][nt][half * 2 + 0];
                v.y = acc[mt][nt][half * 2 + 1];
                if (MODE & MD_BIAS) {
                    float2 bb = *reinterpret_cast<const float2*>(bias + cc);
                    v.x += bb.x; v.y += bb.y;
                }
                if (MODE & MD_RELU) {
                    v.x = fmaxf(v.x, 0.f); v.y = fmaxf(v.y, 0.f);
                }
                if (MODE & MD_RES) {
                    float2 rr = *reinterpret_cast<const float2*>(res + (size_t)r * N + cc);
                    v.x += rr.x; v.y += rr.y;
                }
                if (MODE & MD_QKV) {
                    int b_ = r >> 11, s_ = r & (Ss - 1);
                    int h_ = cc >> 6, d_ = cc & 63;
                    *reinterpret_cast<float2*>(C +
                        ((size_t)(b_ * Hh + h_) * Ss + s_) * HDd + d_) = v;
                } else {
                    *reinterpret_cast<float2*>(C + (size_t)r * N + cc) = v;
                }
            }
        }
}

// ========================= Flash attention (fp32, unchanged) ================
__global__ void __launch_bounds__(256) attn_kernel(
    const float* __restrict__ q, const float* __restrict__ k,
    const float* __restrict__ v, float* __restrict__ o)
{
    __shared__ float QsT[64][64];
    __shared__ float KP [64][64];
    __shared__ float Vs [64][64];

    int tid = threadIdx.x;
    int tr = tid >> 4, tc = tid & 15;
    int bh = blockIdx.y;
    int q0 = blockIdx.x * 64;

    const float* qb = q + ((size_t)bh * Ss + q0) * HDd;
    const float* kb = k + (size_t)bh * Ss * HDd;
    const float* vb = v + (size_t)bh * Ss * HDd;

    {
        int r = tid >> 2;
        const float4* qr = reinterpret_cast<const float4*>(qb + r * HDd);
#pragma unroll
        for (int c4 = 0; c4 < 4; c4++) {
            int dc = (tid & 3) + c4 * 4;
            float4 a = qr[dc];
            int d = dc * 4;
            QsT[d + 0][r] = a.x * SCALE;
            QsT[d + 1][r] = a.y * SCALE;
            QsT[d + 2][r] = a.z * SCALE;
            QsT[d + 3][r] = a.w * SCALE;
        }
    }

    float accO[4][4];
    float m_i[4], l_i[4];
#pragma unroll
    for (int i = 0; i < 4; i++) {
        m_i[i] = -1e30f; l_i[i] = 0.f;
#pragma unroll
        for (int c = 0; c < 4; c++) accO[i][c] = 0.f;
    }

    for (int kt = 0; kt < Ss; kt += 64) {
        {
            int r = tid >> 2;
            const float4* kr = reinterpret_cast<const float4*>(kb + (size_t)(kt + r) * HDd);
            const float4* vr = reinterpret_cast<const float4*>(vb + (size_t)(kt + r) * HDd);
#pragma unroll
            for (int c4 = 0; c4 < 4; c4++) {
                int dc = (tid & 3) + c4 * 4;
                float4 a = kr[dc];
                int d = dc * 4;
                KP[d + 0][r] = a.x;
                KP[d + 1][r] = a.y;
                KP[d + 2][r] = a.z;
                KP[d + 3][r] = a.w;
                *reinterpret_cast<float4*>(&Vs[r][dc * 4]) = vr[dc];
            }
        }
        __syncthreads();

        float sc[4][4];
#pragma unroll
        for (int i = 0; i < 4; i++)
#pragma unroll
            for (int j = 0; j < 4; j++) sc[i][j] = 0.f;

#pragma unroll 8
        for (int d = 0; d < 64; d++) {
            float aq[4], ak[4];
            *reinterpret_cast<float4*>(&aq[0]) = *reinterpret_cast<const float4*>(&QsT[d][tr * 4]);
            *reinterpret_cast<float4*>(&ak[0]) = *reinterpret_cast<const float4*>(&KP[d][tc * 4]);
#pragma unroll
            for (int i = 0; i < 4; i++)
#pragma unroll
                for (int j = 0; j < 4; j++)
                    sc[i][j] = fmaf(aq[i], ak[j], sc[i][j]);
        }

        float pr[4][4];
#pragma unroll
        for (int i = 0; i < 4; i++) {
            float tm = fmaxf(fmaxf(sc[i][0], sc[i][1]), fmaxf(sc[i][2], sc[i][3]));
#pragma unroll
            for (int off = 1; off < 16; off <<= 1)
                tm = fmaxf(tm, __shfl_xor_sync(0xffffffffu, tm, off));
            float nm = fmaxf(m_i[i], tm);
            float corr = __expf(m_i[i] - nm);
            m_i[i] = nm;
            float ps = 0.f;
#pragma unroll
            for (int j = 0; j < 4; j++) {
                pr[i][j] = __expf(sc[i][j] - nm);
                ps += pr[i][j];
            }
#pragma unroll
            for (int off = 1; off < 16; off <<= 1)
                ps += __shfl_xor_sync(0xffffffffu, ps, off);
            l_i[i] = l_i[i] * corr + ps;
#pragma unroll
            for (int c = 0; c < 4; c++) accO[i][c] *= corr;
        }

        __syncthreads();
#pragma unroll
        for (int i = 0; i < 4; i++) {
            float4 p4;
            p4.x = pr[i][0]; p4.y = pr[i][1]; p4.z = pr[i][2]; p4.w = pr[i][3];
            *reinterpret_cast<float4*>(&KP[tr * 4 + i][tc * 4]) = p4;
        }
        __syncthreads();

#pragma unroll 4
        for (int j = 0; j < 64; j += 4) {
            float pv[4][4], vv[4][4];
#pragma unroll
            for (int i = 0; i < 4; i++)
                *reinterpret_cast<float4*>(&pv[i][0]) =
                    *reinterpret_cast<const float4*>(&KP[tr * 4 + i][j]);
#pragma unroll
            for (int jj = 0; jj < 4; jj++)
                *reinterpret_cast<float4*>(&vv[jj][0]) =
                    *reinterpret_cast<const float4*>(&Vs[j + jj][tc * 4]);
#pragma unroll
            for (int i = 0; i < 4; i++)
#pragma unroll
                for (int c = 0; c < 4; c++) {
#pragma unroll
                    for (int jj = 0; jj < 4; jj++)
                        accO[i][c] = fmaf(pv[i][jj], vv[jj][c], accO[i][c]);
                }
        }
        __syncthreads();
    }

    int b_ = bh >> 4, h_ = bh & 15;
#pragma unroll
    for (int i = 0; i < 4; i++) {
        float invl = 1.0f / l_i[i];
        int srow = q0 + tr * 4 + i;
        float4 r4;
        r4.x = accO[i][0] * invl;
        r4.y = accO[i][1] * invl;
        r4.z = accO[i][2] * invl;
        r4.w = accO[i][3] * invl;
        *reinterpret_cast<float4*>(o + ((size_t)(b_ * Ss + srow)) * Dd + h_ * HDd + tc * 4) = r4;
    }
}

// ========================= launch ===========================
extern "C" void kernel_launch(void* const* d_in, const int* in_sizes, int n_in,
                              void* d_out, int out_size)
{
    const float* x     = (const float*)d_in[0];
    const float* ln1_g = (const float*)d_in[1];
    const float* ln1_b = (const float*)d_in[2];
    const float* ln2_g = (const float*)d_in[3];
    const float* ln2_b = (const float*)d_in[4];
    const float* Wq    = (const float*)d_in[5];
    const float* Wk    = (const float*)d_in[6];
    const float* Wv    = (const float*)d_in[7];
    const float* Wo    = (const float*)d_in[8];
    const float* W1    = (const float*)d_in[9];
    const float* b1    = (const float*)d_in[10];
    const float* W2    = (const float*)d_in[11];
    const float* b2    = (const float*)d_in[12];
    float* out = (float*)d_out;

    float *h, *q, *k, *v, *o, *x2, *ff1;
    cudaGetSymbolAddress((void**)&h,   g_h);
    cudaGetSymbolAddress((void**)&q,   g_q);
    cudaGetSymbolAddress((void**)&k,   g_k);
    cudaGetSymbolAddress((void**)&v,   g_v);
    cudaGetSymbolAddress((void**)&o,   g_o);
    cudaGetSymbolAddress((void**)&x2,  g_x2);
    cudaGetSymbolAddress((void**)&ff1, g_ff1);

    cudaFuncSetAttribute(gemm_mma<MD_QKV>, cudaFuncAttributeMaxDynamicSharedMemorySize, GEMM_SMEM);
    cudaFuncSetAttribute(gemm_mma<MD_RES>, cudaFuncAttributeMaxDynamicSharedMemorySize, GEMM_SMEM);
    cudaFuncSetAttribute(gemm_mma<MD_BIAS | MD_RELU>, cudaFuncAttributeMaxDynamicSharedMemorySize, GEMM_SMEM);
    cudaFuncSetAttribute(gemm_mma<MD_BIAS | MD_RELU | MD_RES>, cudaFuncAttributeMaxDynamicSharedMemorySize, GEMM_SMEM);

    dim3 blk(256);
    dim3 gD(Dd / 128, Mm / 128);     // (8, 64)
    dim3 gF(FFf / 128, Mm / 128);    // (32, 64)

    // h = LN1(x)
    ln_kernel<<<Mm, blk>>>(x, ln1_g, ln1_b, h);
    // q,k,v = h @ W{q,k,v}  ([B,H,S,HD] layout)
    gemm_mma<MD_QKV><<<gD, blk, GEMM_SMEM>>>(h, Wq, nullptr, nullptr, q, Dd, Dd);
    gemm_mma<MD_QKV><<<gD, blk, GEMM_SMEM>>>(h, Wk, nullptr, nullptr, k, Dd, Dd);
    gemm_mma<MD_QKV><<<gD, blk, GEMM_SMEM>>>(h, Wv, nullptr, nullptr, v, Dd, Dd);
    // attention
    attn_kernel<<<dim3(Ss / 64, Bb * Hh), blk>>>(q, k, v, o);
    // x2 = x + o @ Wo
    gemm_mma<MD_RES><<<gD, blk, GEMM_SMEM>>>(o, Wo, nullptr, x, x2, Dd, Dd);
    // h = LN2(x2)
    ln_kernel<<<Mm, blk>>>(x2, ln2_g, ln2_b, h);
    // ff1 = relu(h @ W1 + b1)
    gemm_mma<MD_BIAS | MD_RELU><<<gF, blk, GEMM_SMEM>>>(h, W1, b1, nullptr, ff1, FFf, Dd);
    // out = x2 + relu(ff1 @ W2 + b2)
    gemm_mma<MD_BIAS | MD_RELU | MD_RES><<<gD, blk, GEMM_SMEM>>>(ff1, W2, b2, x2, out, Dd, FFf);
}

// round 7
// speedup vs baseline: 2.0406x; 1.3884x over previous
#include <cuda_runtime.h>
#include <cuda_bf16.h>
#include <cstdint>

// ---------------------------------------------------------------------------
// TransformerLayer: B=4, S=2048, D=1024, H=16, HD=64, FF=4096, fp32 I/O.
// Round 6: fix P C-frag->A-frag repack order in attn_mma (no swap needed).
// GEMMs unchanged from R3 (mma.sync split-bf16, tensor=37.6%).
// ---------------------------------------------------------------------------

constexpr int Bb = 4, Ss = 2048, Dd = 1024, Hh = 16, HDd = 64, FFf = 4096;
constexpr int Mm = Bb * Ss;            // 8192 rows
constexpr float EPS = 1e-5f;
// softmax scale folded with log2(e): scores produced directly in log2 domain
constexpr float SCL2 = 0.125f * 1.4426950408889634f;

// fp32 scratch (module-load allocated; no runtime alloc)
__device__ float g_h  [Mm * Dd];
__device__ float g_q  [Mm * Dd];
__device__ float g_k  [Mm * Dd];
__device__ float g_v  [Mm * Dd];
__device__ float g_o  [Mm * Dd];
__device__ float g_x2 [Mm * Dd];
__device__ float g_ff1[(size_t)Mm * FFf];

// ========================= small PTX helpers ===========================
__device__ __forceinline__ uint32_t smem_u32(const void* p) {
    uint32_t a;
    asm("{ .reg .u64 t; cvta.to.shared.u64 t, %1; cvt.u32.u64 %0, t; }" : "=r"(a) : "l"(p));
    return a;
}
__device__ __forceinline__ void ldsm_x4(uint32_t (&r)[4], uint32_t addr) {
    asm volatile("ldmatrix.sync.aligned.m8n8.x4.shared.b16 {%0,%1,%2,%3}, [%4];"
        : "=r"(r[0]), "=r"(r[1]), "=r"(r[2]), "=r"(r[3]) : "r"(addr));
}
__device__ __forceinline__ void ldsm_x4_t(uint32_t (&r)[4], uint32_t addr) {
    asm volatile("ldmatrix.sync.aligned.m8n8.x4.trans.shared.b16 {%0,%1,%2,%3}, [%4];"
        : "=r"(r[0]), "=r"(r[1]), "=r"(r[2]), "=r"(r[3]) : "r"(addr));
}
__device__ __forceinline__ void ldsm_x2_t(uint32_t (&r)[2], uint32_t addr) {
    asm volatile("ldmatrix.sync.aligned.m8n8.x2.trans.shared.b16 {%0,%1}, [%2];"
        : "=r"(r[0]), "=r"(r[1]) : "r"(addr));
}
__device__ __forceinline__ void mma16816(float (&c)[4], const uint32_t (&a)[4],
                                         uint32_t b0, uint32_t b1) {
    asm volatile("mma.sync.aligned.m16n8k16.row.col.f32.bf16.bf16.f32 "
        "{%0,%1,%2,%3}, {%4,%5,%6,%7}, {%8,%9}, {%0,%1,%2,%3};"
        : "+f"(c[0]), "+f"(c[1]), "+f"(c[2]), "+f"(c[3])
        : "r"(a[0]), "r"(a[1]), "r"(a[2]), "r"(a[3]), "r"(b0), "r"(b1));
}
__device__ __forceinline__ uint32_t pack_bf2(float a, float b) {
    __nv_bfloat162 h = __floats2bfloat162_rn(a, b);
    return *reinterpret_cast<uint32_t*>(&h);
}
__device__ __forceinline__ float ex2(float x) {
    float y;
    asm("ex2.approx.ftz.f32 %0, %1;" : "=f"(y) : "f"(x));
    return y;
}

// ========================= LayerNorm ===========================
__global__ void __launch_bounds__(256) ln_kernel(
    const float* __restrict__ x, const float* __restrict__ g,
    const float* __restrict__ b, float* __restrict__ out)
{
    int row = blockIdx.x;
    int t = threadIdx.x;
    const float4 v = reinterpret_cast<const float4*>(x + (size_t)row * Dd)[t];
    float s  = v.x + v.y + v.z + v.w;
    float ss = v.x * v.x + v.y * v.y + v.z * v.z + v.w * v.w;
#pragma unroll
    for (int o = 16; o > 0; o >>= 1) {
        s  += __shfl_xor_sync(0xffffffffu, s,  o);
        ss += __shfl_xor_sync(0xffffffffu, ss, o);
    }
    __shared__ float red[16];
    int w = t >> 5;
    if ((t & 31) == 0) { red[w] = s; red[8 + w] = ss; }
    __syncthreads();
    float st = 0.f, sst = 0.f;
#pragma unroll
    for (int i = 0; i < 8; i++) { st += red[i]; sst += red[8 + i]; }
    float mu  = st  * (1.0f / Dd);
    float var = sst * (1.0f / Dd) - mu * mu;
    float inv = rsqrtf(var + EPS);
    float4 gg = reinterpret_cast<const float4*>(g)[t];
    float4 bb = reinterpret_cast<const float4*>(b)[t];
    float4 o4;
    o4.x = (v.x - mu) * inv * gg.x + bb.x;
    o4.y = (v.y - mu) * inv * gg.y + bb.y;
    o4.z = (v.z - mu) * inv * gg.z + bb.z;
    o4.w = (v.w - mu) * inv * gg.w + bb.w;
    reinterpret_cast<float4*>(out + (size_t)row * Dd)[t] = o4;
}

// ========================= mma.sync split-bf16 GEMM (R3, unchanged) =========
constexpr int MD_BIAS = 1, MD_RELU = 2, MD_RES = 4, MD_QKV = 8;

constexpr int LDA = 40;
constexpr int LDB = 136;
constexpr int A_BYTES = 128 * LDA * 2;
constexpr int B_BYTES = 32 * LDB * 2;
constexpr int B_OFF   = 2 * A_BYTES;
constexpr int STAGE   = 2 * A_BYTES + 2 * B_BYTES;
constexpr int GEMM_SMEM = 2 * STAGE;

template <int MODE>
__global__ void __launch_bounds__(256, 1) gemm_mma(
    const float* __restrict__ A, const float* __restrict__ W,
    const float* __restrict__ bias, const float* __restrict__ res,
    float* __restrict__ C, int N, int K)
{
    extern __shared__ char dsm[];
    const uint32_t smemU = smem_u32(dsm);

    const int tid  = threadIdx.x;
    const int lane = tid & 31;
    const int wid  = tid >> 5;
    const int wm   = wid >> 2;
    const int wn   = wid & 3;
    const int m0   = blockIdx.y * 128;
    const int n0   = blockIdx.x * 128;

    const int arow = tid >> 1, akb = (tid & 1) * 16;
    const int brow = tid >> 3, bnb = (tid & 7) * 16;
    const float* Aptr = A + (size_t)(m0 + arow) * K + akb;
    const float* Wptr = W + (size_t)brow * N + n0 + bnb;

    const int NC = K >> 5;

    float4 ra[4], rb[4];
#pragma unroll
    for (int j = 0; j < 4; j++) {
        ra[j] = *reinterpret_cast<const float4*>(Aptr + 4 * j);
        rb[j] = *reinterpret_cast<const float4*>(Wptr + 4 * j);
    }

    float acc[4][4][4];
#pragma unroll
    for (int mt = 0; mt < 4; mt++)
#pragma unroll
        for (int nt = 0; nt < 4; nt++)
#pragma unroll
            for (int e = 0; e < 4; e++) acc[mt][nt][e] = 0.f;

    const uint32_t aCmp0 = smemU + ((uint32_t)(wm * 64 + (lane & 15)) * LDA +
                                    (uint32_t)(lane >> 4) * 8) * 2u;
    const uint32_t bCmp0 = smemU + (uint32_t)B_OFF +
                           ((uint32_t)(lane & 15) * LDB + (uint32_t)(wn * 32)) * 2u;

    for (int c = 0; c < NC; c++) {
        const int s = c & 1;
        char* st = dsm + (size_t)s * STAGE;

        {
            uint32_t hw[8], lw[8];
#pragma unroll
            for (int j = 0; j < 4; j++) {
                float f[4] = {ra[j].x, ra[j].y, ra[j].z, ra[j].w};
#pragma unroll
                for (int e = 0; e < 2; e++) {
                    float a = f[2 * e], b = f[2 * e + 1];
                    __nv_bfloat16 ha = __float2bfloat16(a);
                    __nv_bfloat16 hb = __float2bfloat16(b);
                    hw[j * 2 + e] = pack_bf2(a, b);
                    lw[j * 2 + e] = pack_bf2(a - __bfloat162float(ha),
                                             b - __bfloat162float(hb));
                }
            }
            uint4* dAh = reinterpret_cast<uint4*>(st + ((size_t)arow * LDA + akb) * 2);
            uint4* dAl = reinterpret_cast<uint4*>(st + A_BYTES + ((size_t)arow * LDA + akb) * 2);
            dAh[0] = make_uint4(hw[0], hw[1], hw[2], hw[3]);
            dAh[1] = make_uint4(hw[4], hw[5], hw[6], hw[7]);
            dAl[0] = make_uint4(lw[0], lw[1], lw[2], lw[3]);
            dAl[1] = make_uint4(lw[4], lw[5], lw[6], lw[7]);

#pragma unroll
            for (int j = 0; j < 4; j++) {
                float f[4] = {rb[j].x, rb[j].y, rb[j].z, rb[j].w};
#pragma unroll
                for (int e = 0; e < 2; e++) {
                    float a = f[2 * e], b = f[2 * e + 1];
                    __nv_bfloat16 ha = __float2bfloat16(a);
                    __nv_bfloat16 hb = __float2bfloat16(b);
                    hw[j * 2 + e] = pack_bf2(a, b);
                    lw[j * 2 + e] = pack_bf2(a - __bfloat162float(ha),
                                             b - __bfloat162float(hb));
                }
            }
            uint4* dBh = reinterpret_cast<uint4*>(st + B_OFF + ((size_t)brow * LDB + bnb) * 2);
            uint4* dBl = reinterpret_cast<uint4*>(st + B_OFF + B_BYTES + ((size_t)brow * LDB + bnb) * 2);
            dBh[0] = make_uint4(hw[0], hw[1], hw[2], hw[3]);
            dBh[1] = make_uint4(hw[4], hw[5], hw[6], hw[7]);
            dBl[0] = make_uint4(lw[0], lw[1], lw[2], lw[3]);
            dBl[1] = make_uint4(lw[4], lw[5], lw[6], lw[7]);
        }
        __syncthreads();

        if (c + 1 < NC) {
            const float* An = Aptr + (c + 1) * 32;
            const float* Wn = Wptr + (size_t)(c + 1) * 32 * N;
#pragma unroll
            for (int j = 0; j < 4; j++) {
                ra[j] = *reinterpret_cast<const float4*>(An + 4 * j);
                rb[j] = *reinterpret_cast<const float4*>(Wn + 4 * j);
            }
        }

        const uint32_t aC = aCmp0 + (uint32_t)s * STAGE;
        const uint32_t bC = bCmp0 + (uint32_t)s * STAGE;
#pragma unroll
        for (int ks = 0; ks < 2; ks++) {
            uint32_t Ah[4][4], Al[4][4], Bh[4][2], Bl[4][2];
#pragma unroll
            for (int mt = 0; mt < 4; mt++) {
                uint32_t ad = aC + (uint32_t)mt * (16 * LDA * 2) + (uint32_t)ks * 32;
                ldsm_x4(Ah[mt], ad);
                ldsm_x4(Al[mt], ad + A_BYTES);
            }
#pragma unroll
            for (int nt = 0; nt < 4; nt++) {
                uint32_t bd = bC + (uint32_t)ks * (16 * LDB * 2) + (uint32_t)nt * 16;
                ldsm_x2_t(Bh[nt], bd);
                ldsm_x2_t(Bl[nt], bd + B_BYTES);
            }
#pragma unroll
            for (int mt = 0; mt < 4; mt++)
#pragma unroll
                for (int nt = 0; nt < 4; nt++) {
                    mma16816(acc[mt][nt], Ah[mt], Bh[nt][0], Bh[nt][1]);
                    mma16816(acc[mt][nt], Ah[mt], Bl[nt][0], Bl[nt][1]);
                    mma16816(acc[mt][nt], Al[mt], Bh[nt][0], Bh[nt][1]);
                }
        }
        __syncthreads();
    }

    const int rbase = m0 + wm * 64;
    const int cbase = n0 + wn * 32;
#pragma unroll
    for (int mt = 0; mt < 4; mt++)
#pragma unroll
        for (int nt = 0; nt < 4; nt++) {
#pragma unroll
            for (int half = 0; half < 2; half++) {
                int r = rbase + mt * 16 + (lane >> 2) + half * 8;
                int cc = cbase + nt * 8 + (lane & 3) * 2;
                float2 v;
                v.x = acc[mt][nt][half * 2 + 0];
                v.y = acc[mt][nt][half * 2 + 1];
                if (MODE & MD_BIAS) {
                    float2 bb = *reinterpret_cast<const float2*>(bias + cc);
                    v.x += bb.x; v.y += bb.y;
                }
                if (MODE & MD_RELU) {
                    v.x = fmaxf(v.x, 0.f); v.y = fmaxf(v.y, 0.f);
                }
                if (MODE & MD_RES) {
                    float2 rr = *reinterpret_cast<const float2*>(res + (size_t)r * N + cc);
                    v.x += rr.x; v.y += rr.y;
                }
                if (MODE & MD_QKV) {
                    int b_ = r >> 11, s_ = r & (Ss - 1);
                    int h_ = cc >> 6, d_ = cc & 63;
                    *reinterpret_cast<float2*>(C +
                        ((size_t)(b_ * Hh + h_) * Ss + s_) * HDd + d_) = v;
                } else {
                    *reinterpret_cast<float2*>(C + (size_t)r * N + cc) = v;
                }
            }
        }
}

// ========================= mma.sync flash attention =========================
// q,k,v in [B*H, S, 64] fp32. One CTA per (bh, 128 q rows). 8 warps x 16 rows.
// Split-bf16 3-pass for both QK^T and PV. Online softmax in log2 domain.
constexpr int ALD = 72;                    // row stride in bf16 elems (144 B)
constexpr int KMAT = 64 * ALD * 2;         // 9216 B per 64x64 matrix
constexpr int ASTAGE = 4 * KMAT;           // 36864
constexpr int QOFF = 2 * ASTAGE;           // 73728
constexpr int QMAT = 128 * ALD * 2;        // 18432
constexpr int ATT_SMEM = QOFF + 2 * QMAT;  // 110592

__global__ void __launch_bounds__(256, 1) attn_mma(
    const float* __restrict__ q, const float* __restrict__ k,
    const float* __restrict__ v, float* __restrict__ o)
{
    extern __shared__ char sm[];
    const uint32_t S0 = smem_u32(sm);
    const int tid = threadIdx.x, lane = tid & 31, w = tid >> 5;
    const int bh = blockIdx.y, q0 = blockIdx.x * 128;
    const int b_ = bh >> 4, h_ = bh & 15;

    const float* qb = q + ((size_t)bh * Ss + q0) * HDd;
    const float* kb = k + (size_t)bh * Ss * HDd;
    const float* vb = v + (size_t)bh * Ss * HDd;

    // ---- load + convert Q (scaled by 0.125*log2e), hi/lo into smem ----
    {
        int r = tid >> 1, cb = (tid & 1) * 32;
        const float4* src = reinterpret_cast<const float4*>(qb + r * HDd + cb);
        char* qh = sm + QOFF;
        char* ql = qh + QMAT;
        uint32_t off = ((uint32_t)r * ALD + (uint32_t)cb) * 2u;
#pragma unroll
        for (int j = 0; j < 8; j += 2) {
            uint32_t hw[4], lw[4];
#pragma unroll
            for (int e = 0; e < 2; e++) {
                float4 f = src[j + e];
                float a = f.x * SCL2, b2 = f.y * SCL2, c = f.z * SCL2, d = f.w * SCL2;
                __nv_bfloat16 ha = __float2bfloat16(a), hb = __float2bfloat16(b2);
                __nv_bfloat16 hc = __float2bfloat16(c), hd = __float2bfloat16(d);
                hw[2 * e + 0] = pack_bf2(a, b2);
                hw[2 * e + 1] = pack_bf2(c, d);
                lw[2 * e + 0] = pack_bf2(a - __bfloat162float(ha), b2 - __bfloat162float(hb));
                lw[2 * e + 1] = pack_bf2(c - __bfloat162float(hc), d - __bfloat162float(hd));
            }
            *reinterpret_cast<uint4*>(qh + off + j * 8) = make_uint4(hw[0], hw[1], hw[2], hw[3]);
            *reinterpret_cast<uint4*>(ql + off + j * 8) = make_uint4(lw[0], lw[1], lw[2], lw[3]);
        }
    }
    __syncthreads();

    // ---- per-warp persistent Q fragments (4 k-steps of 16) ----
    uint32_t Qh[4][4], Ql[4][4];
    {
        uint32_t base = S0 + QOFF +
            (((uint32_t)(w * 16 + (lane & 15))) * ALD + (uint32_t)(lane >> 4) * 8u) * 2u;
#pragma unroll
        for (int ks = 0; ks < 4; ks++) {
            ldsm_x4(Qh[ks], base + (uint32_t)ks * 32u);
            ldsm_x4(Ql[ks], base + (uint32_t)QMAT + (uint32_t)ks * 32u);
        }
    }

    float oa[8][4];
#pragma unroll
    for (int nt = 0; nt < 8; nt++)
#pragma unroll
        for (int e = 0; e < 4; e++) oa[nt][e] = 0.f;
    float mrow[2] = {-1e30f, -1e30f};
    float lrow[2] = {0.f, 0.f};

    // ---- K/V staging addressing ----
    const int krow = tid >> 2, kcb = (tid & 3) * 16;
    float4 rk[4], rv[4];
    {
        const float4* kp = reinterpret_cast<const float4*>(kb + (size_t)krow * HDd + kcb);
        const float4* vp = reinterpret_cast<const float4*>(vb + (size_t)krow * HDd + kcb);
#pragma unroll
        for (int j = 0; j < 4; j++) { rk[j] = kp[j]; rv[j] = vp[j]; }
    }

    const uint32_t stoff = ((uint32_t)krow * ALD + (uint32_t)kcb) * 2u;

    for (int t = 0; t < Ss / 64; t++) {
        const int s = t & 1;
        char* sb = sm + s * ASTAGE;
        const uint32_t sbU = S0 + (uint32_t)(s * ASTAGE);

        // ---- convert + store K/V hi/lo ----
        {
            uint32_t hw[8], lw[8];
#pragma unroll
            for (int j = 0; j < 4; j++) {
                float f0 = rk[j].x, f1 = rk[j].y, f2 = rk[j].z, f3 = rk[j].w;
                __nv_bfloat16 h0 = __float2bfloat16(f0), h1 = __float2bfloat16(f1);
                __nv_bfloat16 h2 = __float2bfloat16(f2), h3 = __float2bfloat16(f3);
                hw[2 * j] = pack_bf2(f0, f1); hw[2 * j + 1] = pack_bf2(f2, f3);
                lw[2 * j] = pack_bf2(f0 - __bfloat162float(h0), f1 - __bfloat162float(h1));
                lw[2 * j + 1] = pack_bf2(f2 - __bfloat162float(h2), f3 - __bfloat162float(h3));
            }
            *reinterpret_cast<uint4*>(sb + stoff)      = make_uint4(hw[0], hw[1], hw[2], hw[3]);
            *reinterpret_cast<uint4*>(sb + stoff + 16) = make_uint4(hw[4], hw[5], hw[6], hw[7]);
            *reinterpret_cast<uint4*>(sb + KMAT + stoff)      = make_uint4(lw[0], lw[1], lw[2], lw[3]);
            *reinterpret_cast<uint4*>(sb + KMAT + stoff + 16) = make_uint4(lw[4], lw[5], lw[6], lw[7]);
#pragma unroll
            for (int j = 0; j < 4; j++) {
                float f0 = rv[j].x, f1 = rv[j].y, f2 = rv[j].z, f3 = rv[j].w;
                __nv_bfloat16 h0 = __float2bfloat16(f0), h1 = __float2bfloat16(f1);
                __nv_bfloat16 h2 = __float2bfloat16(f2), h3 = __float2bfloat16(f3);
                hw[2 * j] = pack_bf2(f0, f1); hw[2 * j + 1] = pack_bf2(f2, f3);
                lw[2 * j] = pack_bf2(f0 - __bfloat162float(h0), f1 - __bfloat162float(h1));
                lw[2 * j + 1] = pack_bf2(f2 - __bfloat162float(h2), f3 - __bfloat162float(h3));
            }
            *reinterpret_cast<uint4*>(sb + 2 * KMAT + stoff)      = make_uint4(hw[0], hw[1], hw[2], hw[3]);
            *reinterpret_cast<uint4*>(sb + 2 * KMAT + stoff + 16) = make_uint4(hw[4], hw[5], hw[6], hw[7]);
            *reinterpret_cast<uint4*>(sb + 3 * KMAT + stoff)      = make_uint4(lw[0], lw[1], lw[2], lw[3]);
            *reinterpret_cast<uint4*>(sb + 3 * KMAT + stoff + 16) = make_uint4(lw[4], lw[5], lw[6], lw[7]);
        }
        __syncthreads();

        // ---- prefetch next tile ----
        if (t + 1 < Ss / 64) {
            const float4* kp = reinterpret_cast<const float4*>(
                kb + (size_t)((t + 1) * 64 + krow) * HDd + kcb);
            const float4* vp = reinterpret_cast<const float4*>(
                vb + (size_t)((t + 1) * 64 + krow) * HDd + kcb);
#pragma unroll
            for (int j = 0; j < 4; j++) { rk[j] = kp[j]; rv[j] = vp[j]; }
        }

        // ---- S = Q K^T (3-pass). sc[nt] covers keys nt*8..nt*8+7 ----
        float sc[8][4];
#pragma unroll
        for (int nt = 0; nt < 8; nt++)
#pragma unroll
            for (int e = 0; e < 4; e++) sc[nt][e] = 0.f;

        // K B-frag (hi+lo in one ldsm.x4): lanes 0-15 -> Kh tiles, 16-31 -> Kl
        const uint32_t kfb = sbU + (uint32_t)(lane >> 4) * (uint32_t)KMAT +
            (((uint32_t)(lane & 7)) * ALD + (uint32_t)((lane >> 3) & 1) * 8u) * 2u;
#pragma unroll
        for (int nt = 0; nt < 8; nt++) {
#pragma unroll
            for (int ks = 0; ks < 4; ks++) {
                uint32_t kf[4];
                ldsm_x4(kf, kfb + ((uint32_t)nt * 8u * ALD + (uint32_t)ks * 16u) * 2u);
                mma16816(sc[nt], Qh[ks], kf[0], kf[1]);   // Qh * Kh
                mma16816(sc[nt], Qh[ks], kf[2], kf[3]);   // Qh * Kl
                mma16816(sc[nt], Ql[ks], kf[0], kf[1]);   // Ql * Kh
            }
        }

        // ---- online softmax (log2 domain) ----
        float mt0 = sc[0][0], mt1 = sc[0][2];
#pragma unroll
        for (int nt = 0; nt < 8; nt++) {
            mt0 = fmaxf(mt0, fmaxf(sc[nt][0], sc[nt][1]));
            mt1 = fmaxf(mt1, fmaxf(sc[nt][2], sc[nt][3]));
        }
        mt0 = fmaxf(mt0, __shfl_xor_sync(0xffffffffu, mt0, 1));
        mt0 = fmaxf(mt0, __shfl_xor_sync(0xffffffffu, mt0, 2));
        mt1 = fmaxf(mt1, __shfl_xor_sync(0xffffffffu, mt1, 1));
        mt1 = fmaxf(mt1, __shfl_xor_sync(0xffffffffu, mt1, 2));
        float mn0 = fmaxf(mrow[0], mt0), mn1 = fmaxf(mrow[1], mt1);
        float c0 = ex2(mrow[0] - mn0), c1 = ex2(mrow[1] - mn1);
        mrow[0] = mn0; mrow[1] = mn1;

        float ls0 = 0.f, ls1 = 0.f;
#pragma unroll
        for (int nt = 0; nt < 8; nt++) {
            sc[nt][0] = ex2(sc[nt][0] - mn0);
            sc[nt][1] = ex2(sc[nt][1] - mn0);
            sc[nt][2] = ex2(sc[nt][2] - mn1);
            sc[nt][3] = ex2(sc[nt][3] - mn1);
            ls0 += sc[nt][0] + sc[nt][1];
            ls1 += sc[nt][2] + sc[nt][3];
        }
        ls0 += __shfl_xor_sync(0xffffffffu, ls0, 1);
        ls0 += __shfl_xor_sync(0xffffffffu, ls0, 2);
        ls1 += __shfl_xor_sync(0xffffffffu, ls1, 1);
        ls1 += __shfl_xor_sync(0xffffffffu, ls1, 2);
        lrow[0] = lrow[0] * c0 + ls0;
        lrow[1] = lrow[1] * c1 + ls1;
#pragma unroll
        for (int nt = 0; nt < 8; nt++) {
            oa[nt][0] *= c0; oa[nt][1] *= c0;
            oa[nt][2] *= c1; oa[nt][3] *= c1;
        }

        // ---- P C-frag -> A-frag (registers only), hi/lo split ----
        // A-frag order: a0=(m,k0-7)=c01(tile 2kk); a1=(m+8,k0-7)=c23(tile 2kk);
        //               a2=(m,k8-15)=c01(tile 2kk+1); a3=(m+8,k8-15)=c23(2kk+1).
        // The natural fill order below is ALREADY correct — no swap.
        uint32_t Ph[4][4], Pl[4][4];
#pragma unroll
        for (int kk = 0; kk < 4; kk++) {
#pragma unroll
            for (int half = 0; half < 2; half++) {       // half 0: tile 2kk, 1: 2kk+1
                float p0 = sc[2 * kk + half][0], p1 = sc[2 * kk + half][1];
                float p2 = sc[2 * kk + half][2], p3 = sc[2 * kk + half][3];
                __nv_bfloat16 h0 = __float2bfloat16(p0), h1 = __float2bfloat16(p1);
                __nv_bfloat16 h2 = __float2bfloat16(p2), h3 = __float2bfloat16(p3);
                Ph[kk][2 * half + 0] = pack_bf2(p0, p1);
                Ph[kk][2 * half + 1] = pack_bf2(p2, p3);
                Pl[kk][2 * half + 0] = pack_bf2(p0 - __bfloat162float(h0),
                                                p1 - __bfloat162float(h1));
                Pl[kk][2 * half + 1] = pack_bf2(p2 - __bfloat162float(h2),
                                                p3 - __bfloat162float(h3));
            }
        }

        // ---- O += P V (3-pass) ----
        // V B-frag trans: lanes 0-15 -> Vh 16 k-rows, lanes 16-31 -> Vl
        const uint32_t vfb = sbU + 2u * (uint32_t)KMAT +
            (uint32_t)(lane >> 4) * (uint32_t)KMAT +
            ((uint32_t)(lane & 15)) * (uint32_t)ALD * 2u;
#pragma unroll
        for (int kk = 0; kk < 4; kk++) {
#pragma unroll
            for (int nt = 0; nt < 8; nt++) {
                uint32_t vf[4];
                ldsm_x4_t(vf, vfb + ((uint32_t)kk * 16u * ALD + (uint32_t)nt * 8u) * 2u);
                mma16816(oa[nt], Ph[kk], vf[0], vf[1]);   // Ph * Vh
                mma16816(oa[nt], Ph[kk], vf[2], vf[3]);   // Ph * Vl
                mma16816(oa[nt], Pl[kk], vf[0], vf[1]);   // Pl * Vh
            }
        }
        __syncthreads();
    }

    // ---- epilogue: normalize, write to [B,S,D] ----
    float il0 = 1.0f / lrow[0], il1 = 1.0f / lrow[1];
    int sr0 = q0 + w * 16 + (lane >> 2);
    int sr1 = sr0 + 8;
#pragma unroll
    for (int nt = 0; nt < 8; nt++) {
        int col = h_ * HDd + nt * 8 + (lane & 3) * 2;
        float2 v0, v1;
        v0.x = oa[nt][0] * il0; v0.y = oa[nt][1] * il0;
        v1.x = oa[nt][2] * il1; v1.y = oa[nt][3] * il1;
        *reinterpret_cast<float2*>(o + ((size_t)(b_ * Ss + sr0)) * Dd + col) = v0;
        *reinterpret_cast<float2*>(o + ((size_t)(b_ * Ss + sr1)) * Dd + col) = v1;
    }
}

// ========================= launch ===========================
extern "C" void kernel_launch(void* const* d_in, const int* in_sizes, int n_in,
                              void* d_out, int out_size)
{
    const float* x     = (const float*)d_in[0];
    const float* ln1_g = (const float*)d_in[1];
    const float* ln1_b = (const float*)d_in[2];
    const float* ln2_g = (const float*)d_in[3];
    const float* ln2_b = (const float*)d_in[4];
    const float* Wq    = (const float*)d_in[5];
    const float* Wk    = (const float*)d_in[6];
    const float* Wv    = (const float*)d_in[7];
    const float* Wo    = (const float*)d_in[8];
    const float* W1    = (const float*)d_in[9];
    const float* b1    = (const float*)d_in[10];
    const float* W2    = (const float*)d_in[11];
    const float* b2    = (const float*)d_in[12];
    float* out = (float*)d_out;

    float *h, *q, *k, *v, *o, *x2, *ff1;
    cudaGetSymbolAddress((void**)&h,   g_h);
    cudaGetSymbolAddress((void**)&q,   g_q);
    cudaGetSymbolAddress((void**)&k,   g_k);
    cudaGetSymbolAddress((void**)&v,   g_v);
    cudaGetSymbolAddress((void**)&o,   g_o);
    cudaGetSymbolAddress((void**)&x2,  g_x2);
    cudaGetSymbolAddress((void**)&ff1, g_ff1);

    cudaFuncSetAttribute(gemm_mma<MD_QKV>, cudaFuncAttributeMaxDynamicSharedMemorySize, GEMM_SMEM);
    cudaFuncSetAttribute(gemm_mma<MD_RES>, cudaFuncAttributeMaxDynamicSharedMemorySize, GEMM_SMEM);
    cudaFuncSetAttribute(gemm_mma<MD_BIAS | MD_RELU>, cudaFuncAttributeMaxDynamicSharedMemorySize, GEMM_SMEM);
    cudaFuncSetAttribute(gemm_mma<MD_BIAS | MD_RELU | MD_RES>, cudaFuncAttributeMaxDynamicSharedMemorySize, GEMM_SMEM);
    cudaFuncSetAttribute(attn_mma, cudaFuncAttributeMaxDynamicSharedMemorySize, ATT_SMEM);

    dim3 blk(256);
    dim3 gD(Dd / 128, Mm / 128);     // (8, 64)
    dim3 gF(FFf / 128, Mm / 128);    // (32, 64)

    // h = LN1(x)
    ln_kernel<<<Mm, blk>>>(x, ln1_g, ln1_b, h);
    // q,k,v = h @ W{q,k,v}  ([B,H,S,HD] layout)
    gemm_mma<MD_QKV><<<gD, blk, GEMM_SMEM>>>(h, Wq, nullptr, nullptr, q, Dd, Dd);
    gemm_mma<MD_QKV><<<gD, blk, GEMM_SMEM>>>(h, Wk, nullptr, nullptr, k, Dd, Dd);
    gemm_mma<MD_QKV><<<gD, blk, GEMM_SMEM>>>(h, Wv, nullptr, nullptr, v, Dd, Dd);
    // attention (tensor-core flash)
    attn_mma<<<dim3(Ss / 128, Bb * Hh), blk, ATT_SMEM>>>(q, k, v, o);
    // x2 = x + o @ Wo
    gemm_mma<MD_RES><<<gD, blk, GEMM_SMEM>>>(o, Wo, nullptr, x, x2, Dd, Dd);
    // h = LN2(x2)
    ln_kernel<<<Mm, blk>>>(x2, ln2_g, ln2_b, h);
    // ff1 = relu(h @ W1 + b1)
    gemm_mma<MD_BIAS | MD_RELU><<<gF, blk, GEMM_SMEM>>>(h, W1, b1, nullptr, ff1, FFf, Dd);
    // out = x2 + relu(ff1 @ W2 + b2)
    gemm_mma<MD_BIAS | MD_RELU | MD_RES><<<gD, blk, GEMM_SMEM>>>(ff1, W2, b2, x2, out, Dd, FFf);
}

// round 8
// speedup vs baseline: 2.3809x; 1.1668x over previous
#include <cuda_runtime.h>
#include <cuda_bf16.h>
#include <cstdint>

// ---------------------------------------------------------------------------
// TransformerLayer: B=4, S=2048, D=1024, H=16, HD=64, FF=4096, fp32 I/O.
// Round 7: pre-split fp32 -> bf16 hi/lo in gmem; GEMM is a pure cp.async
// 3-stage ldsm+mma pipeline (no in-kernel conversion).
// Attention unchanged from R6 (mma.sync flash, passing at 7.5e-6).
// ---------------------------------------------------------------------------

constexpr int Bb = 4, Ss = 2048, Dd = 1024, Hh = 16, HDd = 64, FFf = 4096;
constexpr int Mm = Bb * Ss;            // 8192 rows
constexpr float EPS = 1e-5f;
constexpr float SCL2 = 0.125f * 1.4426950408889634f;

// fp32 scratch
__device__ float g_h  [Mm * Dd];
__device__ float g_q  [Mm * Dd];
__device__ float g_k  [Mm * Dd];
__device__ float g_v  [Mm * Dd];
__device__ float g_o  [Mm * Dd];
__device__ float g_x2 [Mm * Dd];
__device__ float g_ff1[(size_t)Mm * FFf];
// bf16 hi/lo scratch
__device__ __nv_bfloat16 g_ah[(size_t)Mm * FFf];   // activations hi (max K=4096)
__device__ __nv_bfloat16 g_al[(size_t)Mm * FFf];   // activations lo
constexpr size_t WQO = 0, WKO = 1u << 20, WVO = 2u << 20, WOO = 3u << 20;
constexpr size_t W1O = 4u << 20, W2O = 8u << 20, WTOT = 12u << 20;
__device__ __nv_bfloat16 g_wh[WTOT];               // all weights hi, [K,N] layout
__device__ __nv_bfloat16 g_wl[WTOT];               // all weights lo

// ========================= small PTX helpers ===========================
__device__ __forceinline__ uint32_t smem_u32(const void* p) {
    uint32_t a;
    asm("{ .reg .u64 t; cvta.to.shared.u64 t, %1; cvt.u32.u64 %0, t; }" : "=r"(a) : "l"(p));
    return a;
}
__device__ __forceinline__ void ldsm_x4(uint32_t (&r)[4], uint32_t addr) {
    asm volatile("ldmatrix.sync.aligned.m8n8.x4.shared.b16 {%0,%1,%2,%3}, [%4];"
        : "=r"(r[0]), "=r"(r[1]), "=r"(r[2]), "=r"(r[3]) : "r"(addr));
}
__device__ __forceinline__ void ldsm_x4_t(uint32_t (&r)[4], uint32_t addr) {
    asm volatile("ldmatrix.sync.aligned.m8n8.x4.trans.shared.b16 {%0,%1,%2,%3}, [%4];"
        : "=r"(r[0]), "=r"(r[1]), "=r"(r[2]), "=r"(r[3]) : "r"(addr));
}
__device__ __forceinline__ void ldsm_x2_t(uint32_t (&r)[2], uint32_t addr) {
    asm volatile("ldmatrix.sync.aligned.m8n8.x2.trans.shared.b16 {%0,%1}, [%2];"
        : "=r"(r[0]), "=r"(r[1]) : "r"(addr));
}
__device__ __forceinline__ void mma16816(float (&c)[4], const uint32_t (&a)[4],
                                         uint32_t b0, uint32_t b1) {
    asm volatile("mma.sync.aligned.m16n8k16.row.col.f32.bf16.bf16.f32 "
        "{%0,%1,%2,%3}, {%4,%5,%6,%7}, {%8,%9}, {%0,%1,%2,%3};"
        : "+f"(c[0]), "+f"(c[1]), "+f"(c[2]), "+f"(c[3])
        : "r"(a[0]), "r"(a[1]), "r"(a[2]), "r"(a[3]), "r"(b0), "r"(b1));
}
__device__ __forceinline__ uint32_t pack_bf2(float a, float b) {
    __nv_bfloat162 h = __floats2bfloat162_rn(a, b);
    return *reinterpret_cast<uint32_t*>(&h);
}
__device__ __forceinline__ float ex2(float x) {
    float y;
    asm("ex2.approx.ftz.f32 %0, %1;" : "=f"(y) : "f"(x));
    return y;
}
__device__ __forceinline__ void cp16(uint32_t dst, const void* src) {
    asm volatile("cp.async.cg.shared.global [%0], [%1], 16;" :: "r"(dst), "l"(src) : "memory");
}
__device__ __forceinline__ void cp_commit() { asm volatile("cp.async.commit_group;" ::: "memory"); }
template <int N>
__device__ __forceinline__ void cp_wait() {
    asm volatile("cp.async.wait_group %0;" :: "n"(N) : "memory");
}

// ========================= LayerNorm ===========================
__global__ void __launch_bounds__(256) ln_kernel(
    const float* __restrict__ x, const float* __restrict__ g,
    const float* __restrict__ b, float* __restrict__ out)
{
    int row = blockIdx.x;
    int t = threadIdx.x;
    const float4 v = reinterpret_cast<const float4*>(x + (size_t)row * Dd)[t];
    float s  = v.x + v.y + v.z + v.w;
    float ss = v.x * v.x + v.y * v.y + v.z * v.z + v.w * v.w;
#pragma unroll
    for (int o = 16; o > 0; o >>= 1) {
        s  += __shfl_xor_sync(0xffffffffu, s,  o);
        ss += __shfl_xor_sync(0xffffffffu, ss, o);
    }
    __shared__ float red[16];
    int w = t >> 5;
    if ((t & 31) == 0) { red[w] = s; red[8 + w] = ss; }
    __syncthreads();
    float st = 0.f, sst = 0.f;
#pragma unroll
    for (int i = 0; i < 8; i++) { st += red[i]; sst += red[8 + i]; }
    float mu  = st  * (1.0f / Dd);
    float var = sst * (1.0f / Dd) - mu * mu;
    float inv = rsqrtf(var + EPS);
    float4 gg = reinterpret_cast<const float4*>(g)[t];
    float4 bb = reinterpret_cast<const float4*>(b)[t];
    float4 o4;
    o4.x = (v.x - mu) * inv * gg.x + bb.x;
    o4.y = (v.y - mu) * inv * gg.y + bb.y;
    o4.z = (v.z - mu) * inv * gg.z + bb.z;
    o4.w = (v.w - mu) * inv * gg.w + bb.w;
    reinterpret_cast<float4*>(out + (size_t)row * Dd)[t] = o4;
}

// ========================= split fp32 -> bf16 hi/lo =========================
__global__ void __launch_bounds__(256) split_kernel(
    const float* __restrict__ x, __nv_bfloat16* __restrict__ hi,
    __nv_bfloat16* __restrict__ lo, int n4)
{
    int i = blockIdx.x * 256 + threadIdx.x;
    if (i >= n4) return;
    float4 v = reinterpret_cast<const float4*>(x)[i];
    float f[4] = {v.x, v.y, v.z, v.w};
    uint32_t h[2], l[2];
#pragma unroll
    for (int e = 0; e < 2; e++) {
        float a = f[2 * e], b = f[2 * e + 1];
        __nv_bfloat16 ha = __float2bfloat16(a), hb = __float2bfloat16(b);
        h[e] = pack_bf2(a, b);
        l[e] = pack_bf2(a - __bfloat162float(ha), b - __bfloat162float(hb));
    }
    reinterpret_cast<uint2*>(hi)[i] = make_uint2(h[0], h[1]);
    reinterpret_cast<uint2*>(lo)[i] = make_uint2(l[0], l[1]);
}

// ========================= cp.async 3-stage split-bf16 GEMM ==================
// C[M,N] = A[M,K] @ W[K,N]; A,W pre-split to bf16 hi/lo in gmem.
// D = Ah*Bh + Ah*Bl + Al*Bh. CTA tile 128x128x32, 8 warps (64x32 each).
constexpr int MD_BIAS = 1, MD_RELU = 2, MD_RES = 4, MD_QKV = 8;

constexpr int NSTG = 3;
constexpr int LDA = 40;                        // bf16 elems per A smem row
constexpr int LDB = 136;                       // bf16 elems per B smem row
constexpr int A_BYTES = 128 * LDA * 2;         // 10240 per matrix
constexpr int B_BYTES = 32 * LDB * 2;          // 8704 per matrix
constexpr int B_OFF   = 2 * A_BYTES;           // 20480
constexpr int STAGE   = 2 * A_BYTES + 2 * B_BYTES;  // 37888
constexpr int GEMM_SMEM = NSTG * STAGE;        // 113664

template <int MODE>
__global__ void __launch_bounds__(256, 1) gemm_mma(
    const __nv_bfloat16* __restrict__ Ah, const __nv_bfloat16* __restrict__ Al,
    const __nv_bfloat16* __restrict__ Bh, const __nv_bfloat16* __restrict__ Bl,
    const float* __restrict__ bias, const float* __restrict__ res,
    float* __restrict__ C, int N, int K)
{
    extern __shared__ char dsm[];
    const uint32_t smemU = smem_u32(dsm);

    const int tid  = threadIdx.x;
    const int lane = tid & 31;
    const int wid  = tid >> 5;
    const int wm   = wid >> 2;
    const int wn   = wid & 3;
    const int m0   = blockIdx.y * 128;
    const int n0   = blockIdx.x * 128;
    const int NC   = K >> 5;

    // producer addressing: A chunks (row, 4 x 16B segs), B chunks (row, 16 segs)
    const int ar0 = tid >> 1;             // +0, +128 rows via second chunk? no:
    // A: 512 chunks of 16B per matrix. thread does chunks tid, tid+256.
    // chunk c: row=c>>2, seg=c&3.
    // B: 512 chunks: row=c>>4, seg=c&15.

    auto issue_stage = [&](int c) {
        const int s = c % NSTG;
        const uint32_t sb = smemU + (uint32_t)s * STAGE;
        const int k0 = c << 5;
#pragma unroll
        for (int i = 0; i < 2; i++) {
            int ch = tid + i * 256;
            int arow = ch >> 2, aseg = ch & 3;
            uint32_t ad = sb + ((uint32_t)arow * LDA + (uint32_t)aseg * 8u) * 2u;
            const __nv_bfloat16* asrc = Ah + (size_t)(m0 + arow) * K + k0 + aseg * 8;
            const __nv_bfloat16* asrl = Al + (size_t)(m0 + arow) * K + k0 + aseg * 8;
            cp16(ad, asrc);
            cp16(ad + A_BYTES, asrl);
            int brow = ch >> 4, bseg = ch & 15;
            uint32_t bd = sb + (uint32_t)B_OFF + ((uint32_t)brow * LDB + (uint32_t)bseg * 8u) * 2u;
            const __nv_bfloat16* bsrc = Bh + (size_t)(k0 + brow) * N + n0 + bseg * 8;
            const __nv_bfloat16* bsrl = Bl + (size_t)(k0 + brow) * N + n0 + bseg * 8;
            cp16(bd, bsrc);
            cp16(bd + B_BYTES, bsrl);
        }
        cp_commit();
    };

    issue_stage(0);
    issue_stage(1);

    float acc[4][4][4];
#pragma unroll
    for (int mt = 0; mt < 4; mt++)
#pragma unroll
        for (int nt = 0; nt < 4; nt++)
#pragma unroll
            for (int e = 0; e < 4; e++) acc[mt][nt][e] = 0.f;

    const uint32_t aCmp0 = smemU + ((uint32_t)(wm * 64 + (lane & 15)) * LDA +
                                    (uint32_t)(lane >> 4) * 8) * 2u;
    const uint32_t bCmp0 = smemU + (uint32_t)B_OFF +
                           ((uint32_t)(lane & 15) * LDB + (uint32_t)(wn * 32)) * 2u;

    for (int c = 0; c < NC; c++) {
        cp_wait<1>();
        __syncthreads();

        const uint32_t so = (uint32_t)(c % NSTG) * STAGE;
        const uint32_t aC = aCmp0 + so;
        const uint32_t bC = bCmp0 + so;
#pragma unroll
        for (int ks = 0; ks < 2; ks++) {
            uint32_t Ahf[4][4], Alf[4][4], Bhf[4][2], Blf[4][2];
#pragma unroll
            for (int mt = 0; mt < 4; mt++) {
                uint32_t ad = aC + (uint32_t)mt * (16 * LDA * 2) + (uint32_t)ks * 32;
                ldsm_x4(Ahf[mt], ad);
                ldsm_x4(Alf[mt], ad + A_BYTES);
            }
#pragma unroll
            for (int nt = 0; nt < 4; nt++) {
                uint32_t bd = bC + (uint32_t)ks * (16 * LDB * 2) + (uint32_t)nt * 16;
                ldsm_x2_t(Bhf[nt], bd);
                ldsm_x2_t(Blf[nt], bd + B_BYTES);
            }
#pragma unroll
            for (int mt = 0; mt < 4; mt++)
#pragma unroll
                for (int nt = 0; nt < 4; nt++) {
                    mma16816(acc[mt][nt], Ahf[mt], Bhf[nt][0], Bhf[nt][1]);
                    mma16816(acc[mt][nt], Ahf[mt], Blf[nt][0], Blf[nt][1]);
                    mma16816(acc[mt][nt], Alf[mt], Bhf[nt][0], Bhf[nt][1]);
                }
        }
        __syncthreads();
        if (c + 2 < NC) issue_stage(c + 2);
    }

    // -------- epilogue --------
    const int rbase = m0 + wm * 64;
    const int cbase = n0 + wn * 32;
#pragma unroll
    for (int mt = 0; mt < 4; mt++)
#pragma unroll
        for (int nt = 0; nt < 4; nt++) {
#pragma unroll
            for (int half = 0; half < 2; half++) {
                int r = rbase + mt * 16 + (lane >> 2) + half * 8;
                int cc = cbase + nt * 8 + (lane & 3) * 2;
                float2 v;
                v.x = acc[mt][nt][half * 2 + 0];
                v.y = acc[mt][nt][half * 2 + 1];
                if (MODE & MD_BIAS) {
                    float2 bb = *reinterpret_cast<const float2*>(bias + cc);
                    v.x += bb.x; v.y += bb.y;
                }
                if (MODE & MD_RELU) {
                    v.x = fmaxf(v.x, 0.f); v.y = fmaxf(v.y, 0.f);
                }
                if (MODE & MD_RES) {
                    float2 rr = *reinterpret_cast<const float2*>(res + (size_t)r * N + cc);
                    v.x += rr.x; v.y += rr.y;
                }
                if (MODE & MD_QKV) {
                    int b_ = r >> 11, s_ = r & (Ss - 1);
                    int h_ = cc >> 6, d_ = cc & 63;
                    *reinterpret_cast<float2*>(C +
                        ((size_t)(b_ * Hh + h_) * Ss + s_) * HDd + d_) = v;
                } else {
                    *reinterpret_cast<float2*>(C + (size_t)r * N + cc) = v;
                }
            }
        }
}

// ========================= mma.sync flash attention (R6, unchanged) =========
constexpr int ALD = 72;
constexpr int KMAT = 64 * ALD * 2;
constexpr int ASTAGE = 4 * KMAT;
constexpr int QOFF = 2 * ASTAGE;
constexpr int QMAT = 128 * ALD * 2;
constexpr int ATT_SMEM = QOFF + 2 * QMAT;

__global__ void __launch_bounds__(256, 1) attn_mma(
    const float* __restrict__ q, const float* __restrict__ k,
    const float* __restrict__ v, float* __restrict__ o)
{
    extern __shared__ char sm[];
    const uint32_t S0 = smem_u32(sm);
    const int tid = threadIdx.x, lane = tid & 31, w = tid >> 5;
    const int bh = blockIdx.y, q0 = blockIdx.x * 128;
    const int b_ = bh >> 4, h_ = bh & 15;

    const float* qb = q + ((size_t)bh * Ss + q0) * HDd;
    const float* kb = k + (size_t)bh * Ss * HDd;
    const float* vb = v + (size_t)bh * Ss * HDd;

    {
        int r = tid >> 1, cb = (tid & 1) * 32;
        const float4* src = reinterpret_cast<const float4*>(qb + r * HDd + cb);
        char* qh = sm + QOFF;
        char* ql = qh + QMAT;
        uint32_t off = ((uint32_t)r * ALD + (uint32_t)cb) * 2u;
#pragma unroll
        for (int j = 0; j < 8; j += 2) {
            uint32_t hw[4], lw[4];
#pragma unroll
            for (int e = 0; e < 2; e++) {
                float4 f = src[j + e];
                float a = f.x * SCL2, b2 = f.y * SCL2, c = f.z * SCL2, d = f.w * SCL2;
                __nv_bfloat16 ha = __float2bfloat16(a), hb = __float2bfloat16(b2);
                __nv_bfloat16 hc = __float2bfloat16(c), hd = __float2bfloat16(d);
                hw[2 * e + 0] = pack_bf2(a, b2);
                hw[2 * e + 1] = pack_bf2(c, d);
                lw[2 * e + 0] = pack_bf2(a - __bfloat162float(ha), b2 - __bfloat162float(hb));
                lw[2 * e + 1] = pack_bf2(c - __bfloat162float(hc), d - __bfloat162float(hd));
            }
            *reinterpret_cast<uint4*>(qh + off + j * 8) = make_uint4(hw[0], hw[1], hw[2], hw[3]);
            *reinterpret_cast<uint4*>(ql + off + j * 8) = make_uint4(lw[0], lw[1], lw[2], lw[3]);
        }
    }
    __syncthreads();

    uint32_t Qh[4][4], Ql[4][4];
    {
        uint32_t base = S0 + QOFF +
            (((uint32_t)(w * 16 + (lane & 15))) * ALD + (uint32_t)(lane >> 4) * 8u) * 2u;
#pragma unroll
        for (int ks = 0; ks < 4; ks++) {
            ldsm_x4(Qh[ks], base + (uint32_t)ks * 32u);
            ldsm_x4(Ql[ks], base + (uint32_t)QMAT + (uint32_t)ks * 32u);
        }
    }

    float oa[8][4];
#pragma unroll
    for (int nt = 0; nt < 8; nt++)
#pragma unroll
        for (int e = 0; e < 4; e++) oa[nt][e] = 0.f;
    float mrow[2] = {-1e30f, -1e30f};
    float lrow[2] = {0.f, 0.f};

    const int krow = tid >> 2, kcb = (tid & 3) * 16;
    float4 rk[4], rv[4];
    {
        const float4* kp = reinterpret_cast<const float4*>(kb + (size_t)krow * HDd + kcb);
        const float4* vp = reinterpret_cast<const float4*>(vb + (size_t)krow * HDd + kcb);
#pragma unroll
        for (int j = 0; j < 4; j++) { rk[j] = kp[j]; rv[j] = vp[j]; }
    }

    const uint32_t stoff = ((uint32_t)krow * ALD + (uint32_t)kcb) * 2u;

    for (int t = 0; t < Ss / 64; t++) {
        const int s = t & 1;
        char* sb = sm + s * ASTAGE;
        const uint32_t sbU = S0 + (uint32_t)(s * ASTAGE);

        {
            uint32_t hw[8], lw[8];
#pragma unroll
            for (int j = 0; j < 4; j++) {
                float f0 = rk[j].x, f1 = rk[j].y, f2 = rk[j].z, f3 = rk[j].w;
                __nv_bfloat16 h0 = __float2bfloat16(f0), h1 = __float2bfloat16(f1);
                __nv_bfloat16 h2 = __float2bfloat16(f2), h3 = __float2bfloat16(f3);
                hw[2 * j] = pack_bf2(f0, f1); hw[2 * j + 1] = pack_bf2(f2, f3);
                lw[2 * j] = pack_bf2(f0 - __bfloat162float(h0), f1 - __bfloat162float(h1));
                lw[2 * j + 1] = pack_bf2(f2 - __bfloat162float(h2), f3 - __bfloat162float(h3));
            }
            *reinterpret_cast<uint4*>(sb + stoff)      = make_uint4(hw[0], hw[1], hw[2], hw[3]);
            *reinterpret_cast<uint4*>(sb + stoff + 16) = make_uint4(hw[4], hw[5], hw[6], hw[7]);
            *reinterpret_cast<uint4*>(sb + KMAT + stoff)      = make_uint4(lw[0], lw[1], lw[2], lw[3]);
            *reinterpret_cast<uint4*>(sb + KMAT + stoff + 16) = make_uint4(lw[4], lw[5], lw[6], lw[7]);
#pragma unroll
            for (int j = 0; j < 4; j++) {
                float f0 = rv[j].x, f1 = rv[j].y, f2 = rv[j].z, f3 = rv[j].w;
                __nv_bfloat16 h0 = __float2bfloat16(f0), h1 = __float2bfloat16(f1);
                __nv_bfloat16 h2 = __float2bfloat16(f2), h3 = __float2bfloat16(f3);
                hw[2 * j] = pack_bf2(f0, f1); hw[2 * j + 1] = pack_bf2(f2, f3);
                lw[2 * j] = pack_bf2(f0 - __bfloat162float(h0), f1 - __bfloat162float(h1));
                lw[2 * j + 1] = pack_bf2(f2 - __bfloat162float(h2), f3 - __bfloat162float(h3));
            }
            *reinterpret_cast<uint4*>(sb + 2 * KMAT + stoff)      = make_uint4(hw[0], hw[1], hw[2], hw[3]);
            *reinterpret_cast<uint4*>(sb + 2 * KMAT + stoff + 16) = make_uint4(hw[4], hw[5], hw[6], hw[7]);
            *reinterpret_cast<uint4*>(sb + 3 * KMAT + stoff)      = make_uint4(lw[0], lw[1], lw[2], lw[3]);
            *reinterpret_cast<uint4*>(sb + 3 * KMAT + stoff + 16) = make_uint4(lw[4], lw[5], lw[6], lw[7]);
        }
        __syncthreads();

        if (t + 1 < Ss / 64) {
            const float4* kp = reinterpret_cast<const float4*>(
                kb + (size_t)((t + 1) * 64 + krow) * HDd + kcb);
            const float4* vp = reinterpret_cast<const float4*>(
                vb + (size_t)((t + 1) * 64 + krow) * HDd + kcb);
#pragma unroll
            for (int j = 0; j < 4; j++) { rk[j] = kp[j]; rv[j] = vp[j]; }
        }

        float sc[8][4];
#pragma unroll
        for (int nt = 0; nt < 8; nt++)
#pragma unroll
            for (int e = 0; e < 4; e++) sc[nt][e] = 0.f;

        const uint32_t kfb = sbU + (uint32_t)(lane >> 4) * (uint32_t)KMAT +
            (((uint32_t)(lane & 7)) * ALD + (uint32_t)((lane >> 3) & 1) * 8u) * 2u;
#pragma unroll
        for (int nt = 0; nt < 8; nt++) {
#pragma unroll
            for (int ks = 0; ks < 4; ks++) {
                uint32_t kf[4];
                ldsm_x4(kf, kfb + ((uint32_t)nt * 8u * ALD + (uint32_t)ks * 16u) * 2u);
                mma16816(sc[nt], Qh[ks], kf[0], kf[1]);
                mma16816(sc[nt], Qh[ks], kf[2], kf[3]);
                mma16816(sc[nt], Ql[ks], kf[0], kf[1]);
            }
        }

        float mt0 = sc[0][0], mt1 = sc[0][2];
#pragma unroll
        for (int nt = 0; nt < 8; nt++) {
            mt0 = fmaxf(mt0, fmaxf(sc[nt][0], sc[nt][1]));
            mt1 = fmaxf(mt1, fmaxf(sc[nt][2], sc[nt][3]));
        }
        mt0 = fmaxf(mt0, __shfl_xor_sync(0xffffffffu, mt0, 1));
        mt0 = fmaxf(mt0, __shfl_xor_sync(0xffffffffu, mt0, 2));
        mt1 = fmaxf(mt1, __shfl_xor_sync(0xffffffffu, mt1, 1));
        mt1 = fmaxf(mt1, __shfl_xor_sync(0xffffffffu, mt1, 2));
        float mn0 = fmaxf(mrow[0], mt0), mn1 = fmaxf(mrow[1], mt1);
        float c0 = ex2(mrow[0] - mn0), c1 = ex2(mrow[1] - mn1);
        mrow[0] = mn0; mrow[1] = mn1;

        float ls0 = 0.f, ls1 = 0.f;
#pragma unroll
        for (int nt = 0; nt < 8; nt++) {
            sc[nt][0] = ex2(sc[nt][0] - mn0);
            sc[nt][1] = ex2(sc[nt][1] - mn0);
            sc[nt][2] = ex2(sc[nt][2] - mn1);
            sc[nt][3] = ex2(sc[nt][3] - mn1);
            ls0 += sc[nt][0] + sc[nt][1];
            ls1 += sc[nt][2] + sc[nt][3];
        }
        ls0 += __shfl_xor_sync(0xffffffffu, ls0, 1);
        ls0 += __shfl_xor_sync(0xffffffffu, ls0, 2);
        ls1 += __shfl_xor_sync(0xffffffffu, ls1, 1);
        ls1 += __shfl_xor_sync(0xffffffffu, ls1, 2);
        lrow[0] = lrow[0] * c0 + ls0;
        lrow[1] = lrow[1] * c1 + ls1;
#pragma unroll
        for (int nt = 0; nt < 8; nt++) {
            oa[nt][0] *= c0; oa[nt][1] *= c0;
            oa[nt][2] *= c1; oa[nt][3] *= c1;
        }

        uint32_t Ph[4][4], Pl[4][4];
#pragma unroll
        for (int kk = 0; kk < 4; kk++) {
#pragma unroll
            for (int half = 0; half < 2; half++) {
                float p0 = sc[2 * kk + half][0], p1 = sc[2 * kk + half][1];
                float p2 = sc[2 * kk + half][2], p3 = sc[2 * kk + half][3];
                __nv_bfloat16 h0 = __float2bfloat16(p0), h1 = __float2bfloat16(p1);
                __nv_bfloat16 h2 = __float2bfloat16(p2), h3 = __float2bfloat16(p3);
                Ph[kk][2 * half + 0] = pack_bf2(p0, p1);
                Ph[kk][2 * half + 1] = pack_bf2(p2, p3);
                Pl[kk][2 * half + 0] = pack_bf2(p0 - __bfloat162float(h0),
                                                p1 - __bfloat162float(h1));
                Pl[kk][2 * half + 1] = pack_bf2(p2 - __bfloat162float(h2),
                                                p3 - __bfloat162float(h3));
            }
        }

        const uint32_t vfb = sbU + 2u * (uint32_t)KMAT +
            (uint32_t)(lane >> 4) * (uint32_t)KMAT +
            ((uint32_t)(lane & 15)) * (uint32_t)ALD * 2u;
#pragma unroll
        for (int kk = 0; kk < 4; kk++) {
#pragma unroll
            for (int nt = 0; nt < 8; nt++) {
                uint32_t vf[4];
                ldsm_x4_t(vf, vfb + ((uint32_t)kk * 16u * ALD + (uint32_t)nt * 8u) * 2u);
                mma16816(oa[nt], Ph[kk], vf[0], vf[1]);
                mma16816(oa[nt], Ph[kk], vf[2], vf[3]);
                mma16816(oa[nt], Pl[kk], vf[0], vf[1]);
            }
        }
        __syncthreads();
    }

    float il0 = 1.0f / lrow[0], il1 = 1.0f / lrow[1];
    int sr0 = q0 + w * 16 + (lane >> 2);
    int sr1 = sr0 + 8;
#pragma unroll
    for (int nt = 0; nt < 8; nt++) {
        int col = h_ * HDd + nt * 8 + (lane & 3) * 2;
        float2 v0, v1;
        v0.x = oa[nt][0] * il0; v0.y = oa[nt][1] * il0;
        v1.x = oa[nt][2] * il1; v1.y = oa[nt][3] * il1;
        *reinterpret_cast<float2*>(o + ((size_t)(b_ * Ss + sr0)) * Dd + col) = v0;
        *reinterpret_cast<float2*>(o + ((size_t)(b_ * Ss + sr1)) * Dd + col) = v1;
    }
}

// ========================= launch ===========================
extern "C" void kernel_launch(void* const* d_in, const int* in_sizes, int n_in,
                              void* d_out, int out_size)
{
    const float* x     = (const float*)d_in[0];
    const float* ln1_g = (const float*)d_in[1];
    const float* ln1_b = (const float*)d_in[2];
    const float* ln2_g = (const float*)d_in[3];
    const float* ln2_b = (const float*)d_in[4];
    const float* Wq    = (const float*)d_in[5];
    const float* Wk    = (const float*)d_in[6];
    const float* Wv    = (const float*)d_in[7];
    const float* Wo    = (const float*)d_in[8];
    const float* W1    = (const float*)d_in[9];
    const float* b1    = (const float*)d_in[10];
    const float* W2    = (const float*)d_in[11];
    const float* b2    = (const float*)d_in[12];
    float* out = (float*)d_out;

    float *h, *q, *k, *v, *o, *x2, *ff1;
    __nv_bfloat16 *ah, *al, *wh, *wl;
    cudaGetSymbolAddress((void**)&h,   g_h);
    cudaGetSymbolAddress((void**)&q,   g_q);
    cudaGetSymbolAddress((void**)&k,   g_k);
    cudaGetSymbolAddress((void**)&v,   g_v);
    cudaGetSymbolAddress((void**)&o,   g_o);
    cudaGetSymbolAddress((void**)&x2,  g_x2);
    cudaGetSymbolAddress((void**)&ff1, g_ff1);
    cudaGetSymbolAddress((void**)&ah,  g_ah);
    cudaGetSymbolAddress((void**)&al,  g_al);
    cudaGetSymbolAddress((void**)&wh,  g_wh);
    cudaGetSymbolAddress((void**)&wl,  g_wl);

    cudaFuncSetAttribute(gemm_mma<MD_QKV>, cudaFuncAttributeMaxDynamicSharedMemorySize, GEMM_SMEM);
    cudaFuncSetAttribute(gemm_mma<MD_RES>, cudaFuncAttributeMaxDynamicSharedMemorySize, GEMM_SMEM);
    cudaFuncSetAttribute(gemm_mma<MD_BIAS | MD_RELU>, cudaFuncAttributeMaxDynamicSharedMemorySize, GEMM_SMEM);
    cudaFuncSetAttribute(gemm_mma<MD_BIAS | MD_RELU | MD_RES>, cudaFuncAttributeMaxDynamicSharedMemorySize, GEMM_SMEM);
    cudaFuncSetAttribute(attn_mma, cudaFuncAttributeMaxDynamicSharedMemorySize, ATT_SMEM);

    dim3 blk(256);
    dim3 gD(Dd / 128, Mm / 128);     // (8, 64)
    dim3 gF(FFf / 128, Mm / 128);    // (32, 64)
    const int MD4 = Mm * Dd / 4, QD4 = Dd * Dd / 4, FD4 = Dd * FFf / 4;

    // ---- weight splits (once per call) ----
    split_kernel<<<QD4 / 256, blk>>>(Wq, wh + WQO, wl + WQO, QD4);
    split_kernel<<<QD4 / 256, blk>>>(Wk, wh + WKO, wl + WKO, QD4);
    split_kernel<<<QD4 / 256, blk>>>(Wv, wh + WVO, wl + WVO, QD4);
    split_kernel<<<QD4 / 256, blk>>>(Wo, wh + WOO, wl + WOO, QD4);
    split_kernel<<<FD4 / 256, blk>>>(W1, wh + W1O, wl + W1O, FD4);
    split_kernel<<<FD4 / 256, blk>>>(W2, wh + W2O, wl + W2O, FD4);

    // h = LN1(x); split
    ln_kernel<<<Mm, blk>>>(x, ln1_g, ln1_b, h);
    split_kernel<<<MD4 / 256, blk>>>(h, ah, al, MD4);
    // q,k,v = h @ W{q,k,v}  ([B,H,S,HD] layout)
    gemm_mma<MD_QKV><<<gD, blk, GEMM_SMEM>>>(ah, al, wh + WQO, wl + WQO, nullptr, nullptr, q, Dd, Dd);
    gemm_mma<MD_QKV><<<gD, blk, GEMM_SMEM>>>(ah, al, wh + WKO, wl + WKO, nullptr, nullptr, k, Dd, Dd);
    gemm_mma<MD_QKV><<<gD, blk, GEMM_SMEM>>>(ah, al, wh + WVO, wl + WVO, nullptr, nullptr, v, Dd, Dd);
    // attention
    attn_mma<<<dim3(Ss / 128, Bb * Hh), blk, ATT_SMEM>>>(q, k, v, o);
    // x2 = x + o @ Wo
    split_kernel<<<MD4 / 256, blk>>>(o, ah, al, MD4);
    gemm_mma<MD_RES><<<gD, blk, GEMM_SMEM>>>(ah, al, wh + WOO, wl + WOO, nullptr, x, x2, Dd, Dd);
    // h = LN2(x2); split
    ln_kernel<<<Mm, blk>>>(x2, ln2_g, ln2_b, h);
    split_kernel<<<MD4 / 256, blk>>>(h, ah, al, MD4);
    // ff1 = relu(h @ W1 + b1)
    gemm_mma<MD_BIAS | MD_RELU><<<gF, blk, GEMM_SMEM>>>(ah, al, wh + W1O, wl + W1O, b1, nullptr, ff1, FFf, Dd);
    // out = x2 + relu(ff1 @ W2 + b2)
    split_kernel<<<(Mm / 256) * (FFf / 4), blk>>>(ff1, ah, al, Mm * (FFf / 4));
    gemm_mma<MD_BIAS | MD_RELU | MD_RES><<<gD, blk, GEMM_SMEM>>>(ah, al, wh + W2O, wl + W2O, b2, x2, out, Dd, FFf);
}

// round 9
// speedup vs baseline: 2.6322x; 1.1055x over previous
#include <cuda_runtime.h>
#include <cuda_bf16.h>
#include <cstdint>

// ---------------------------------------------------------------------------
// TransformerLayer: B=4, S=2048, D=1024, H=16, HD=64, FF=4096, fp32 I/O.
// Round 8: GEMM CTA tile 256x128 (8 warps x 64x64), 1 barrier/chunk, NSTG=3
// cp.async pipeline. All activation hi/lo splits fused into producers
// (LN, attention epilogue, W1 epilogue) — no fp32 activation round-trips.
// ---------------------------------------------------------------------------

constexpr int Bb = 4, Ss = 2048, Dd = 1024, Hh = 16, HDd = 64, FFf = 4096;
constexpr int Mm = Bb * Ss;            // 8192 rows
constexpr float EPS = 1e-5f;
constexpr float SCL2 = 0.125f * 1.4426950408889634f;

// fp32 scratch
__device__ float g_q  [Mm * Dd];
__device__ float g_k  [Mm * Dd];
__device__ float g_v  [Mm * Dd];
__device__ float g_x2 [Mm * Dd];
// bf16 hi/lo activation scratch
__device__ __nv_bfloat16 g_xh[(size_t)Mm * Dd];    // LN output hi
__device__ __nv_bfloat16 g_xl[(size_t)Mm * Dd];    // LN output lo
__device__ __nv_bfloat16 g_oh[(size_t)Mm * Dd];    // attention out hi
__device__ __nv_bfloat16 g_ol[(size_t)Mm * Dd];    // attention out lo
__device__ __nv_bfloat16 g_fh[(size_t)Mm * FFf];   // ff1 hi
__device__ __nv_bfloat16 g_fl[(size_t)Mm * FFf];   // ff1 lo
// bf16 hi/lo weights, [K,N] layout
constexpr size_t WQO = 0, WKO = 1u << 20, WVO = 2u << 20, WOO = 3u << 20;
constexpr size_t W1O = 4u << 20, W2O = 8u << 20, WTOT = 12u << 20;
__device__ __nv_bfloat16 g_wh[WTOT];
__device__ __nv_bfloat16 g_wl[WTOT];

// ========================= small PTX helpers ===========================
__device__ __forceinline__ uint32_t smem_u32(const void* p) {
    uint32_t a;
    asm("{ .reg .u64 t; cvta.to.shared.u64 t, %1; cvt.u32.u64 %0, t; }" : "=r"(a) : "l"(p));
    return a;
}
__device__ __forceinline__ void ldsm_x4(uint32_t (&r)[4], uint32_t addr) {
    asm volatile("ldmatrix.sync.aligned.m8n8.x4.shared.b16 {%0,%1,%2,%3}, [%4];"
        : "=r"(r[0]), "=r"(r[1]), "=r"(r[2]), "=r"(r[3]) : "r"(addr));
}
__device__ __forceinline__ void ldsm_x4_t(uint32_t (&r)[4], uint32_t addr) {
    asm volatile("ldmatrix.sync.aligned.m8n8.x4.trans.shared.b16 {%0,%1,%2,%3}, [%4];"
        : "=r"(r[0]), "=r"(r[1]), "=r"(r[2]), "=r"(r[3]) : "r"(addr));
}
__device__ __forceinline__ void ldsm_x2_t(uint32_t (&r)[2], uint32_t addr) {
    asm volatile("ldmatrix.sync.aligned.m8n8.x2.trans.shared.b16 {%0,%1}, [%2];"
        : "=r"(r[0]), "=r"(r[1]) : "r"(addr));
}
__device__ __forceinline__ void mma16816(float (&c)[4], const uint32_t (&a)[4],
                                         uint32_t b0, uint32_t b1) {
    asm volatile("mma.sync.aligned.m16n8k16.row.col.f32.bf16.bf16.f32 "
        "{%0,%1,%2,%3}, {%4,%5,%6,%7}, {%8,%9}, {%0,%1,%2,%3};"
        : "+f"(c[0]), "+f"(c[1]), "+f"(c[2]), "+f"(c[3])
        : "r"(a[0]), "r"(a[1]), "r"(a[2]), "r"(a[3]), "r"(b0), "r"(b1));
}
__device__ __forceinline__ uint32_t pack_bf2(float a, float b) {
    __nv_bfloat162 h = __floats2bfloat162_rn(a, b);
    return *reinterpret_cast<uint32_t*>(&h);
}
__device__ __forceinline__ float ex2(float x) {
    float y;
    asm("ex2.approx.ftz.f32 %0, %1;" : "=f"(y) : "f"(x));
    return y;
}
__device__ __forceinline__ void cp16(uint32_t dst, const void* src) {
    asm volatile("cp.async.cg.shared.global [%0], [%1], 16;" :: "r"(dst), "l"(src) : "memory");
}
__device__ __forceinline__ void cp_commit() { asm volatile("cp.async.commit_group;" ::: "memory"); }
template <int N>
__device__ __forceinline__ void cp_wait() {
    asm volatile("cp.async.wait_group %0;" :: "n"(N) : "memory");
}

// ========================= LayerNorm (writes hi/lo bf16) ====================
__global__ void __launch_bounds__(256) ln_split_kernel(
    const float* __restrict__ x, const float* __restrict__ g,
    const float* __restrict__ b, __nv_bfloat16* __restrict__ oh,
    __nv_bfloat16* __restrict__ ol)
{
    int row = blockIdx.x;
    int t = threadIdx.x;
    const float4 v = reinterpret_cast<const float4*>(x + (size_t)row * Dd)[t];
    float s  = v.x + v.y + v.z + v.w;
    float ss = v.x * v.x + v.y * v.y + v.z * v.z + v.w * v.w;
#pragma unroll
    for (int o = 16; o > 0; o >>= 1) {
        s  += __shfl_xor_sync(0xffffffffu, s,  o);
        ss += __shfl_xor_sync(0xffffffffu, ss, o);
    }
    __shared__ float red[16];
    int w = t >> 5;
    if ((t & 31) == 0) { red[w] = s; red[8 + w] = ss; }
    __syncthreads();
    float st = 0.f, sst = 0.f;
#pragma unroll
    for (int i = 0; i < 8; i++) { st += red[i]; sst += red[8 + i]; }
    float mu  = st  * (1.0f / Dd);
    float var = sst * (1.0f / Dd) - mu * mu;
    float inv = rsqrtf(var + EPS);
    float4 gg = reinterpret_cast<const float4*>(g)[t];
    float4 bb = reinterpret_cast<const float4*>(b)[t];
    float f[4];
    f[0] = (v.x - mu) * inv * gg.x + bb.x;
    f[1] = (v.y - mu) * inv * gg.y + bb.y;
    f[2] = (v.z - mu) * inv * gg.z + bb.z;
    f[3] = (v.w - mu) * inv * gg.w + bb.w;
    uint32_t hw[2], lw[2];
#pragma unroll
    for (int e = 0; e < 2; e++) {
        float a = f[2 * e], c = f[2 * e + 1];
        __nv_bfloat16 ha = __float2bfloat16(a), hc = __float2bfloat16(c);
        hw[e] = pack_bf2(a, c);
        lw[e] = pack_bf2(a - __bfloat162float(ha), c - __bfloat162float(hc));
    }
    size_t idx = (size_t)row * (Dd / 4) + t;
    reinterpret_cast<uint2*>(oh)[idx] = make_uint2(hw[0], hw[1]);
    reinterpret_cast<uint2*>(ol)[idx] = make_uint2(lw[0], lw[1]);
}

// ========================= split fp32 -> bf16 hi/lo (weights) ===============
__global__ void __launch_bounds__(256) split_kernel(
    const float* __restrict__ x, __nv_bfloat16* __restrict__ hi,
    __nv_bfloat16* __restrict__ lo, int n4)
{
    int i = blockIdx.x * 256 + threadIdx.x;
    if (i >= n4) return;
    float4 v = reinterpret_cast<const float4*>(x)[i];
    float f[4] = {v.x, v.y, v.z, v.w};
    uint32_t h[2], l[2];
#pragma unroll
    for (int e = 0; e < 2; e++) {
        float a = f[2 * e], b = f[2 * e + 1];
        __nv_bfloat16 ha = __float2bfloat16(a), hb = __float2bfloat16(b);
        h[e] = pack_bf2(a, b);
        l[e] = pack_bf2(a - __bfloat162float(ha), b - __bfloat162float(hb));
    }
    reinterpret_cast<uint2*>(hi)[i] = make_uint2(h[0], h[1]);
    reinterpret_cast<uint2*>(lo)[i] = make_uint2(l[0], l[1]);
}

// ========================= cp.async split-bf16 GEMM =========================
// C[M,N] = A[M,K] @ W[K,N]; both pre-split bf16 hi/lo. D = AhBh + AhBl + AlBh.
// CTA tile 256x128x32; 8 warps as 4(m) x 2(n), warp tile 64x64.
constexpr int MD_BIAS = 1, MD_RELU = 2, MD_RES = 4, MD_QKV = 8, MD_SPLIT = 16;

constexpr int NSTG = 3;
constexpr int LDA = 40;                         // bf16 elems per A smem row
constexpr int LDB = 136;                        // bf16 elems per B smem row
constexpr int A_BYTES = 256 * LDA * 2;          // 20480 per matrix
constexpr int B_BYTES = 32 * LDB * 2;           // 8704 per matrix
constexpr int B_OFF   = 2 * A_BYTES;            // 40960
constexpr int STAGE   = 2 * A_BYTES + 2 * B_BYTES;   // 58368
constexpr int GEMM_SMEM = NSTG * STAGE;         // 175104

template <int MODE>
__global__ void __launch_bounds__(256, 1) gemm_mma(
    const __nv_bfloat16* __restrict__ Ah, const __nv_bfloat16* __restrict__ Al,
    const __nv_bfloat16* __restrict__ Bh, const __nv_bfloat16* __restrict__ Bl,
    const float* __restrict__ bias, const float* __restrict__ res,
    float* __restrict__ C, __nv_bfloat16* __restrict__ Chi,
    __nv_bfloat16* __restrict__ Clo, int N, int K)
{
    extern __shared__ char dsm[];
    const uint32_t smemU = smem_u32(dsm);

    const int tid  = threadIdx.x;
    const int lane = tid & 31;
    const int wid  = tid >> 5;
    const int wm   = wid >> 1;          // 0..3 (64-row slab)
    const int wn   = wid & 1;           // 0..1 (64-col slab)
    const int m0   = blockIdx.y * 256;
    const int n0   = blockIdx.x * 128;
    const int NC   = K >> 5;

    auto issue_stage = [&](int c) {
        const int s = c % NSTG;
        const uint32_t sb = smemU + (uint32_t)s * STAGE;
        const int k0 = c << 5;
        // A: 1024 16B-chunks per matrix (256 rows x 4 segs); 4 per thread
#pragma unroll
        for (int i = 0; i < 4; i++) {
            int ch = tid + i * 256;
            int arow = ch >> 2, aseg = ch & 3;
            uint32_t ad = sb + ((uint32_t)arow * LDA + (uint32_t)aseg * 8u) * 2u;
            cp16(ad, Ah + (size_t)(m0 + arow) * K + k0 + aseg * 8);
            cp16(ad + A_BYTES, Al + (size_t)(m0 + arow) * K + k0 + aseg * 8);
        }
        // B: 512 chunks per matrix (32 rows x 16 segs); 2 per thread
#pragma unroll
        for (int i = 0; i < 2; i++) {
            int ch = tid + i * 256;
            int brow = ch >> 4, bseg = ch & 15;
            uint32_t bd = sb + (uint32_t)B_OFF + ((uint32_t)brow * LDB + (uint32_t)bseg * 8u) * 2u;
            cp16(bd, Bh + (size_t)(k0 + brow) * N + n0 + bseg * 8);
            cp16(bd + B_BYTES, Bl + (size_t)(k0 + brow) * N + n0 + bseg * 8);
        }
        cp_commit();
    };

    issue_stage(0);
    issue_stage(1);

    float acc[4][8][4];
#pragma unroll
    for (int mt = 0; mt < 4; mt++)
#pragma unroll
        for (int nt = 0; nt < 8; nt++)
#pragma unroll
            for (int e = 0; e < 4; e++) acc[mt][nt][e] = 0.f;

    const uint32_t aCmp0 = smemU + ((uint32_t)(wm * 64 + (lane & 15)) * LDA +
                                    (uint32_t)(lane >> 4) * 8) * 2u;
    const uint32_t bCmp0 = smemU + (uint32_t)B_OFF +
                           ((uint32_t)(lane & 15) * LDB + (uint32_t)(wn * 64)) * 2u;

    for (int c = 0; c < NC; c++) {
        cp_wait<1>();
        __syncthreads();
        // safe: stage (c+2)%3 == (c-1)%3, whose readers all passed this barrier
        if (c + 2 < NC) issue_stage(c + 2);

        const uint32_t so = (uint32_t)(c % NSTG) * STAGE;
        const uint32_t aC = aCmp0 + so;
        const uint32_t bC = bCmp0 + so;
#pragma unroll
        for (int ks = 0; ks < 2; ks++) {
            uint32_t Ahf[4][4], Alf[4][4], Bhf[8][2], Blf[8][2];
#pragma unroll
            for (int mt = 0; mt < 4; mt++) {
                uint32_t ad = aC + (uint32_t)mt * (16 * LDA * 2) + (uint32_t)ks * 32;
                ldsm_x4(Ahf[mt], ad);
                ldsm_x4(Alf[mt], ad + A_BYTES);
            }
#pragma unroll
            for (int nt = 0; nt < 8; nt++) {
                uint32_t bd = bC + (uint32_t)ks * (16 * LDB * 2) + (uint32_t)nt * 16;
                ldsm_x2_t(Bhf[nt], bd);
                ldsm_x2_t(Blf[nt], bd + B_BYTES);
            }
#pragma unroll
            for (int mt = 0; mt < 4; mt++)
#pragma unroll
                for (int nt = 0; nt < 8; nt++) {
                    mma16816(acc[mt][nt], Ahf[mt], Bhf[nt][0], Bhf[nt][1]);
                    mma16816(acc[mt][nt], Ahf[mt], Blf[nt][0], Blf[nt][1]);
                    mma16816(acc[mt][nt], Alf[mt], Bhf[nt][0], Bhf[nt][1]);
                }
        }
    }

    // -------- epilogue --------
    const int rbase = m0 + wm * 64;
    const int cbase = n0 + wn * 64;
#pragma unroll
    for (int mt = 0; mt < 4; mt++)
#pragma unroll
        for (int nt = 0; nt < 8; nt++) {
#pragma unroll
            for (int half = 0; half < 2; half++) {
                int r = rbase + mt * 16 + (lane >> 2) + half * 8;
                int cc = cbase + nt * 8 + (lane & 3) * 2;
                float2 v;
                v.x = acc[mt][nt][half * 2 + 0];
                v.y = acc[mt][nt][half * 2 + 1];
                if (MODE & MD_BIAS) {
                    float2 bb = *reinterpret_cast<const float2*>(bias + cc);
                    v.x += bb.x; v.y += bb.y;
                }
                if (MODE & MD_RELU) {
                    v.x = fmaxf(v.x, 0.f); v.y = fmaxf(v.y, 0.f);
                }
                if (MODE & MD_RES) {
                    float2 rr = *reinterpret_cast<const float2*>(res + (size_t)r * N + cc);
                    v.x += rr.x; v.y += rr.y;
                }
                if (MODE & MD_SPLIT) {
                    __nv_bfloat16 hx = __float2bfloat16(v.x), hy = __float2bfloat16(v.y);
                    size_t idx = ((size_t)r * N + cc) >> 1;
                    reinterpret_cast<uint32_t*>(Chi)[idx] = pack_bf2(v.x, v.y);
                    reinterpret_cast<uint32_t*>(Clo)[idx] =
                        pack_bf2(v.x - __bfloat162float(hx), v.y - __bfloat162float(hy));
                } else if (MODE & MD_QKV) {
                    int b_ = r >> 11, s_ = r & (Ss - 1);
                    int h_ = cc >> 6, d_ = cc & 63;
                    *reinterpret_cast<float2*>(C +
                        ((size_t)(b_ * Hh + h_) * Ss + s_) * HDd + d_) = v;
                } else {
                    *reinterpret_cast<float2*>(C + (size_t)r * N + cc) = v;
                }
            }
        }
}

// ========================= mma.sync flash attention =========================
// Epilogue now writes hi/lo bf16 (consumed by Wo gemm).
constexpr int ALD = 72;
constexpr int KMAT = 64 * ALD * 2;
constexpr int ASTAGE = 4 * KMAT;
constexpr int QOFF = 2 * ASTAGE;
constexpr int QMAT = 128 * ALD * 2;
constexpr int ATT_SMEM = QOFF + 2 * QMAT;

__global__ void __launch_bounds__(256, 1) attn_mma(
    const float* __restrict__ q, const float* __restrict__ k,
    const float* __restrict__ v, __nv_bfloat16* __restrict__ oh,
    __nv_bfloat16* __restrict__ ol)
{
    extern __shared__ char sm[];
    const uint32_t S0 = smem_u32(sm);
    const int tid = threadIdx.x, lane = tid & 31, w = tid >> 5;
    const int bh = blockIdx.y, q0 = blockIdx.x * 128;
    const int b_ = bh >> 4, h_ = bh & 15;

    const float* qb = q + ((size_t)bh * Ss + q0) * HDd;
    const float* kb = k + (size_t)bh * Ss * HDd;
    const float* vb = v + (size_t)bh * Ss * HDd;

    {
        int r = tid >> 1, cb = (tid & 1) * 32;
        const float4* src = reinterpret_cast<const float4*>(qb + r * HDd + cb);
        char* qh = sm + QOFF;
        char* ql = qh + QMAT;
        uint32_t off = ((uint32_t)r * ALD + (uint32_t)cb) * 2u;
#pragma unroll
        for (int j = 0; j < 8; j += 2) {
            uint32_t hw[4], lw[4];
#pragma unroll
            for (int e = 0; e < 2; e++) {
                float4 f = src[j + e];
                float a = f.x * SCL2, b2 = f.y * SCL2, c = f.z * SCL2, d = f.w * SCL2;
                __nv_bfloat16 ha = __float2bfloat16(a), hb = __float2bfloat16(b2);
                __nv_bfloat16 hc = __float2bfloat16(c), hd = __float2bfloat16(d);
                hw[2 * e + 0] = pack_bf2(a, b2);
                hw[2 * e + 1] = pack_bf2(c, d);
                lw[2 * e + 0] = pack_bf2(a - __bfloat162float(ha), b2 - __bfloat162float(hb));
                lw[2 * e + 1] = pack_bf2(c - __bfloat162float(hc), d - __bfloat162float(hd));
            }
            *reinterpret_cast<uint4*>(qh + off + j * 8) = make_uint4(hw[0], hw[1], hw[2], hw[3]);
            *reinterpret_cast<uint4*>(ql + off + j * 8) = make_uint4(lw[0], lw[1], lw[2], lw[3]);
        }
    }
    __syncthreads();

    uint32_t Qh[4][4], Ql[4][4];
    {
        uint32_t base = S0 + QOFF +
            (((uint32_t)(w * 16 + (lane & 15))) * ALD + (uint32_t)(lane >> 4) * 8u) * 2u;
#pragma unroll
        for (int ks = 0; ks < 4; ks++) {
            ldsm_x4(Qh[ks], base + (uint32_t)ks * 32u);
            ldsm_x4(Ql[ks], base + (uint32_t)QMAT + (uint32_t)ks * 32u);
        }
    }

    float oa[8][4];
#pragma unroll
    for (int nt = 0; nt < 8; nt++)
#pragma unroll
        for (int e = 0; e < 4; e++) oa[nt][e] = 0.f;
    float mrow[2] = {-1e30f, -1e30f};
    float lrow[2] = {0.f, 0.f};

    const int krow = tid >> 2, kcb = (tid & 3) * 16;
    float4 rk[4], rv[4];
    {
        const float4* kp = reinterpret_cast<const float4*>(kb + (size_t)krow * HDd + kcb);
        const float4* vp = reinterpret_cast<const float4*>(vb + (size_t)krow * HDd + kcb);
#pragma unroll
        for (int j = 0; j < 4; j++) { rk[j] = kp[j]; rv[j] = vp[j]; }
    }

    const uint32_t stoff = ((uint32_t)krow * ALD + (uint32_t)kcb) * 2u;

    for (int t = 0; t < Ss / 64; t++) {
        const int s = t & 1;
        char* sb = sm + s * ASTAGE;
        const uint32_t sbU = S0 + (uint32_t)(s * ASTAGE);

        {
            uint32_t hw[8], lw[8];
#pragma unroll
            for (int j = 0; j < 4; j++) {
                float f0 = rk[j].x, f1 = rk[j].y, f2 = rk[j].z, f3 = rk[j].w;
                __nv_bfloat16 h0 = __float2bfloat16(f0), h1 = __float2bfloat16(f1);
                __nv_bfloat16 h2 = __float2bfloat16(f2), h3 = __float2bfloat16(f3);
                hw[2 * j] = pack_bf2(f0, f1); hw[2 * j + 1] = pack_bf2(f2, f3);
                lw[2 * j] = pack_bf2(f0 - __bfloat162float(h0), f1 - __bfloat162float(h1));
                lw[2 * j + 1] = pack_bf2(f2 - __bfloat162float(h2), f3 - __bfloat162float(h3));
            }
            *reinterpret_cast<uint4*>(sb + stoff)      = make_uint4(hw[0], hw[1], hw[2], hw[3]);
            *reinterpret_cast<uint4*>(sb + stoff + 16) = make_uint4(hw[4], hw[5], hw[6], hw[7]);
            *reinterpret_cast<uint4*>(sb + KMAT + stoff)      = make_uint4(lw[0], lw[1], lw[2], lw[3]);
            *reinterpret_cast<uint4*>(sb + KMAT + stoff + 16) = make_uint4(lw[4], lw[5], lw[6], lw[7]);
#pragma unroll
            for (int j = 0; j < 4; j++) {
                float f0 = rv[j].x, f1 = rv[j].y, f2 = rv[j].z, f3 = rv[j].w;
                __nv_bfloat16 h0 = __float2bfloat16(f0), h1 = __float2bfloat16(f1);
                __nv_bfloat16 h2 = __float2bfloat16(f2), h3 = __float2bfloat16(f3);
                hw[2 * j] = pack_bf2(f0, f1); hw[2 * j + 1] = pack_bf2(f2, f3);
                lw[2 * j] = pack_bf2(f0 - __bfloat162float(h0), f1 - __bfloat162float(h1));
                lw[2 * j + 1] = pack_bf2(f2 - __bfloat162float(h2), f3 - __bfloat162float(h3));
            }
            *reinterpret_cast<uint4*>(sb + 2 * KMAT + stoff)      = make_uint4(hw[0], hw[1], hw[2], hw[3]);
            *reinterpret_cast<uint4*>(sb + 2 * KMAT + stoff + 16) = make_uint4(hw[4], hw[5], hw[6], hw[7]);
            *reinterpret_cast<uint4*>(sb + 3 * KMAT + stoff)      = make_uint4(lw[0], lw[1], lw[2], lw[3]);
            *reinterpret_cast<uint4*>(sb + 3 * KMAT + stoff + 16) = make_uint4(lw[4], lw[5], lw[6], lw[7]);
        }
        __syncthreads();

        if (t + 1 < Ss / 64) {
            const float4* kp = reinterpret_cast<const float4*>(
                kb + (size_t)((t + 1) * 64 + krow) * HDd + kcb);
            const float4* vp = reinterpret_cast<const float4*>(
                vb + (size_t)((t + 1) * 64 + krow) * HDd + kcb);
#pragma unroll
            for (int j = 0; j < 4; j++) { rk[j] = kp[j]; rv[j] = vp[j]; }
        }

        float sc[8][4];
#pragma unroll
        for (int nt = 0; nt < 8; nt++)
#pragma unroll
            for (int e = 0; e < 4; e++) sc[nt][e] = 0.f;

        const uint32_t kfb = sbU + (uint32_t)(lane >> 4) * (uint32_t)KMAT +
            (((uint32_t)(lane & 7)) * ALD + (uint32_t)((lane >> 3) & 1) * 8u) * 2u;
#pragma unroll
        for (int nt = 0; nt < 8; nt++) {
#pragma unroll
            for (int ks = 0; ks < 4; ks++) {
                uint32_t kf[4];
                ldsm_x4(kf, kfb + ((uint32_t)nt * 8u * ALD + (uint32_t)ks * 16u) * 2u);
                mma16816(sc[nt], Qh[ks], kf[0], kf[1]);
                mma16816(sc[nt], Qh[ks], kf[2], kf[3]);
                mma16816(sc[nt], Ql[ks], kf[0], kf[1]);
            }
        }

        float mt0 = sc[0][0], mt1 = sc[0][2];
#pragma unroll
        for (int nt = 0; nt < 8; nt++) {
            mt0 = fmaxf(mt0, fmaxf(sc[nt][0], sc[nt][1]));
            mt1 = fmaxf(mt1, fmaxf(sc[nt][2], sc[nt][3]));
        }
        mt0 = fmaxf(mt0, __shfl_xor_sync(0xffffffffu, mt0, 1));
        mt0 = fmaxf(mt0, __shfl_xor_sync(0xffffffffu, mt0, 2));
        mt1 = fmaxf(mt1, __shfl_xor_sync(0xffffffffu, mt1, 1));
        mt1 = fmaxf(mt1, __shfl_xor_sync(0xffffffffu, mt1, 2));
        float mn0 = fmaxf(mrow[0], mt0), mn1 = fmaxf(mrow[1], mt1);
        float c0 = ex2(mrow[0] - mn0), c1 = ex2(mrow[1] - mn1);
        mrow[0] = mn0; mrow[1] = mn1;

        float ls0 = 0.f, ls1 = 0.f;
#pragma unroll
        for (int nt = 0; nt < 8; nt++) {
            sc[nt][0] = ex2(sc[nt][0] - mn0);
            sc[nt][1] = ex2(sc[nt][1] - mn0);
            sc[nt][2] = ex2(sc[nt][2] - mn1);
            sc[nt][3] = ex2(sc[nt][3] - mn1);
            ls0 += sc[nt][0] + sc[nt][1];
            ls1 += sc[nt][2] + sc[nt][3];
        }
        ls0 += __shfl_xor_sync(0xffffffffu, ls0, 1);
        ls0 += __shfl_xor_sync(0xffffffffu, ls0, 2);
        ls1 += __shfl_xor_sync(0xffffffffu, ls1, 1);
        ls1 += __shfl_xor_sync(0xffffffffu, ls1, 2);
        lrow[0] = lrow[0] * c0 + ls0;
        lrow[1] = lrow[1] * c1 + ls1;
#pragma unroll
        for (int nt = 0; nt < 8; nt++) {
            oa[nt][0] *= c0; oa[nt][1] *= c0;
            oa[nt][2] *= c1; oa[nt][3] *= c1;
        }

        uint32_t Ph[4][4], Pl[4][4];
#pragma unroll
        for (int kk = 0; kk < 4; kk++) {
#pragma unroll
            for (int half = 0; half < 2; half++) {
                float p0 = sc[2 * kk + half][0], p1 = sc[2 * kk + half][1];
                float p2 = sc[2 * kk + half][2], p3 = sc[2 * kk + half][3];
                __nv_bfloat16 h0 = __float2bfloat16(p0), h1 = __float2bfloat16(p1);
                __nv_bfloat16 h2 = __float2bfloat16(p2), h3 = __float2bfloat16(p3);
                Ph[kk][2 * half + 0] = pack_bf2(p0, p1);
                Ph[kk][2 * half + 1] = pack_bf2(p2, p3);
                Pl[kk][2 * half + 0] = pack_bf2(p0 - __bfloat162float(h0),
                                                p1 - __bfloat162float(h1));
                Pl[kk][2 * half + 1] = pack_bf2(p2 - __bfloat162float(h2),
                                                p3 - __bfloat162float(h3));
            }
        }

        const uint32_t vfb = sbU + 2u * (uint32_t)KMAT +
            (uint32_t)(lane >> 4) * (uint32_t)KMAT +
            ((uint32_t)(lane & 15)) * (uint32_t)ALD * 2u;
#pragma unroll
        for (int kk = 0; kk < 4; kk++) {
#pragma unroll
            for (int nt = 0; nt < 8; nt++) {
                uint32_t vf[4];
                ldsm_x4_t(vf, vfb + ((uint32_t)kk * 16u * ALD + (uint32_t)nt * 8u) * 2u);
                mma16816(oa[nt], Ph[kk], vf[0], vf[1]);
                mma16816(oa[nt], Ph[kk], vf[2], vf[3]);
                mma16816(oa[nt], Pl[kk], vf[0], vf[1]);
            }
        }
        __syncthreads();
    }

    // ---- epilogue: normalize, split to hi/lo bf16, write [B,S,D] ----
    float il0 = 1.0f / lrow[0], il1 = 1.0f / lrow[1];
    int sr0 = q0 + w * 16 + (lane >> 2);
    int sr1 = sr0 + 8;
#pragma unroll
    for (int nt = 0; nt < 8; nt++) {
        int col = h_ * HDd + nt * 8 + (lane & 3) * 2;
        float a0 = oa[nt][0] * il0, a1 = oa[nt][1] * il0;
        float a2 = oa[nt][2] * il1, a3 = oa[nt][3] * il1;
        __nv_bfloat16 h0 = __float2bfloat16(a0), h1 = __float2bfloat16(a1);
        __nv_bfloat16 h2 = __float2bfloat16(a2), h3 = __float2bfloat16(a3);
        size_t i0 = (((size_t)(b_ * Ss + sr0)) * Dd + col) >> 1;
        size_t i1 = (((size_t)(b_ * Ss + sr1)) * Dd + col) >> 1;
        reinterpret_cast<uint32_t*>(oh)[i0] = pack_bf2(a0, a1);
        reinterpret_cast<uint32_t*>(ol)[i0] =
            pack_bf2(a0 - __bfloat162float(h0), a1 - __bfloat162float(h1));
        reinterpret_cast<uint32_t*>(oh)[i1] = pack_bf2(a2, a3);
        reinterpret_cast<uint32_t*>(ol)[i1] =
            pack_bf2(a2 - __bfloat162float(h2), a3 - __bfloat162float(h3));
    }
}

// ========================= launch ===========================
extern "C" void kernel_launch(void* const* d_in, const int* in_sizes, int n_in,
                              void* d_out, int out_size)
{
    const float* x     = (const float*)d_in[0];
    const float* ln1_g = (const float*)d_in[1];
    const float* ln1_b = (const float*)d_in[2];
    const float* ln2_g = (const float*)d_in[3];
    const float* ln2_b = (const float*)d_in[4];
    const float* Wq    = (const float*)d_in[5];
    const float* Wk    = (const float*)d_in[6];
    const float* Wv    = (const float*)d_in[7];
    const float* Wo    = (const float*)d_in[8];
    const float* W1    = (const float*)d_in[9];
    const float* b1    = (const float*)d_in[10];
    const float* W2    = (const float*)d_in[11];
    const float* b2    = (const float*)d_in[12];
    float* out = (float*)d_out;

    float *q, *k, *v, *x2;
    __nv_bfloat16 *xh, *xl, *oh, *ol, *fh, *fl, *wh, *wl;
    cudaGetSymbolAddress((void**)&q,   g_q);
    cudaGetSymbolAddress((void**)&k,   g_k);
    cudaGetSymbolAddress((void**)&v,   g_v);
    cudaGetSymbolAddress((void**)&x2,  g_x2);
    cudaGetSymbolAddress((void**)&xh,  g_xh);
    cudaGetSymbolAddress((void**)&xl,  g_xl);
    cudaGetSymbolAddress((void**)&oh,  g_oh);
    cudaGetSymbolAddress((void**)&ol,  g_ol);
    cudaGetSymbolAddress((void**)&fh,  g_fh);
    cudaGetSymbolAddress((void**)&fl,  g_fl);
    cudaGetSymbolAddress((void**)&wh,  g_wh);
    cudaGetSymbolAddress((void**)&wl,  g_wl);

    cudaFuncSetAttribute(gemm_mma<MD_QKV>, cudaFuncAttributeMaxDynamicSharedMemorySize, GEMM_SMEM);
    cudaFuncSetAttribute(gemm_mma<MD_RES>, cudaFuncAttributeMaxDynamicSharedMemorySize, GEMM_SMEM);
    cudaFuncSetAttribute(gemm_mma<MD_BIAS | MD_RELU | MD_SPLIT>, cudaFuncAttributeMaxDynamicSharedMemorySize, GEMM_SMEM);
    cudaFuncSetAttribute(gemm_mma<MD_BIAS | MD_RELU | MD_RES>, cudaFuncAttributeMaxDynamicSharedMemorySize, GEMM_SMEM);
    cudaFuncSetAttribute(attn_mma, cudaFuncAttributeMaxDynamicSharedMemorySize, ATT_SMEM);

    dim3 blk(256);
    dim3 gD(Dd / 128, Mm / 256);     // (8, 32)
    dim3 gF(FFf / 128, Mm / 256);    // (32, 32)
    const int QD4 = Dd * Dd / 4, FD4 = Dd * FFf / 4;

    // weight splits
    split_kernel<<<QD4 / 256, blk>>>(Wq, wh + WQO, wl + WQO, QD4);
    split_kernel<<<QD4 / 256, blk>>>(Wk, wh + WKO, wl + WKO, QD4);
    split_kernel<<<QD4 / 256, blk>>>(Wv, wh + WVO, wl + WVO, QD4);
    split_kernel<<<QD4 / 256, blk>>>(Wo, wh + WOO, wl + WOO, QD4);
    split_kernel<<<FD4 / 256, blk>>>(W1, wh + W1O, wl + W1O, FD4);
    split_kernel<<<FD4 / 256, blk>>>(W2, wh + W2O, wl + W2O, FD4);

    // h = LN1(x) -> hi/lo
    ln_split_kernel<<<Mm, blk>>>(x, ln1_g, ln1_b, xh, xl);
    // q,k,v = h @ W{q,k,v}  ([B,H,S,HD] layout, fp32)
    gemm_mma<MD_QKV><<<gD, blk, GEMM_SMEM>>>(xh, xl, wh + WQO, wl + WQO, nullptr, nullptr, q, nullptr, nullptr, Dd, Dd);
    gemm_mma<MD_QKV><<<gD, blk, GEMM_SMEM>>>(xh, xl, wh + WKO, wl + WKO, nullptr, nullptr, k, nullptr, nullptr, Dd, Dd);
    gemm_mma<MD_QKV><<<gD, blk, GEMM_SMEM>>>(xh, xl, wh + WVO, wl + WVO, nullptr, nullptr, v, nullptr, nullptr, Dd, Dd);
    // attention -> hi/lo o
    attn_mma<<<dim3(Ss / 128, Bb * Hh), blk, ATT_SMEM>>>(q, k, v, oh, ol);
    // x2 = x + o @ Wo
    gemm_mma<MD_RES><<<gD, blk, GEMM_SMEM>>>(oh, ol, wh + WOO, wl + WOO, nullptr, x, x2, nullptr, nullptr, Dd, Dd);
    // h = LN2(x2) -> hi/lo
    ln_split_kernel<<<Mm, blk>>>(x2, ln2_g, ln2_b, xh, xl);
    // ff1 = relu(h @ W1 + b1) -> hi/lo
    gemm_mma<MD_BIAS | MD_RELU | MD_SPLIT><<<gF, blk, GEMM_SMEM>>>(xh, xl, wh + W1O, wl + W1O, b1, nullptr, nullptr, fh, fl, FFf, Dd);
    // out = x2 + relu(ff1 @ W2 + b2)
    gemm_mma<MD_BIAS | MD_RELU | MD_RES><<<gD, blk, GEMM_SMEM>>>(fh, fl, wh + W2O, wl + W2O, b2, x2, out, nullptr, nullptr, Dd, FFf);
}

// round 10
// speedup vs baseline: 2.7989x; 1.0633x over previous
#include <cuda_runtime.h>
#include <cuda_bf16.h>
#include <cstdint>

// ---------------------------------------------------------------------------
// TransformerLayer: B=4, S=2048, D=1024, H=16, HD=64, FF=4096, fp32 I/O.
// Round 9: GEMM k-chunk 64, NSTG=2, ONE barrier per chunk, ldsm.x4.trans for
// B (2 n-tiles/instr). 256x128 CTA tile, warps 4(m)x2(n) of 64x64.
// Splits fused into producers as in R8. Attention unchanged (R6).
// ---------------------------------------------------------------------------

constexpr int Bb = 4, Ss = 2048, Dd = 1024, Hh = 16, HDd = 64, FFf = 4096;
constexpr int Mm = Bb * Ss;            // 8192 rows
constexpr float EPS = 1e-5f;
constexpr float SCL2 = 0.125f * 1.4426950408889634f;

// fp32 scratch
__device__ float g_q  [Mm * Dd];
__device__ float g_k  [Mm * Dd];
__device__ float g_v  [Mm * Dd];
__device__ float g_x2 [Mm * Dd];
// bf16 hi/lo activation scratch
__device__ __nv_bfloat16 g_xh[(size_t)Mm * Dd];
__device__ __nv_bfloat16 g_xl[(size_t)Mm * Dd];
__device__ __nv_bfloat16 g_oh[(size_t)Mm * Dd];
__device__ __nv_bfloat16 g_ol[(size_t)Mm * Dd];
__device__ __nv_bfloat16 g_fh[(size_t)Mm * FFf];
__device__ __nv_bfloat16 g_fl[(size_t)Mm * FFf];
// bf16 hi/lo weights, [K,N] layout
constexpr size_t WQO = 0, WKO = 1u << 20, WVO = 2u << 20, WOO = 3u << 20;
constexpr size_t W1O = 4u << 20, W2O = 8u << 20, WTOT = 12u << 20;
__device__ __nv_bfloat16 g_wh[WTOT];
__device__ __nv_bfloat16 g_wl[WTOT];

// ========================= small PTX helpers ===========================
__device__ __forceinline__ uint32_t smem_u32(const void* p) {
    uint32_t a;
    asm("{ .reg .u64 t; cvta.to.shared.u64 t, %1; cvt.u32.u64 %0, t; }" : "=r"(a) : "l"(p));
    return a;
}
__device__ __forceinline__ void ldsm_x4(uint32_t (&r)[4], uint32_t addr) {
    asm volatile("ldmatrix.sync.aligned.m8n8.x4.shared.b16 {%0,%1,%2,%3}, [%4];"
        : "=r"(r[0]), "=r"(r[1]), "=r"(r[2]), "=r"(r[3]) : "r"(addr));
}
__device__ __forceinline__ void ldsm_x4_t(uint32_t (&r)[4], uint32_t addr) {
    asm volatile("ldmatrix.sync.aligned.m8n8.x4.trans.shared.b16 {%0,%1,%2,%3}, [%4];"
        : "=r"(r[0]), "=r"(r[1]), "=r"(r[2]), "=r"(r[3]) : "r"(addr));
}
__device__ __forceinline__ void mma16816(float (&c)[4], const uint32_t (&a)[4],
                                         uint32_t b0, uint32_t b1) {
    asm volatile("mma.sync.aligned.m16n8k16.row.col.f32.bf16.bf16.f32 "
        "{%0,%1,%2,%3}, {%4,%5,%6,%7}, {%8,%9}, {%0,%1,%2,%3};"
        : "+f"(c[0]), "+f"(c[1]), "+f"(c[2]), "+f"(c[3])
        : "r"(a[0]), "r"(a[1]), "r"(a[2]), "r"(a[3]), "r"(b0), "r"(b1));
}
__device__ __forceinline__ uint32_t pack_bf2(float a, float b) {
    __nv_bfloat162 h = __floats2bfloat162_rn(a, b);
    return *reinterpret_cast<uint32_t*>(&h);
}
__device__ __forceinline__ float ex2(float x) {
    float y;
    asm("ex2.approx.ftz.f32 %0, %1;" : "=f"(y) : "f"(x));
    return y;
}
__device__ __forceinline__ void cp16(uint32_t dst, const void* src) {
    asm volatile("cp.async.cg.shared.global [%0], [%1], 16;" :: "r"(dst), "l"(src) : "memory");
}
__device__ __forceinline__ void cp_commit() { asm volatile("cp.async.commit_group;" ::: "memory"); }
template <int N>
__device__ __forceinline__ void cp_wait() {
    asm volatile("cp.async.wait_group %0;" :: "n"(N) : "memory");
}

// ========================= LayerNorm (writes hi/lo bf16) ====================
__global__ void __launch_bounds__(256) ln_split_kernel(
    const float* __restrict__ x, const float* __restrict__ g,
    const float* __restrict__ b, __nv_bfloat16* __restrict__ oh,
    __nv_bfloat16* __restrict__ ol)
{
    int row = blockIdx.x;
    int t = threadIdx.x;
    const float4 v = reinterpret_cast<const float4*>(x + (size_t)row * Dd)[t];
    float s  = v.x + v.y + v.z + v.w;
    float ss = v.x * v.x + v.y * v.y + v.z * v.z + v.w * v.w;
#pragma unroll
    for (int o = 16; o > 0; o >>= 1) {
        s  += __shfl_xor_sync(0xffffffffu, s,  o);
        ss += __shfl_xor_sync(0xffffffffu, ss, o);
    }
    __shared__ float red[16];
    int w = t >> 5;
    if ((t & 31) == 0) { red[w] = s; red[8 + w] = ss; }
    __syncthreads();
    float st = 0.f, sst = 0.f;
#pragma unroll
    for (int i = 0; i < 8; i++) { st += red[i]; sst += red[8 + i]; }
    float mu  = st  * (1.0f / Dd);
    float var = sst * (1.0f / Dd) - mu * mu;
    float inv = rsqrtf(var + EPS);
    float4 gg = reinterpret_cast<const float4*>(g)[t];
    float4 bb = reinterpret_cast<const float4*>(b)[t];
    float f[4];
    f[0] = (v.x - mu) * inv * gg.x + bb.x;
    f[1] = (v.y - mu) * inv * gg.y + bb.y;
    f[2] = (v.z - mu) * inv * gg.z + bb.z;
    f[3] = (v.w - mu) * inv * gg.w + bb.w;
    uint32_t hw[2], lw[2];
#pragma unroll
    for (int e = 0; e < 2; e++) {
        float a = f[2 * e], c = f[2 * e + 1];
        __nv_bfloat16 ha = __float2bfloat16(a), hc = __float2bfloat16(c);
        hw[e] = pack_bf2(a, c);
        lw[e] = pack_bf2(a - __bfloat162float(ha), c - __bfloat162float(hc));
    }
    size_t idx = (size_t)row * (Dd / 4) + t;
    reinterpret_cast<uint2*>(oh)[idx] = make_uint2(hw[0], hw[1]);
    reinterpret_cast<uint2*>(ol)[idx] = make_uint2(lw[0], lw[1]);
}

// ========================= split fp32 -> bf16 hi/lo (weights) ===============
__global__ void __launch_bounds__(256) split_kernel(
    const float* __restrict__ x, __nv_bfloat16* __restrict__ hi,
    __nv_bfloat16* __restrict__ lo, int n4)
{
    int i = blockIdx.x * 256 + threadIdx.x;
    if (i >= n4) return;
    float4 v = reinterpret_cast<const float4*>(x)[i];
    float f[4] = {v.x, v.y, v.z, v.w};
    uint32_t h[2], l[2];
#pragma unroll
    for (int e = 0; e < 2; e++) {
        float a = f[2 * e], b = f[2 * e + 1];
        __nv_bfloat16 ha = __float2bfloat16(a), hb = __float2bfloat16(b);
        h[e] = pack_bf2(a, b);
        l[e] = pack_bf2(a - __bfloat162float(ha), b - __bfloat162float(hb));
    }
    reinterpret_cast<uint2*>(hi)[i] = make_uint2(h[0], h[1]);
    reinterpret_cast<uint2*>(lo)[i] = make_uint2(l[0], l[1]);
}

// ========================= cp.async split-bf16 GEMM =========================
// C[M,N] = A[M,K] @ W[K,N]; both pre-split bf16 hi/lo. D = AhBh + AhBl + AlBh.
// CTA tile 256x128x64; 8 warps as 4(m) x 2(n), warp tile 64x64. NSTG=2,
// single barrier per chunk (top barrier proves compute(c-1) done everywhere).
constexpr int MD_BIAS = 1, MD_RELU = 2, MD_RES = 4, MD_QKV = 8, MD_SPLIT = 16;

constexpr int LDA = 72;                         // bf16 elems per A smem row (64+8)
constexpr int LDB = 136;                        // bf16 elems per B smem row (128+8)
constexpr int A_BYTES = 256 * LDA * 2;          // 36864 per matrix
constexpr int B_BYTES = 64 * LDB * 2;           // 17408 per matrix
constexpr int B_OFF   = 2 * A_BYTES;            // 73728
constexpr int STAGE   = B_OFF + 2 * B_BYTES;    // 108544
constexpr int GEMM_SMEM = 2 * STAGE;            // 217088

template <int MODE>
__global__ void __launch_bounds__(256, 1) gemm_mma(
    const __nv_bfloat16* __restrict__ Ah, const __nv_bfloat16* __restrict__ Al,
    const __nv_bfloat16* __restrict__ Bh, const __nv_bfloat16* __restrict__ Bl,
    const float* __restrict__ bias, const float* __restrict__ res,
    float* __restrict__ C, __nv_bfloat16* __restrict__ Chi,
    __nv_bfloat16* __restrict__ Clo, int N, int K)
{
    extern __shared__ char dsm[];
    const uint32_t smemU = smem_u32(dsm);

    const int tid  = threadIdx.x;
    const int lane = tid & 31;
    const int wid  = tid >> 5;
    const int wm   = wid >> 1;          // 0..3 (64-row slab)
    const int wn   = wid & 1;           // 0..1 (64-col slab)
    const int m0   = blockIdx.y * 256;
    const int n0   = blockIdx.x * 128;
    const int NC   = K >> 6;

    auto issue_stage = [&](int c) {
        const uint32_t sb = smemU + (uint32_t)(c & 1) * STAGE;
        const int k0 = c << 6;
        // A: 256 rows x 8 segs of 16B per matrix; 8 chunks/thread
#pragma unroll
        for (int i = 0; i < 8; i++) {
            int ch = tid + i * 256;
            int arow = ch >> 3, aseg = ch & 7;
            uint32_t ad = sb + ((uint32_t)arow * LDA + (uint32_t)aseg * 8u) * 2u;
            cp16(ad, Ah + (size_t)(m0 + arow) * K + k0 + aseg * 8);
            cp16(ad + A_BYTES, Al + (size_t)(m0 + arow) * K + k0 + aseg * 8);
        }
        // B: 64 rows x 16 segs per matrix; 4 chunks/thread
#pragma unroll
        for (int i = 0; i < 4; i++) {
            int ch = tid + i * 256;
            int brow = ch >> 4, bseg = ch & 15;
            uint32_t bd = sb + (uint32_t)B_OFF + ((uint32_t)brow * LDB + (uint32_t)bseg * 8u) * 2u;
            cp16(bd, Bh + (size_t)(k0 + brow) * N + n0 + bseg * 8);
            cp16(bd + B_BYTES, Bl + (size_t)(k0 + brow) * N + n0 + bseg * 8);
        }
        cp_commit();
    };

    issue_stage(0);

    float acc[4][8][4];
#pragma unroll
    for (int mt = 0; mt < 4; mt++)
#pragma unroll
        for (int nt = 0; nt < 8; nt++)
#pragma unroll
            for (int e = 0; e < 4; e++) acc[mt][nt][e] = 0.f;

    const uint32_t aCmp0 = smemU + ((uint32_t)(wm * 64 + (lane & 15)) * LDA +
                                    (uint32_t)(lane >> 4) * 8) * 2u;
    // B: lanes 0-15 -> 16 k-rows at n-col base; lanes 16-31 -> same rows +16B
    // (next 8 n-cols). One ldsm.x4.trans = B-frags for TWO n-tiles.
    const uint32_t bCmp0 = smemU + (uint32_t)B_OFF +
                           ((uint32_t)(lane & 15) * LDB + (uint32_t)(wn * 64)) * 2u +
                           (uint32_t)(lane >> 4) * 16u;

    for (int c = 0; c < NC; c++) {
        cp_wait<0>();
        __syncthreads();
        // buffer (c+1)&1 was last read in compute(c-1); the barrier above
        // proves every warp finished that — safe to overwrite now.
        if (c + 1 < NC) issue_stage(c + 1);

        const uint32_t so = (uint32_t)(c & 1) * STAGE;
        const uint32_t aC = aCmp0 + so;
        const uint32_t bC = bCmp0 + so;
#pragma unroll
        for (int ks = 0; ks < 4; ks++) {
            uint32_t Bhf[8][2], Blf[8][2];
#pragma unroll
            for (int np = 0; np < 4; np++) {
                uint32_t bd = bC + (uint32_t)ks * (16 * LDB * 2) + (uint32_t)np * 32u;
                uint32_t t4[4];
                ldsm_x4_t(t4, bd);
                Bhf[2 * np][0] = t4[0]; Bhf[2 * np][1] = t4[1];
                Bhf[2 * np + 1][0] = t4[2]; Bhf[2 * np + 1][1] = t4[3];
                ldsm_x4_t(t4, bd + B_BYTES);
                Blf[2 * np][0] = t4[0]; Blf[2 * np][1] = t4[1];
                Blf[2 * np + 1][0] = t4[2]; Blf[2 * np + 1][1] = t4[3];
            }
#pragma unroll
            for (int mt = 0; mt < 4; mt++) {
                uint32_t Ahf[4], Alf[4];
                uint32_t ad = aC + (uint32_t)mt * (16 * LDA * 2) + (uint32_t)ks * 32u;
                ldsm_x4(Ahf, ad);
                ldsm_x4(Alf, ad + A_BYTES);
#pragma unroll
                for (int nt = 0; nt < 8; nt++) {
                    mma16816(acc[mt][nt], Ahf, Bhf[nt][0], Bhf[nt][1]);
                    mma16816(acc[mt][nt], Ahf, Blf[nt][0], Blf[nt][1]);
                    mma16816(acc[mt][nt], Alf, Bhf[nt][0], Bhf[nt][1]);
                }
            }
        }
    }

    // -------- epilogue --------
    const int rbase = m0 + wm * 64;
    const int cbase = n0 + wn * 64;
#pragma unroll
    for (int mt = 0; mt < 4; mt++)
#pragma unroll
        for (int nt = 0; nt < 8; nt++) {
#pragma unroll
            for (int half = 0; half < 2; half++) {
                int r = rbase + mt * 16 + (lane >> 2) + half * 8;
                int cc = cbase + nt * 8 + (lane & 3) * 2;
                float2 v;
                v.x = acc[mt][nt][half * 2 + 0];
                v.y = acc[mt][nt][half * 2 + 1];
                if (MODE & MD_BIAS) {
                    float2 bb = *reinterpret_cast<const float2*>(bias + cc);
                    v.x += bb.x; v.y += bb.y;
                }
                if (MODE & MD_RELU) {
                    v.x = fmaxf(v.x, 0.f); v.y = fmaxf(v.y, 0.f);
                }
                if (MODE & MD_RES) {
                    float2 rr = *reinterpret_cast<const float2*>(res + (size_t)r * N + cc);
                    v.x += rr.x; v.y += rr.y;
                }
                if (MODE & MD_SPLIT) {
                    __nv_bfloat16 hx = __float2bfloat16(v.x), hy = __float2bfloat16(v.y);
                    size_t idx = ((size_t)r * N + cc) >> 1;
                    reinterpret_cast<uint32_t*>(Chi)[idx] = pack_bf2(v.x, v.y);
                    reinterpret_cast<uint32_t*>(Clo)[idx] =
                        pack_bf2(v.x - __bfloat162float(hx), v.y - __bfloat162float(hy));
                } else if (MODE & MD_QKV) {
                    int b_ = r >> 11, s_ = r & (Ss - 1);
                    int h_ = cc >> 6, d_ = cc & 63;
                    *reinterpret_cast<float2*>(C +
                        ((size_t)(b_ * Hh + h_) * Ss + s_) * HDd + d_) = v;
                } else {
                    *reinterpret_cast<float2*>(C + (size_t)r * N + cc) = v;
                }
            }
        }
}

// ========================= mma.sync flash attention (R6/R8) =================
constexpr int ALD = 72;
constexpr int KMAT = 64 * ALD * 2;
constexpr int ASTAGE = 4 * KMAT;
constexpr int QOFF = 2 * ASTAGE;
constexpr int QMAT = 128 * ALD * 2;
constexpr int ATT_SMEM = QOFF + 2 * QMAT;

__global__ void __launch_bounds__(256, 1) attn_mma(
    const float* __restrict__ q, const float* __restrict__ k,
    const float* __restrict__ v, __nv_bfloat16* __restrict__ oh,
    __nv_bfloat16* __restrict__ ol)
{
    extern __shared__ char sm[];
    const uint32_t S0 = smem_u32(sm);
    const int tid = threadIdx.x, lane = tid & 31, w = tid >> 5;
    const int bh = blockIdx.y, q0 = blockIdx.x * 128;
    const int b_ = bh >> 4, h_ = bh & 15;

    const float* qb = q + ((size_t)bh * Ss + q0) * HDd;
    const float* kb = k + (size_t)bh * Ss * HDd;
    const float* vb = v + (size_t)bh * Ss * HDd;

    {
        int r = tid >> 1, cb = (tid & 1) * 32;
        const float4* src = reinterpret_cast<const float4*>(qb + r * HDd + cb);
        char* qh = sm + QOFF;
        char* ql = qh + QMAT;
        uint32_t off = ((uint32_t)r * ALD + (uint32_t)cb) * 2u;
#pragma unroll
        for (int j = 0; j < 8; j += 2) {
            uint32_t hw[4], lw[4];
#pragma unroll
            for (int e = 0; e < 2; e++) {
                float4 f = src[j + e];
                float a = f.x * SCL2, b2 = f.y * SCL2, c = f.z * SCL2, d = f.w * SCL2;
                __nv_bfloat16 ha = __float2bfloat16(a), hb = __float2bfloat16(b2);
                __nv_bfloat16 hc = __float2bfloat16(c), hd = __float2bfloat16(d);
                hw[2 * e + 0] = pack_bf2(a, b2);
                hw[2 * e + 1] = pack_bf2(c, d);
                lw[2 * e + 0] = pack_bf2(a - __bfloat162float(ha), b2 - __bfloat162float(hb));
                lw[2 * e + 1] = pack_bf2(c - __bfloat162float(hc), d - __bfloat162float(hd));
            }
            *reinterpret_cast<uint4*>(qh + off + j * 8) = make_uint4(hw[0], hw[1], hw[2], hw[3]);
            *reinterpret_cast<uint4*>(ql + off + j * 8) = make_uint4(lw[0], lw[1], lw[2], lw[3]);
        }
    }
    __syncthreads();

    uint32_t Qh[4][4], Ql[4][4];
    {
        uint32_t base = S0 + QOFF +
            (((uint32_t)(w * 16 + (lane & 15))) * ALD + (uint32_t)(lane >> 4) * 8u) * 2u;
#pragma unroll
        for (int ks = 0; ks < 4; ks++) {
            ldsm_x4(Qh[ks], base + (uint32_t)ks * 32u);
            ldsm_x4(Ql[ks], base + (uint32_t)QMAT + (uint32_t)ks * 32u);
        }
    }

    float oa[8][4];
#pragma unroll
    for (int nt = 0; nt < 8; nt++)
#pragma unroll
        for (int e = 0; e < 4; e++) oa[nt][e] = 0.f;
    float mrow[2] = {-1e30f, -1e30f};
    float lrow[2] = {0.f, 0.f};

    const int krow = tid >> 2, kcb = (tid & 3) * 16;
    float4 rk[4], rv[4];
    {
        const float4* kp = reinterpret_cast<const float4*>(kb + (size_t)krow * HDd + kcb);
        const float4* vp = reinterpret_cast<const float4*>(vb + (size_t)krow * HDd + kcb);
#pragma unroll
        for (int j = 0; j < 4; j++) { rk[j] = kp[j]; rv[j] = vp[j]; }
    }

    const uint32_t stoff = ((uint32_t)krow * ALD + (uint32_t)kcb) * 2u;

    for (int t = 0; t < Ss / 64; t++) {
        const int s = t & 1;
        char* sb = sm + s * ASTAGE;
        const uint32_t sbU = S0 + (uint32_t)(s * ASTAGE);

        {
            uint32_t hw[8], lw[8];
#pragma unroll
            for (int j = 0; j < 4; j++) {
                float f0 = rk[j].x, f1 = rk[j].y, f2 = rk[j].z, f3 = rk[j].w;
                __nv_bfloat16 h0 = __float2bfloat16(f0), h1 = __float2bfloat16(f1);
                __nv_bfloat16 h2 = __float2bfloat16(f2), h3 = __float2bfloat16(f3);
                hw[2 * j] = pack_bf2(f0, f1); hw[2 * j + 1] = pack_bf2(f2, f3);
                lw[2 * j] = pack_bf2(f0 - __bfloat162float(h0), f1 - __bfloat162float(h1));
                lw[2 * j + 1] = pack_bf2(f2 - __bfloat162float(h2), f3 - __bfloat162float(h3));
            }
            *reinterpret_cast<uint4*>(sb + stoff)      = make_uint4(hw[0], hw[1], hw[2], hw[3]);
            *reinterpret_cast<uint4*>(sb + stoff + 16) = make_uint4(hw[4], hw[5], hw[6], hw[7]);
            *reinterpret_cast<uint4*>(sb + KMAT + stoff)      = make_uint4(lw[0], lw[1], lw[2], lw[3]);
            *reinterpret_cast<uint4*>(sb + KMAT + stoff + 16) = make_uint4(lw[4], lw[5], lw[6], lw[7]);
#pragma unroll
            for (int j = 0; j < 4; j++) {
                float f0 = rv[j].x, f1 = rv[j].y, f2 = rv[j].z, f3 = rv[j].w;
                __nv_bfloat16 h0 = __float2bfloat16(f0), h1 = __float2bfloat16(f1);
                __nv_bfloat16 h2 = __float2bfloat16(f2), h3 = __float2bfloat16(f3);
                hw[2 * j] = pack_bf2(f0, f1); hw[2 * j + 1] = pack_bf2(f2, f3);
                lw[2 * j] = pack_bf2(f0 - __bfloat162float(h0), f1 - __bfloat162float(h1));
                lw[2 * j + 1] = pack_bf2(f2 - __bfloat162float(h2), f3 - __bfloat162float(h3));
            }
            *reinterpret_cast<uint4*>(sb + 2 * KMAT + stoff)      = make_uint4(hw[0], hw[1], hw[2], hw[3]);
            *reinterpret_cast<uint4*>(sb + 2 * KMAT + stoff + 16) = make_uint4(hw[4], hw[5], hw[6], hw[7]);
            *reinterpret_cast<uint4*>(sb + 3 * KMAT + stoff)      = make_uint4(lw[0], lw[1], lw[2], lw[3]);
            *reinterpret_cast<uint4*>(sb + 3 * KMAT + stoff + 16) = make_uint4(lw[4], lw[5], lw[6], lw[7]);
        }
        __syncthreads();

        if (t + 1 < Ss / 64) {
            const float4* kp = reinterpret_cast<const float4*>(
                kb + (size_t)((t + 1) * 64 + krow) * HDd + kcb);
            const float4* vp = reinterpret_cast<const float4*>(
                vb + (size_t)((t + 1) * 64 + krow) * HDd + kcb);
#pragma unroll
            for (int j = 0; j < 4; j++) { rk[j] = kp[j]; rv[j] = vp[j]; }
        }

        float sc[8][4];
#pragma unroll
        for (int nt = 0; nt < 8; nt++)
#pragma unroll
            for (int e = 0; e < 4; e++) sc[nt][e] = 0.f;

        const uint32_t kfb = sbU + (uint32_t)(lane >> 4) * (uint32_t)KMAT +
            (((uint32_t)(lane & 7)) * ALD + (uint32_t)((lane >> 3) & 1) * 8u) * 2u;
#pragma unroll
        for (int nt = 0; nt < 8; nt++) {
#pragma unroll
            for (int ks = 0; ks < 4; ks++) {
                uint32_t kf[4];
                ldsm_x4(kf, kfb + ((uint32_t)nt * 8u * ALD + (uint32_t)ks * 16u) * 2u);
                mma16816(sc[nt], Qh[ks], kf[0], kf[1]);
                mma16816(sc[nt], Qh[ks], kf[2], kf[3]);
                mma16816(sc[nt], Ql[ks], kf[0], kf[1]);
            }
        }

        float mt0 = sc[0][0], mt1 = sc[0][2];
#pragma unroll
        for (int nt = 0; nt < 8; nt++) {
            mt0 = fmaxf(mt0, fmaxf(sc[nt][0], sc[nt][1]));
            mt1 = fmaxf(mt1, fmaxf(sc[nt][2], sc[nt][3]));
        }
        mt0 = fmaxf(mt0, __shfl_xor_sync(0xffffffffu, mt0, 1));
        mt0 = fmaxf(mt0, __shfl_xor_sync(0xffffffffu, mt0, 2));
        mt1 = fmaxf(mt1, __shfl_xor_sync(0xffffffffu, mt1, 1));
        mt1 = fmaxf(mt1, __shfl_xor_sync(0xffffffffu, mt1, 2));
        float mn0 = fmaxf(mrow[0], mt0), mn1 = fmaxf(mrow[1], mt1);
        float c0 = ex2(mrow[0] - mn0), c1 = ex2(mrow[1] - mn1);
        mrow[0] = mn0; mrow[1] = mn1;

        float ls0 = 0.f, ls1 = 0.f;
#pragma unroll
        for (int nt = 0; nt < 8; nt++) {
            sc[nt][0] = ex2(sc[nt][0] - mn0);
            sc[nt][1] = ex2(sc[nt][1] - mn0);
            sc[nt][2] = ex2(sc[nt][2] - mn1);
            sc[nt][3] = ex2(sc[nt][3] - mn1);
            ls0 += sc[nt][0] + sc[nt][1];
            ls1 += sc[nt][2] + sc[nt][3];
        }
        ls0 += __shfl_xor_sync(0xffffffffu, ls0, 1);
        ls0 += __shfl_xor_sync(0xffffffffu, ls0, 2);
        ls1 += __shfl_xor_sync(0xffffffffu, ls1, 1);
        ls1 += __shfl_xor_sync(0xffffffffu, ls1, 2);
        lrow[0] = lrow[0] * c0 + ls0;
        lrow[1] = lrow[1] * c1 + ls1;
#pragma unroll
        for (int nt = 0; nt < 8; nt++) {
            oa[nt][0] *= c0; oa[nt][1] *= c0;
            oa[nt][2] *= c1; oa[nt][3] *= c1;
        }

        uint32_t Ph[4][4], Pl[4][4];
#pragma unroll
        for (int kk = 0; kk < 4; kk++) {
#pragma unroll
            for (int half = 0; half < 2; half++) {
                float p0 = sc[2 * kk + half][0], p1 = sc[2 * kk + half][1];
                float p2 = sc[2 * kk + half][2], p3 = sc[2 * kk + half][3];
                __nv_bfloat16 h0 = __float2bfloat16(p0), h1 = __float2bfloat16(p1);
                __nv_bfloat16 h2 = __float2bfloat16(p2), h3 = __float2bfloat16(p3);
                Ph[kk][2 * half + 0] = pack_bf2(p0, p1);
                Ph[kk][2 * half + 1] = pack_bf2(p2, p3);
                Pl[kk][2 * half + 0] = pack_bf2(p0 - __bfloat162float(h0),
                                                p1 - __bfloat162float(h1));
                Pl[kk][2 * half + 1] = pack_bf2(p2 - __bfloat162float(h2),
                                                p3 - __bfloat162float(h3));
            }
        }

        const uint32_t vfb = sbU + 2u * (uint32_t)KMAT +
            (uint32_t)(lane >> 4) * (uint32_t)KMAT +
            ((uint32_t)(lane & 15)) * (uint32_t)ALD * 2u;
#pragma unroll
        for (int kk = 0; kk < 4; kk++) {
#pragma unroll
            for (int nt = 0; nt < 8; nt++) {
                uint32_t vf[4];
                ldsm_x4_t(vf, vfb + ((uint32_t)kk * 16u * ALD + (uint32_t)nt * 8u) * 2u);
                mma16816(oa[nt], Ph[kk], vf[0], vf[1]);
                mma16816(oa[nt], Ph[kk], vf[2], vf[3]);
                mma16816(oa[nt], Pl[kk], vf[0], vf[1]);
            }
        }
        __syncthreads();
    }

    float il0 = 1.0f / lrow[0], il1 = 1.0f / lrow[1];
    int sr0 = q0 + w * 16 + (lane >> 2);
    int sr1 = sr0 + 8;
#pragma unroll
    for (int nt = 0; nt < 8; nt++) {
        int col = h_ * HDd + nt * 8 + (lane & 3) * 2;
        float a0 = oa[nt][0] * il0, a1 = oa[nt][1] * il0;
        float a2 = oa[nt][2] * il1, a3 = oa[nt][3] * il1;
        __nv_bfloat16 h0 = __float2bfloat16(a0), h1 = __float2bfloat16(a1);
        __nv_bfloat16 h2 = __float2bfloat16(a2), h3 = __float2bfloat16(a3);
        size_t i0 = (((size_t)(b_ * Ss + sr0)) * Dd + col) >> 1;
        size_t i1 = (((size_t)(b_ * Ss + sr1)) * Dd + col) >> 1;
        reinterpret_cast<uint32_t*>(oh)[i0] = pack_bf2(a0, a1);
        reinterpret_cast<uint32_t*>(ol)[i0] =
            pack_bf2(a0 - __bfloat162float(h0), a1 - __bfloat162float(h1));
        reinterpret_cast<uint32_t*>(oh)[i1] = pack_bf2(a2, a3);
        reinterpret_cast<uint32_t*>(ol)[i1] =
            pack_bf2(a2 - __bfloat162float(h2), a3 - __bfloat162float(h3));
    }
}

// ========================= launch ===========================
extern "C" void kernel_launch(void* const* d_in, const int* in_sizes, int n_in,
                              void* d_out, int out_size)
{
    const float* x     = (const float*)d_in[0];
    const float* ln1_g = (const float*)d_in[1];
    const float* ln1_b = (const float*)d_in[2];
    const float* ln2_g = (const float*)d_in[3];
    const float* ln2_b = (const float*)d_in[4];
    const float* Wq    = (const float*)d_in[5];
    const float* Wk    = (const float*)d_in[6];
    const float* Wv    = (const float*)d_in[7];
    const float* Wo    = (const float*)d_in[8];
    const float* W1    = (const float*)d_in[9];
    const float* b1    = (const float*)d_in[10];
    const float* W2    = (const float*)d_in[11];
    const float* b2    = (const float*)d_in[12];
    float* out = (float*)d_out;

    float *q, *k, *v, *x2;
    __nv_bfloat16 *xh, *xl, *oh, *ol, *fh, *fl, *wh, *wl;
    cudaGetSymbolAddress((void**)&q,   g_q);
    cudaGetSymbolAddress((void**)&k,   g_k);
    cudaGetSymbolAddress((void**)&v,   g_v);
    cudaGetSymbolAddress((void**)&x2,  g_x2);
    cudaGetSymbolAddress((void**)&xh,  g_xh);
    cudaGetSymbolAddress((void**)&xl,  g_xl);
    cudaGetSymbolAddress((void**)&oh,  g_oh);
    cudaGetSymbolAddress((void**)&ol,  g_ol);
    cudaGetSymbolAddress((void**)&fh,  g_fh);
    cudaGetSymbolAddress((void**)&fl,  g_fl);
    cudaGetSymbolAddress((void**)&wh,  g_wh);
    cudaGetSymbolAddress((void**)&wl,  g_wl);

    cudaFuncSetAttribute(gemm_mma<MD_QKV>, cudaFuncAttributeMaxDynamicSharedMemorySize, GEMM_SMEM);
    cudaFuncSetAttribute(gemm_mma<MD_RES>, cudaFuncAttributeMaxDynamicSharedMemorySize, GEMM_SMEM);
    cudaFuncSetAttribute(gemm_mma<MD_BIAS | MD_RELU | MD_SPLIT>, cudaFuncAttributeMaxDynamicSharedMemorySize, GEMM_SMEM);
    cudaFuncSetAttribute(gemm_mma<MD_BIAS | MD_RELU | MD_RES>, cudaFuncAttributeMaxDynamicSharedMemorySize, GEMM_SMEM);
    cudaFuncSetAttribute(attn_mma, cudaFuncAttributeMaxDynamicSharedMemorySize, ATT_SMEM);

    dim3 blk(256);
    dim3 gD(Dd / 128, Mm / 256);     // (8, 32)
    dim3 gF(FFf / 128, Mm / 256);    // (32, 32)
    const int QD4 = Dd * Dd / 4, FD4 = Dd * FFf / 4;

    // weight splits
    split_kernel<<<QD4 / 256, blk>>>(Wq, wh + WQO, wl + WQO, QD4);
    split_kernel<<<QD4 / 256, blk>>>(Wk, wh + WKO, wl + WKO, QD4);
    split_kernel<<<QD4 / 256, blk>>>(Wv, wh + WVO, wl + WVO, QD4);
    split_kernel<<<QD4 / 256, blk>>>(Wo, wh + WOO, wl + WOO, QD4);
    split_kernel<<<FD4 / 256, blk>>>(W1, wh + W1O, wl + W1O, FD4);
    split_kernel<<<FD4 / 256, blk>>>(W2, wh + W2O, wl + W2O, FD4);

    // h = LN1(x) -> hi/lo
    ln_split_kernel<<<Mm, blk>>>(x, ln1_g, ln1_b, xh, xl);
    // q,k,v = h @ W{q,k,v}  ([B,H,S,HD] layout, fp32)
    gemm_mma<MD_QKV><<<gD, blk, GEMM_SMEM>>>(xh, xl, wh + WQO, wl + WQO, nullptr, nullptr, q, nullptr, nullptr, Dd, Dd);
    gemm_mma<MD_QKV><<<gD, blk, GEMM_SMEM>>>(xh, xl, wh + WKO, wl + WKO, nullptr, nullptr, k, nullptr, nullptr, Dd, Dd);
    gemm_mma<MD_QKV><<<gD, blk, GEMM_SMEM>>>(xh, xl, wh + WVO, wl + WVO, nullptr, nullptr, v, nullptr, nullptr, Dd, Dd);
    // attention -> hi/lo o
    attn_mma<<<dim3(Ss / 128, Bb * Hh), blk, ATT_SMEM>>>(q, k, v, oh, ol);
    // x2 = x + o @ Wo
    gemm_mma<MD_RES><<<gD, blk, GEMM_SMEM>>>(oh, ol, wh + WOO, wl + WOO, nullptr, x, x2, nullptr, nullptr, Dd, Dd);
    // h = LN2(x2) -> hi/lo
    ln_split_kernel<<<Mm, blk>>>(x2, ln2_g, ln2_b, xh, xl);
    // ff1 = relu(h @ W1 + b1) -> hi/lo
    gemm_mma<MD_BIAS | MD_RELU | MD_SPLIT><<<gF, blk, GEMM_SMEM>>>(xh, xl, wh + W1O, wl + W1O, b1, nullptr, nullptr, fh, fl, FFf, Dd);
    // out = x2 + relu(ff1 @ W2 + b2)
    gemm_mma<MD_BIAS | MD_RELU | MD_RES><<<gD, blk, GEMM_SMEM>>>(fh, fl, wh + W2O, wl + W2O, b2, x2, out, nullptr, nullptr, Dd, FFf);
}

// round 12
// speedup vs baseline: 2.8017x; 1.0010x over previous
#include <cuda_runtime.h>
#include <cuda_bf16.h>
#include <cstdint>

// ---------------------------------------------------------------------------
// TransformerLayer: B=4, S=2048, D=1024, H=16, HD=64, FF=4096, fp32 I/O.
// Round 11: R10 with cp.async alignment fixed (LDA=40/LDB=136, rows ≡ 0 mod
// 16 B). 128x128 tile, k-chunk 32, NSTG=3, one barrier/chunk, 2 CTAs/SM.
// Fused QKV (N=3072). Attention unchanged (R6/R9).
// ---------------------------------------------------------------------------

constexpr int Bb = 4, Ss = 2048, Dd = 1024, Hh = 16, HDd = 64, FFf = 4096;
constexpr int Mm = Bb * Ss;            // 8192 rows
constexpr float EPS = 1e-5f;
constexpr float SCL2 = 0.125f * 1.4426950408889634f;

// fp32 scratch
__device__ float g_q  [Mm * Dd];
__device__ float g_k  [Mm * Dd];
__device__ float g_v  [Mm * Dd];
__device__ float g_x2 [Mm * Dd];
// bf16 hi/lo activation scratch
__device__ __nv_bfloat16 g_xh[(size_t)Mm * Dd];
__device__ __nv_bfloat16 g_xl[(size_t)Mm * Dd];
__device__ __nv_bfloat16 g_oh[(size_t)Mm * Dd];
__device__ __nv_bfloat16 g_ol[(size_t)Mm * Dd];
__device__ __nv_bfloat16 g_fh[(size_t)Mm * FFf];
__device__ __nv_bfloat16 g_fl[(size_t)Mm * FFf];
// bf16 hi/lo weights. Layout: [0,3M) fused Wqkv [1024,3072]; then Wo, W1, W2.
constexpr size_t WQKV = 0, WOO = 3u << 20;
constexpr size_t W1O = 4u << 20, W2O = 8u << 20, WTOT = 12u << 20;
__device__ __nv_bfloat16 g_wh[WTOT];
__device__ __nv_bfloat16 g_wl[WTOT];

// ========================= small PTX helpers ===========================
__device__ __forceinline__ uint32_t smem_u32(const void* p) {
    uint32_t a;
    asm("{ .reg .u64 t; cvta.to.shared.u64 t, %1; cvt.u32.u64 %0, t; }" : "=r"(a) : "l"(p));
    return a;
}
__device__ __forceinline__ void ldsm_x4(uint32_t (&r)[4], uint32_t addr) {
    asm volatile("ldmatrix.sync.aligned.m8n8.x4.shared.b16 {%0,%1,%2,%3}, [%4];"
        : "=r"(r[0]), "=r"(r[1]), "=r"(r[2]), "=r"(r[3]) : "r"(addr));
}
__device__ __forceinline__ void ldsm_x4_t(uint32_t (&r)[4], uint32_t addr) {
    asm volatile("ldmatrix.sync.aligned.m8n8.x4.trans.shared.b16 {%0,%1,%2,%3}, [%4];"
        : "=r"(r[0]), "=r"(r[1]), "=r"(r[2]), "=r"(r[3]) : "r"(addr));
}
__device__ __forceinline__ void mma16816(float (&c)[4], const uint32_t (&a)[4],
                                         uint32_t b0, uint32_t b1) {
    asm volatile("mma.sync.aligned.m16n8k16.row.col.f32.bf16.bf16.f32 "
        "{%0,%1,%2,%3}, {%4,%5,%6,%7}, {%8,%9}, {%0,%1,%2,%3};"
        : "+f"(c[0]), "+f"(c[1]), "+f"(c[2]), "+f"(c[3])
        : "r"(a[0]), "r"(a[1]), "r"(a[2]), "r"(a[3]), "r"(b0), "r"(b1));
}
__device__ __forceinline__ uint32_t pack_bf2(float a, float b) {
    __nv_bfloat162 h = __floats2bfloat162_rn(a, b);
    return *reinterpret_cast<uint32_t*>(&h);
}
__device__ __forceinline__ float ex2(float x) {
    float y;
    asm("ex2.approx.ftz.f32 %0, %1;" : "=f"(y) : "f"(x));
    return y;
}
__device__ __forceinline__ void cp16(uint32_t dst, const void* src) {
    asm volatile("cp.async.cg.shared.global [%0], [%1], 16;" :: "r"(dst), "l"(src) : "memory");
}
__device__ __forceinline__ void cp_commit() { asm volatile("cp.async.commit_group;" ::: "memory"); }
template <int N>
__device__ __forceinline__ void cp_wait() {
    asm volatile("cp.async.wait_group %0;" :: "n"(N) : "memory");
}

// ========================= LayerNorm (writes hi/lo bf16) ====================
__global__ void __launch_bounds__(256) ln_split_kernel(
    const float* __restrict__ x, const float* __restrict__ g,
    const float* __restrict__ b, __nv_bfloat16* __restrict__ oh,
    __nv_bfloat16* __restrict__ ol)
{
    int row = blockIdx.x;
    int t = threadIdx.x;
    const float4 v = reinterpret_cast<const float4*>(x + (size_t)row * Dd)[t];
    float s  = v.x + v.y + v.z + v.w;
    float ss = v.x * v.x + v.y * v.y + v.z * v.z + v.w * v.w;
#pragma unroll
    for (int o = 16; o > 0; o >>= 1) {
        s  += __shfl_xor_sync(0xffffffffu, s,  o);
        ss += __shfl_xor_sync(0xffffffffu, ss, o);
    }
    __shared__ float red[16];
    int w = t >> 5;
    if ((t & 31) == 0) { red[w] = s; red[8 + w] = ss; }
    __syncthreads();
    float st = 0.f, sst = 0.f;
#pragma unroll
    for (int i = 0; i < 8; i++) { st += red[i]; sst += red[8 + i]; }
    float mu  = st  * (1.0f / Dd);
    float var = sst * (1.0f / Dd) - mu * mu;
    float inv = rsqrtf(var + EPS);
    float4 gg = reinterpret_cast<const float4*>(g)[t];
    float4 bb = reinterpret_cast<const float4*>(b)[t];
    float f[4];
    f[0] = (v.x - mu) * inv * gg.x + bb.x;
    f[1] = (v.y - mu) * inv * gg.y + bb.y;
    f[2] = (v.z - mu) * inv * gg.z + bb.z;
    f[3] = (v.w - mu) * inv * gg.w + bb.w;
    uint32_t hw[2], lw[2];
#pragma unroll
    for (int e = 0; e < 2; e++) {
        float a = f[2 * e], c = f[2 * e + 1];
        __nv_bfloat16 ha = __float2bfloat16(a), hc = __float2bfloat16(c);
        hw[e] = pack_bf2(a, c);
        lw[e] = pack_bf2(a - __bfloat162float(ha), c - __bfloat162float(hc));
    }
    size_t idx = (size_t)row * (Dd / 4) + t;
    reinterpret_cast<uint2*>(oh)[idx] = make_uint2(hw[0], hw[1]);
    reinterpret_cast<uint2*>(ol)[idx] = make_uint2(lw[0], lw[1]);
}

// ========================= split fp32 -> bf16 hi/lo =========================
__global__ void __launch_bounds__(256) split_kernel(
    const float* __restrict__ x, __nv_bfloat16* __restrict__ hi,
    __nv_bfloat16* __restrict__ lo, int n4)
{
    int i = blockIdx.x * 256 + threadIdx.x;
    if (i >= n4) return;
    float4 v = reinterpret_cast<const float4*>(x)[i];
    float f[4] = {v.x, v.y, v.z, v.w};
    uint32_t h[2], l[2];
#pragma unroll
    for (int e = 0; e < 2; e++) {
        float a = f[2 * e], b = f[2 * e + 1];
        __nv_bfloat16 ha = __float2bfloat16(a), hb = __float2bfloat16(b);
        h[e] = pack_bf2(a, b);
        l[e] = pack_bf2(a - __bfloat162float(ha), b - __bfloat162float(hb));
    }
    reinterpret_cast<uint2*>(hi)[i] = make_uint2(h[0], h[1]);
    reinterpret_cast<uint2*>(lo)[i] = make_uint2(l[0], l[1]);
}

// strided split: src [K,1024] -> dst rows stride 3072, column offset coloff
__global__ void __launch_bounds__(256) split_strided_kernel(
    const float* __restrict__ x, __nv_bfloat16* __restrict__ hi,
    __nv_bfloat16* __restrict__ lo, int coloff, int n4)
{
    int i = blockIdx.x * 256 + threadIdx.x;
    if (i >= n4) return;
    float4 v = reinterpret_cast<const float4*>(x)[i];
    float f[4] = {v.x, v.y, v.z, v.w};
    uint32_t h[2], l[2];
#pragma unroll
    for (int e = 0; e < 2; e++) {
        float a = f[2 * e], b = f[2 * e + 1];
        __nv_bfloat16 ha = __float2bfloat16(a), hb = __float2bfloat16(b);
        h[e] = pack_bf2(a, b);
        l[e] = pack_bf2(a - __bfloat162float(ha), b - __bfloat162float(hb));
    }
    int row = (i * 4) >> 10;                  // src N = 1024
    int col = (i * 4) & 1023;
    size_t di = ((size_t)row * 3072 + coloff + col) >> 2;
    reinterpret_cast<uint2*>(hi)[di] = make_uint2(h[0], h[1]);
    reinterpret_cast<uint2*>(lo)[di] = make_uint2(l[0], l[1]);
}

// ========================= cp.async split-bf16 GEMM =========================
// C[M,N] = A[M,K] @ W[K,N]; pre-split bf16 hi/lo. D = AhBh + AhBl + AlBh.
// CTA tile 128x128x32; 8 warps 2(m)x4(n), warp 64x32. NSTG=3, one barrier
// per chunk, 2 CTAs/SM. Row pitches MUST be 16B-multiples for cp.async.
constexpr int MD_BIAS = 1, MD_RELU = 2, MD_RES = 4, MD_QKV = 8, MD_SPLIT = 16;

constexpr int NSTG = 3;
constexpr int LDA = 40;                         // 80 B rows (16B-aligned)
constexpr int LDB = 136;                        // 272 B rows (16B-aligned)
constexpr int A_BYTES = 128 * LDA * 2;          // 10240 per matrix
constexpr int B_BYTES = 32 * LDB * 2;           // 8704 per matrix
constexpr int B_OFF   = 2 * A_BYTES;            // 20480
constexpr int STAGE   = B_OFF + 2 * B_BYTES;    // 37888
constexpr int GEMM_SMEM = NSTG * STAGE;         // 113664 (2 CTAs = 227328)

template <int MODE>
__global__ void __launch_bounds__(256, 2) gemm_mma(
    const __nv_bfloat16* __restrict__ Ah, const __nv_bfloat16* __restrict__ Al,
    const __nv_bfloat16* __restrict__ Bh, const __nv_bfloat16* __restrict__ Bl,
    const float* __restrict__ bias, const float* __restrict__ res,
    float* __restrict__ C, float* __restrict__ C2, float* __restrict__ C3,
    __nv_bfloat16* __restrict__ Chi, __nv_bfloat16* __restrict__ Clo,
    int N, int K)
{
    extern __shared__ char dsm[];
    const uint32_t smemU = smem_u32(dsm);

    const int tid  = threadIdx.x;
    const int lane = tid & 31;
    const int wid  = tid >> 5;
    const int wm   = wid >> 2;          // 0..1 (64-row slab)
    const int wn   = wid & 3;           // 0..3 (32-col slab)
    const int m0   = blockIdx.y * 128;
    const int n0   = blockIdx.x * 128;
    const int NC   = K >> 5;

    auto issue_stage = [&](int c) {
        const uint32_t sb = smemU + (uint32_t)(c % NSTG) * STAGE;
        const int k0 = c << 5;
        // A: 128 rows x 4 segs of 16B per matrix = 512 chunks; 2/thread
#pragma unroll
        for (int i = 0; i < 2; i++) {
            int ch = tid + i * 256;
            int arow = ch >> 2, aseg = ch & 3;
            uint32_t ad = sb + ((uint32_t)arow * LDA + (uint32_t)aseg * 8u) * 2u;
            cp16(ad, Ah + (size_t)(m0 + arow) * K + k0 + aseg * 8);
            cp16(ad + A_BYTES, Al + (size_t)(m0 + arow) * K + k0 + aseg * 8);
        }
        // B: 32 rows x 16 segs per matrix = 512 chunks; 2/thread
#pragma unroll
        for (int i = 0; i < 2; i++) {
            int ch = tid + i * 256;
            int brow = ch >> 4, bseg = ch & 15;
            uint32_t bd = sb + (uint32_t)B_OFF + ((uint32_t)brow * LDB + (uint32_t)bseg * 8u) * 2u;
            cp16(bd, Bh + (size_t)(k0 + brow) * N + n0 + bseg * 8);
            cp16(bd + B_BYTES, Bl + (size_t)(k0 + brow) * N + n0 + bseg * 8);
        }
        cp_commit();
    };

    issue_stage(0);
    issue_stage(1);

    float acc[4][4][4];
#pragma unroll
    for (int mt = 0; mt < 4; mt++)
#pragma unroll
        for (int nt = 0; nt < 4; nt++)
#pragma unroll
            for (int e = 0; e < 4; e++) acc[mt][nt][e] = 0.f;

    const uint32_t aCmp0 = smemU + ((uint32_t)(wm * 64 + (lane & 15)) * LDA +
                                    (uint32_t)(lane >> 4) * 8) * 2u;
    // ldsm.x4.trans: lanes 0-15 rows at n-base, lanes 16-31 at +16B (next 8 n)
    const uint32_t bCmp0 = smemU + (uint32_t)B_OFF +
                           ((uint32_t)(lane & 15) * LDB + (uint32_t)(wn * 32)) * 2u +
                           (uint32_t)(lane >> 4) * 16u;

    for (int c = 0; c < NC; c++) {
        cp_wait<1>();
        __syncthreads();
        // stage (c+2)%3 == (c-1)%3; its readers finished before this barrier
        if (c + 2 < NC) issue_stage(c + 2);

        const uint32_t so = (uint32_t)(c % NSTG) * STAGE;
        const uint32_t aC = aCmp0 + so;
        const uint32_t bC = bCmp0 + so;
#pragma unroll
        for (int ks = 0; ks < 2; ks++) {
            uint32_t Bhf[4][2], Blf[4][2];
#pragma unroll
            for (int np = 0; np < 2; np++) {
                uint32_t bd = bC + (uint32_t)ks * (16 * LDB * 2) + (uint32_t)np * 32u;
                uint32_t t4[4];
                ldsm_x4_t(t4, bd);
                Bhf[2 * np][0] = t4[0]; Bhf[2 * np][1] = t4[1];
                Bhf[2 * np + 1][0] = t4[2]; Bhf[2 * np + 1][1] = t4[3];
                ldsm_x4_t(t4, bd + B_BYTES);
                Blf[2 * np][0] = t4[0]; Blf[2 * np][1] = t4[1];
                Blf[2 * np + 1][0] = t4[2]; Blf[2 * np + 1][1] = t4[3];
            }
#pragma unroll
            for (int mt = 0; mt < 4; mt++) {
                uint32_t Ahf[4], Alf[4];
                uint32_t ad = aC + (uint32_t)mt * (16 * LDA * 2) + (uint32_t)ks * 32u;
                ldsm_x4(Ahf, ad);
                ldsm_x4(Alf, ad + A_BYTES);
#pragma unroll
                for (int nt = 0; nt < 4; nt++) {
                    mma16816(acc[mt][nt], Ahf, Bhf[nt][0], Bhf[nt][1]);
                    mma16816(acc[mt][nt], Ahf, Blf[nt][0], Blf[nt][1]);
                    mma16816(acc[mt][nt], Alf, Bhf[nt][0], Bhf[nt][1]);
                }
            }
        }
    }

    // -------- epilogue --------
    const int rbase = m0 + wm * 64;
    const int cbase = n0 + wn * 32;
#pragma unroll
    for (int mt = 0; mt < 4; mt++)
#pragma unroll
        for (int nt = 0; nt < 4; nt++) {
#pragma unroll
            for (int half = 0; half < 2; half++) {
                int r = rbase + mt * 16 + (lane >> 2) + half * 8;
                int cc = cbase + nt * 8 + (lane & 3) * 2;
                float2 v;
                v.x = acc[mt][nt][half * 2 + 0];
                v.y = acc[mt][nt][half * 2 + 1];
                if (MODE & MD_BIAS) {
                    float2 bb = *reinterpret_cast<const float2*>(bias + cc);
                    v.x += bb.x; v.y += bb.y;
                }
                if (MODE & MD_RELU) {
                    v.x = fmaxf(v.x, 0.f); v.y = fmaxf(v.y, 0.f);
                }
                if (MODE & MD_RES) {
                    float2 rr = *reinterpret_cast<const float2*>(res + (size_t)r * N + cc);
                    v.x += rr.x; v.y += rr.y;
                }
                if (MODE & MD_SPLIT) {
                    __nv_bfloat16 hx = __float2bfloat16(v.x), hy = __float2bfloat16(v.y);
                    size_t idx = ((size_t)r * N + cc) >> 1;
                    reinterpret_cast<uint32_t*>(Chi)[idx] = pack_bf2(v.x, v.y);
                    reinterpret_cast<uint32_t*>(Clo)[idx] =
                        pack_bf2(v.x - __bfloat162float(hx), v.y - __bfloat162float(hy));
                } else if (MODE & MD_QKV) {
                    // fused QKV: cc in [0,3072). which selects q/k/v.
                    int which = cc >> 10;
                    int c1 = cc & 1023;
                    float* dst = which == 0 ? C : (which == 1 ? C2 : C3);
                    int b_ = r >> 11, s_ = r & (Ss - 1);
                    int h_ = c1 >> 6, d_ = c1 & 63;
                    *reinterpret_cast<float2*>(dst +
                        ((size_t)(b_ * Hh + h_) * Ss + s_) * HDd + d_) = v;
                } else {
                    *reinterpret_cast<float2*>(C + (size_t)r * N + cc) = v;
                }
            }
        }
}

// ========================= mma.sync flash attention (R6/R9) =================
constexpr int ALD = 72;
constexpr int KMAT = 64 * ALD * 2;
constexpr int ASTAGE = 4 * KMAT;
constexpr int QOFF = 2 * ASTAGE;
constexpr int QMAT = 128 * ALD * 2;
constexpr int ATT_SMEM = QOFF + 2 * QMAT;

__global__ void __launch_bounds__(256, 1) attn_mma(
    const float* __restrict__ q, const float* __restrict__ k,
    const float* __restrict__ v, __nv_bfloat16* __restrict__ oh,
    __nv_bfloat16* __restrict__ ol)
{
    extern __shared__ char sm[];
    const uint32_t S0 = smem_u32(sm);
    const int tid = threadIdx.x, lane = tid & 31, w = tid >> 5;
    const int bh = blockIdx.y, q0 = blockIdx.x * 128;
    const int b_ = bh >> 4, h_ = bh & 15;

    const float* qb = q + ((size_t)bh * Ss + q0) * HDd;
    const float* kb = k + (size_t)bh * Ss * HDd;
    const float* vb = v + (size_t)bh * Ss * HDd;

    {
        int r = tid >> 1, cb = (tid & 1) * 32;
        const float4* src = reinterpret_cast<const float4*>(qb + r * HDd + cb);
        char* qh = sm + QOFF;
        char* ql = qh + QMAT;
        uint32_t off = ((uint32_t)r * ALD + (uint32_t)cb) * 2u;
#pragma unroll
        for (int j = 0; j < 8; j += 2) {
            uint32_t hw[4], lw[4];
#pragma unroll
            for (int e = 0; e < 2; e++) {
                float4 f = src[j + e];
                float a = f.x * SCL2, b2 = f.y * SCL2, c = f.z * SCL2, d = f.w * SCL2;
                __nv_bfloat16 ha = __float2bfloat16(a), hb = __float2bfloat16(b2);
                __nv_bfloat16 hc = __float2bfloat16(c), hd = __float2bfloat16(d);
                hw[2 * e + 0] = pack_bf2(a, b2);
                hw[2 * e + 1] = pack_bf2(c, d);
                lw[2 * e + 0] = pack_bf2(a - __bfloat162float(ha), b2 - __bfloat162float(hb));
                lw[2 * e + 1] = pack_bf2(c - __bfloat162float(hc), d - __bfloat162float(hd));
            }
            *reinterpret_cast<uint4*>(qh + off + j * 8) = make_uint4(hw[0], hw[1], hw[2], hw[3]);
            *reinterpret_cast<uint4*>(ql + off + j * 8) = make_uint4(lw[0], lw[1], lw[2], lw[3]);
        }
    }
    __syncthreads();

    uint32_t Qh[4][4], Ql[4][4];
    {
        uint32_t base = S0 + QOFF +
            (((uint32_t)(w * 16 + (lane & 15))) * ALD + (uint32_t)(lane >> 4) * 8u) * 2u;
#pragma unroll
        for (int ks = 0; ks < 4; ks++) {
            ldsm_x4(Qh[ks], base + (uint32_t)ks * 32u);
            ldsm_x4(Ql[ks], base + (uint32_t)QMAT + (uint32_t)ks * 32u);
        }
    }

    float oa[8][4];
#pragma unroll
    for (int nt = 0; nt < 8; nt++)
#pragma unroll
        for (int e = 0; e < 4; e++) oa[nt][e] = 0.f;
    float mrow[2] = {-1e30f, -1e30f};
    float lrow[2] = {0.f, 0.f};

    const int krow = tid >> 2, kcb = (tid & 3) * 16;
    float4 rk[4], rv[4];
    {
        const float4* kp = reinterpret_cast<const float4*>(kb + (size_t)krow * HDd + kcb);
        const float4* vp = reinterpret_cast<const float4*>(vb + (size_t)krow * HDd + kcb);
#pragma unroll
        for (int j = 0; j < 4; j++) { rk[j] = kp[j]; rv[j] = vp[j]; }
    }

    const uint32_t stoff = ((uint32_t)krow * ALD + (uint32_t)kcb) * 2u;

    for (int t = 0; t < Ss / 64; t++) {
        const int s = t & 1;
        char* sb = sm + s * ASTAGE;
        const uint32_t sbU = S0 + (uint32_t)(s * ASTAGE);

        {
            uint32_t hw[8], lw[8];
#pragma unroll
            for (int j = 0; j < 4; j++) {
                float f0 = rk[j].x, f1 = rk[j].y, f2 = rk[j].z, f3 = rk[j].w;
                __nv_bfloat16 h0 = __float2bfloat16(f0), h1 = __float2bfloat16(f1);
                __nv_bfloat16 h2 = __float2bfloat16(f2), h3 = __float2bfloat16(f3);
                hw[2 * j] = pack_bf2(f0, f1); hw[2 * j + 1] = pack_bf2(f2, f3);
                lw[2 * j] = pack_bf2(f0 - __bfloat162float(h0), f1 - __bfloat162float(h1));
                lw[2 * j + 1] = pack_bf2(f2 - __bfloat162float(h2), f3 - __bfloat162float(h3));
            }
            *reinterpret_cast<uint4*>(sb + stoff)      = make_uint4(hw[0], hw[1], hw[2], hw[3]);
            *reinterpret_cast<uint4*>(sb + stoff + 16) = make_uint4(hw[4], hw[5], hw[6], hw[7]);
            *reinterpret_cast<uint4*>(sb + KMAT + stoff)      = make_uint4(lw[0], lw[1], lw[2], lw[3]);
            *reinterpret_cast<uint4*>(sb + KMAT + stoff + 16) = make_uint4(lw[4], lw[5], lw[6], lw[7]);
#pragma unroll
            for (int j = 0; j < 4; j++) {
                float f0 = rv[j].x, f1 = rv[j].y, f2 = rv[j].z, f3 = rv[j].w;
                __nv_bfloat16 h0 = __float2bfloat16(f0), h1 = __float2bfloat16(f1);
                __nv_bfloat16 h2 = __float2bfloat16(f2), h3 = __float2bfloat16(f3);
                hw[2 * j] = pack_bf2(f0, f1); hw[2 * j + 1] = pack_bf2(f2, f3);
                lw[2 * j] = pack_bf2(f0 - __bfloat162float(h0), f1 - __bfloat162float(h1));
                lw[2 * j + 1] = pack_bf2(f2 - __bfloat162float(h2), f3 - __bfloat162float(h3));
            }
            *reinterpret_cast<uint4*>(sb + 2 * KMAT + stoff)      = make_uint4(hw[0], hw[1], hw[2], hw[3]);
            *reinterpret_cast<uint4*>(sb + 2 * KMAT + stoff + 16) = make_uint4(hw[4], hw[5], hw[6], hw[7]);
            *reinterpret_cast<uint4*>(sb + 3 * KMAT + stoff)      = make_uint4(lw[0], lw[1], lw[2], lw[3]);
            *reinterpret_cast<uint4*>(sb + 3 * KMAT + stoff + 16) = make_uint4(lw[4], lw[5], lw[6], lw[7]);
        }
        __syncthreads();

        if (t + 1 < Ss / 64) {
            const float4* kp = reinterpret_cast<const float4*>(
                kb + (size_t)((t + 1) * 64 + krow) * HDd + kcb);
            const float4* vp = reinterpret_cast<const float4*>(
                vb + (size_t)((t + 1) * 64 + krow) * HDd + kcb);
#pragma unroll
            for (int j = 0; j < 4; j++) { rk[j] = kp[j]; rv[j] = vp[j]; }
        }

        float sc[8][4];
#pragma unroll
        for (int nt = 0; nt < 8; nt++)
#pragma unroll
            for (int e = 0; e < 4; e++) sc[nt][e] = 0.f;

        const uint32_t kfb = sbU + (uint32_t)(lane >> 4) * (uint32_t)KMAT +
            (((uint32_t)(lane & 7)) * ALD + (uint32_t)((lane >> 3) & 1) * 8u) * 2u;
#pragma unroll
        for (int nt = 0; nt < 8; nt++) {
#pragma unroll
            for (int ks = 0; ks < 4; ks++) {
                uint32_t kf[4];
                ldsm_x4(kf, kfb + ((uint32_t)nt * 8u * ALD + (uint32_t)ks * 16u) * 2u);
                mma16816(sc[nt], Qh[ks], kf[0], kf[1]);
                mma16816(sc[nt], Qh[ks], kf[2], kf[3]);
                mma16816(sc[nt], Ql[ks], kf[0], kf[1]);
            }
        }

        float mt0 = sc[0][0], mt1 = sc[0][2];
#pragma unroll
        for (int nt = 0; nt < 8; nt++) {
            mt0 = fmaxf(mt0, fmaxf(sc[nt][0], sc[nt][1]));
            mt1 = fmaxf(mt1, fmaxf(sc[nt][2], sc[nt][3]));
        }
        mt0 = fmaxf(mt0, __shfl_xor_sync(0xffffffffu, mt0, 1));
        mt0 = fmaxf(mt0, __shfl_xor_sync(0xffffffffu, mt0, 2));
        mt1 = fmaxf(mt1, __shfl_xor_sync(0xffffffffu, mt1, 1));
        mt1 = fmaxf(mt1, __shfl_xor_sync(0xffffffffu, mt1, 2));
        float mn0 = fmaxf(mrow[0], mt0), mn1 = fmaxf(mrow[1], mt1);
        float c0 = ex2(mrow[0] - mn0), c1 = ex2(mrow[1] - mn1);
        mrow[0] = mn0; mrow[1] = mn1;

        float ls0 = 0.f, ls1 = 0.f;
#pragma unroll
        for (int nt = 0; nt < 8; nt++) {
            sc[nt][0] = ex2(sc[nt][0] - mn0);
            sc[nt][1] = ex2(sc[nt][1] - mn0);
            sc[nt][2] = ex2(sc[nt][2] - mn1);
            sc[nt][3] = ex2(sc[nt][3] - mn1);
            ls0 += sc[nt][0] + sc[nt][1];
            ls1 += sc[nt][2] + sc[nt][3];
        }
        ls0 += __shfl_xor_sync(0xffffffffu, ls0, 1);
        ls0 += __shfl_xor_sync(0xffffffffu, ls0, 2);
        ls1 += __shfl_xor_sync(0xffffffffu, ls1, 1);
        ls1 += __shfl_xor_sync(0xffffffffu, ls1, 2);
        lrow[0] = lrow[0] * c0 + ls0;
        lrow[1] = lrow[1] * c1 + ls1;
#pragma unroll
        for (int nt = 0; nt < 8; nt++) {
            oa[nt][0] *= c0; oa[nt][1] *= c0;
            oa[nt][2] *= c1; oa[nt][3] *= c1;
        }

        uint32_t Ph[4][4], Pl[4][4];
#pragma unroll
        for (int kk = 0; kk < 4; kk++) {
#pragma unroll
            for (int half = 0; half < 2; half++) {
                float p0 = sc[2 * kk + half][0], p1 = sc[2 * kk + half][1];
                float p2 = sc[2 * kk + half][2], p3 = sc[2 * kk + half][3];
                __nv_bfloat16 h0 = __float2bfloat16(p0), h1 = __float2bfloat16(p1);
                __nv_bfloat16 h2 = __float2bfloat16(p2), h3 = __float2bfloat16(p3);
                Ph[kk][2 * half + 0] = pack_bf2(p0, p1);
                Ph[kk][2 * half + 1] = pack_bf2(p2, p3);
                Pl[kk][2 * half + 0] = pack_bf2(p0 - __bfloat162float(h0),
                                                p1 - __bfloat162float(h1));
                Pl[kk][2 * half + 1] = pack_bf2(p2 - __bfloat162float(h2),
                                                p3 - __bfloat162float(h3));
            }
        }

        const uint32_t vfb = sbU + 2u * (uint32_t)KMAT +
            (uint32_t)(lane >> 4) * (uint32_t)KMAT +
            ((uint32_t)(lane & 15)) * (uint32_t)ALD * 2u;
#pragma unroll
        for (int kk = 0; kk < 4; kk++) {
#pragma unroll
            for (int nt = 0; nt < 8; nt++) {
                uint32_t vf[4];
                ldsm_x4_t(vf, vfb + ((uint32_t)kk * 16u * ALD + (uint32_t)nt * 8u) * 2u);
                mma16816(oa[nt], Ph[kk], vf[0], vf[1]);
                mma16816(oa[nt], Ph[kk], vf[2], vf[3]);
                mma16816(oa[nt], Pl[kk], vf[0], vf[1]);
            }
        }
        __syncthreads();
    }

    float il0 = 1.0f / lrow[0], il1 = 1.0f / lrow[1];
    int sr0 = q0 + w * 16 + (lane >> 2);
    int sr1 = sr0 + 8;
#pragma unroll
    for (int nt = 0; nt < 8; nt++) {
        int col = h_ * HDd + nt * 8 + (lane & 3) * 2;
        float a0 = oa[nt][0] * il0, a1 = oa[nt][1] * il0;
        float a2 = oa[nt][2] * il1, a3 = oa[nt][3] * il1;
        __nv_bfloat16 h0 = __float2bfloat16(a0), h1 = __float2bfloat16(a1);
        __nv_bfloat16 h2 = __float2bfloat16(a2), h3 = __float2bfloat16(a3);
        size_t i0 = (((size_t)(b_ * Ss + sr0)) * Dd + col) >> 1;
        size_t i1 = (((size_t)(b_ * Ss + sr1)) * Dd + col) >> 1;
        reinterpret_cast<uint32_t*>(oh)[i0] = pack_bf2(a0, a1);
        reinterpret_cast<uint32_t*>(ol)[i0] =
            pack_bf2(a0 - __bfloat162float(h0), a1 - __bfloat162float(h1));
        reinterpret_cast<uint32_t*>(oh)[i1] = pack_bf2(a2, a3);
        reinterpret_cast<uint32_t*>(ol)[i1] =
            pack_bf2(a2 - __bfloat162float(h2), a3 - __bfloat162float(h3));
    }
}

// ========================= launch ===========================
extern "C" void kernel_launch(void* const* d_in, const int* in_sizes, int n_in,
                              void* d_out, int out_size)
{
    const float* x     = (const float*)d_in[0];
    const float* ln1_g = (const float*)d_in[1];
    const float* ln1_b = (const float*)d_in[2];
    const float* ln2_g = (const float*)d_in[3];
    const float* ln2_b = (const float*)d_in[4];
    const float* Wq    = (const float*)d_in[5];
    const float* Wk    = (const float*)d_in[6];
    const float* Wv    = (const float*)d_in[7];
    const float* Wo    = (const float*)d_in[8];
    const float* W1    = (const float*)d_in[9];
    const float* b1    = (const float*)d_in[10];
    const float* W2    = (const float*)d_in[11];
    const float* b2    = (const float*)d_in[12];
    float* out = (float*)d_out;

    float *q, *k, *v, *x2;
    __nv_bfloat16 *xh, *xl, *oh, *ol, *fh, *fl, *wh, *wl;
    cudaGetSymbolAddress((void**)&q,   g_q);
    cudaGetSymbolAddress((void**)&k,   g_k);
    cudaGetSymbolAddress((void**)&v,   g_v);
    cudaGetSymbolAddress((void**)&x2,  g_x2);
    cudaGetSymbolAddress((void**)&xh,  g_xh);
    cudaGetSymbolAddress((void**)&xl,  g_xl);
    cudaGetSymbolAddress((void**)&oh,  g_oh);
    cudaGetSymbolAddress((void**)&ol,  g_ol);
    cudaGetSymbolAddress((void**)&fh,  g_fh);
    cudaGetSymbolAddress((void**)&fl,  g_fl);
    cudaGetSymbolAddress((void**)&wh,  g_wh);
    cudaGetSymbolAddress((void**)&wl,  g_wl);

    cudaFuncSetAttribute(gemm_mma<MD_QKV>, cudaFuncAttributeMaxDynamicSharedMemorySize, GEMM_SMEM);
    cudaFuncSetAttribute(gemm_mma<MD_RES>, cudaFuncAttributeMaxDynamicSharedMemorySize, GEMM_SMEM);
    cudaFuncSetAttribute(gemm_mma<MD_BIAS | MD_RELU | MD_SPLIT>, cudaFuncAttributeMaxDynamicSharedMemorySize, GEMM_SMEM);
    cudaFuncSetAttribute(gemm_mma<MD_BIAS | MD_RELU | MD_RES>, cudaFuncAttributeMaxDynamicSharedMemorySize, GEMM_SMEM);
    cudaFuncSetAttribute(attn_mma, cudaFuncAttributeMaxDynamicSharedMemorySize, ATT_SMEM);

    dim3 blk(256);
    dim3 gQKV(3072 / 128, Mm / 128); // (24, 64)
    dim3 gD(Dd / 128, Mm / 128);     // (8, 64)
    dim3 gF(FFf / 128, Mm / 128);    // (32, 64)
    const int QD4 = Dd * Dd / 4, FD4 = Dd * FFf / 4;

    // weight splits: Wq/Wk/Wv strided into fused [1024,3072]; Wo/W1/W2 plain
    split_strided_kernel<<<QD4 / 256, blk>>>(Wq, wh + WQKV, wl + WQKV, 0,    QD4);
    split_strided_kernel<<<QD4 / 256, blk>>>(Wk, wh + WQKV, wl + WQKV, 1024, QD4);
    split_strided_kernel<<<QD4 / 256, blk>>>(Wv, wh + WQKV, wl + WQKV, 2048, QD4);
    split_kernel<<<QD4 / 256, blk>>>(Wo, wh + WOO, wl + WOO, QD4);
    split_kernel<<<FD4 / 256, blk>>>(W1, wh + W1O, wl + W1O, FD4);
    split_kernel<<<FD4 / 256, blk>>>(W2, wh + W2O, wl + W2O, FD4);

    // h = LN1(x) -> hi/lo
    ln_split_kernel<<<Mm, blk>>>(x, ln1_g, ln1_b, xh, xl);
    // q|k|v = h @ Wqkv (fused N=3072, [B,H,S,HD] outputs)
    gemm_mma<MD_QKV><<<gQKV, blk, GEMM_SMEM>>>(xh, xl, wh + WQKV, wl + WQKV,
        nullptr, nullptr, q, k, v, nullptr, nullptr, 3072, Dd);
    // attention -> hi/lo o
    attn_mma<<<dim3(Ss / 128, Bb * Hh), blk, ATT_SMEM>>>(q, k, v, oh, ol);
    // x2 = x + o @ Wo
    gemm_mma<MD_RES><<<gD, blk, GEMM_SMEM>>>(oh, ol, wh + WOO, wl + WOO,
        nullptr, x, x2, nullptr, nullptr, nullptr, nullptr, Dd, Dd);
    // h = LN2(x2) -> hi/lo
    ln_split_kernel<<<Mm, blk>>>(x2, ln2_g, ln2_b, xh, xl);
    // ff1 = relu(h @ W1 + b1) -> hi/lo
    gemm_mma<MD_BIAS | MD_RELU | MD_SPLIT><<<gF, blk, GEMM_SMEM>>>(xh, xl,
        wh + W1O, wl + W1O, b1, nullptr, nullptr, nullptr, nullptr, fh, fl, FFf, Dd);
    // out = x2 + relu(ff1 @ W2 + b2)
    gemm_mma<MD_BIAS | MD_RELU | MD_RES><<<gD, blk, GEMM_SMEM>>>(fh, fl,
        wh + W2O, wl + W2O, b2, x2, out, nullptr, nullptr, nullptr, nullptr, Dd, FFf);
}

// round 13
// speedup vs baseline: 2.8506x; 1.0175x over previous
#include <cuda_runtime.h>
#include <cuda_bf16.h>
#include <cstdint>

// ---------------------------------------------------------------------------
// TransformerLayer: B=4, S=2048, D=1024, H=16, HD=64, FF=4096, fp32 I/O.
// Round 12: attention v2 — 256 q-rows/CTA, m=32/warp (K/V frags shared
// across 2 m-tiles), q/k/v pre-split to bf16 hi/lo in QKV epilogue (q
// pre-scaled), cp.async K/V ring, no converts in the attention loop.
// GEMMs unchanged from R11 (smem-BW-bound at ~58%).
// ---------------------------------------------------------------------------

constexpr int Bb = 4, Ss = 2048, Dd = 1024, Hh = 16, HDd = 64, FFf = 4096;
constexpr int Mm = Bb * Ss;            // 8192 rows
constexpr float EPS = 1e-5f;
constexpr float SCL2 = 0.125f * 1.4426950408889634f;

// fp32 scratch
__device__ float g_x2 [Mm * Dd];
// bf16 hi/lo activation scratch (q/k/v hold hi then lo, each Mm*Dd)
__device__ __nv_bfloat16 g_qh[2 * (size_t)Mm * Dd];
__device__ __nv_bfloat16 g_kh[2 * (size_t)Mm * Dd];
__device__ __nv_bfloat16 g_vh[2 * (size_t)Mm * Dd];
__device__ __nv_bfloat16 g_xh[(size_t)Mm * Dd];
__device__ __nv_bfloat16 g_xl[(size_t)Mm * Dd];
__device__ __nv_bfloat16 g_oh[(size_t)Mm * Dd];
__device__ __nv_bfloat16 g_ol[(size_t)Mm * Dd];
__device__ __nv_bfloat16 g_fh[(size_t)Mm * FFf];
__device__ __nv_bfloat16 g_fl[(size_t)Mm * FFf];
// bf16 hi/lo weights. Layout: [0,3M) fused Wqkv [1024,3072]; then Wo, W1, W2.
constexpr size_t WQKV = 0, WOO = 3u << 20;
constexpr size_t W1O = 4u << 20, W2O = 8u << 20, WTOT = 12u << 20;
__device__ __nv_bfloat16 g_wh[WTOT];
__device__ __nv_bfloat16 g_wl[WTOT];

// ========================= small PTX helpers ===========================
__device__ __forceinline__ uint32_t smem_u32(const void* p) {
    uint32_t a;
    asm("{ .reg .u64 t; cvta.to.shared.u64 t, %1; cvt.u32.u64 %0, t; }" : "=r"(a) : "l"(p));
    return a;
}
__device__ __forceinline__ void ldsm_x4(uint32_t (&r)[4], uint32_t addr) {
    asm volatile("ldmatrix.sync.aligned.m8n8.x4.shared.b16 {%0,%1,%2,%3}, [%4];"
        : "=r"(r[0]), "=r"(r[1]), "=r"(r[2]), "=r"(r[3]) : "r"(addr));
}
__device__ __forceinline__ void ldsm_x4_t(uint32_t (&r)[4], uint32_t addr) {
    asm volatile("ldmatrix.sync.aligned.m8n8.x4.trans.shared.b16 {%0,%1,%2,%3}, [%4];"
        : "=r"(r[0]), "=r"(r[1]), "=r"(r[2]), "=r"(r[3]) : "r"(addr));
}
__device__ __forceinline__ void mma16816(float (&c)[4], const uint32_t (&a)[4],
                                         uint32_t b0, uint32_t b1) {
    asm volatile("mma.sync.aligned.m16n8k16.row.col.f32.bf16.bf16.f32 "
        "{%0,%1,%2,%3}, {%4,%5,%6,%7}, {%8,%9}, {%0,%1,%2,%3};"
        : "+f"(c[0]), "+f"(c[1]), "+f"(c[2]), "+f"(c[3])
        : "r"(a[0]), "r"(a[1]), "r"(a[2]), "r"(a[3]), "r"(b0), "r"(b1));
}
__device__ __forceinline__ uint32_t pack_bf2(float a, float b) {
    __nv_bfloat162 h = __floats2bfloat162_rn(a, b);
    return *reinterpret_cast<uint32_t*>(&h);
}
__device__ __forceinline__ float ex2(float x) {
    float y;
    asm("ex2.approx.ftz.f32 %0, %1;" : "=f"(y) : "f"(x));
    return y;
}
__device__ __forceinline__ void cp16(uint32_t dst, const void* src) {
    asm volatile("cp.async.cg.shared.global [%0], [%1], 16;" :: "r"(dst), "l"(src) : "memory");
}
__device__ __forceinline__ void cp_commit() { asm volatile("cp.async.commit_group;" ::: "memory"); }
template <int N>
__device__ __forceinline__ void cp_wait() {
    asm volatile("cp.async.wait_group %0;" :: "n"(N) : "memory");
}

// ========================= LayerNorm (writes hi/lo bf16) ====================
__global__ void __launch_bounds__(256) ln_split_kernel(
    const float* __restrict__ x, const float* __restrict__ g,
    const float* __restrict__ b, __nv_bfloat16* __restrict__ oh,
    __nv_bfloat16* __restrict__ ol)
{
    int row = blockIdx.x;
    int t = threadIdx.x;
    const float4 v = reinterpret_cast<const float4*>(x + (size_t)row * Dd)[t];
    float s  = v.x + v.y + v.z + v.w;
    float ss = v.x * v.x + v.y * v.y + v.z * v.z + v.w * v.w;
#pragma unroll
    for (int o = 16; o > 0; o >>= 1) {
        s  += __shfl_xor_sync(0xffffffffu, s,  o);
        ss += __shfl_xor_sync(0xffffffffu, ss, o);
    }
    __shared__ float red[16];
    int w = t >> 5;
    if ((t & 31) == 0) { red[w] = s; red[8 + w] = ss; }
    __syncthreads();
    float st = 0.f, sst = 0.f;
#pragma unroll
    for (int i = 0; i < 8; i++) { st += red[i]; sst += red[8 + i]; }
    float mu  = st  * (1.0f / Dd);
    float var = sst * (1.0f / Dd) - mu * mu;
    float inv = rsqrtf(var + EPS);
    float4 gg = reinterpret_cast<const float4*>(g)[t];
    float4 bb = reinterpret_cast<const float4*>(b)[t];
    float f[4];
    f[0] = (v.x - mu) * inv * gg.x + bb.x;
    f[1] = (v.y - mu) * inv * gg.y + bb.y;
    f[2] = (v.z - mu) * inv * gg.z + bb.z;
    f[3] = (v.w - mu) * inv * gg.w + bb.w;
    uint32_t hw[2], lw[2];
#pragma unroll
    for (int e = 0; e < 2; e++) {
        float a = f[2 * e], c = f[2 * e + 1];
        __nv_bfloat16 ha = __float2bfloat16(a), hc = __float2bfloat16(c);
        hw[e] = pack_bf2(a, c);
        lw[e] = pack_bf2(a - __bfloat162float(ha), c - __bfloat162float(hc));
    }
    size_t idx = (size_t)row * (Dd / 4) + t;
    reinterpret_cast<uint2*>(oh)[idx] = make_uint2(hw[0], hw[1]);
    reinterpret_cast<uint2*>(ol)[idx] = make_uint2(lw[0], lw[1]);
}

// ========================= split fp32 -> bf16 hi/lo =========================
__global__ void __launch_bounds__(256) split_kernel(
    const float* __restrict__ x, __nv_bfloat16* __restrict__ hi,
    __nv_bfloat16* __restrict__ lo, int n4)
{
    int i = blockIdx.x * 256 + threadIdx.x;
    if (i >= n4) return;
    float4 v = reinterpret_cast<const float4*>(x)[i];
    float f[4] = {v.x, v.y, v.z, v.w};
    uint32_t h[2], l[2];
#pragma unroll
    for (int e = 0; e < 2; e++) {
        float a = f[2 * e], b = f[2 * e + 1];
        __nv_bfloat16 ha = __float2bfloat16(a), hb = __float2bfloat16(b);
        h[e] = pack_bf2(a, b);
        l[e] = pack_bf2(a - __bfloat162float(ha), b - __bfloat162float(hb));
    }
    reinterpret_cast<uint2*>(hi)[i] = make_uint2(h[0], h[1]);
    reinterpret_cast<uint2*>(lo)[i] = make_uint2(l[0], l[1]);
}

// strided split: src [K,1024] -> dst rows stride 3072, column offset coloff
__global__ void __launch_bounds__(256) split_strided_kernel(
    const float* __restrict__ x, __nv_bfloat16* __restrict__ hi,
    __nv_bfloat16* __restrict__ lo, int coloff, int n4)
{
    int i = blockIdx.x * 256 + threadIdx.x;
    if (i >= n4) return;
    float4 v = reinterpret_cast<const float4*>(x)[i];
    float f[4] = {v.x, v.y, v.z, v.w};
    uint32_t h[2], l[2];
#pragma unroll
    for (int e = 0; e < 2; e++) {
        float a = f[2 * e], b = f[2 * e + 1];
        __nv_bfloat16 ha = __float2bfloat16(a), hb = __float2bfloat16(b);
        h[e] = pack_bf2(a, b);
        l[e] = pack_bf2(a - __bfloat162float(ha), b - __bfloat162float(hb));
    }
    int row = (i * 4) >> 10;
    int col = (i * 4) & 1023;
    size_t di = ((size_t)row * 3072 + coloff + col) >> 2;
    reinterpret_cast<uint2*>(hi)[di] = make_uint2(h[0], h[1]);
    reinterpret_cast<uint2*>(lo)[di] = make_uint2(l[0], l[1]);
}

// ========================= cp.async split-bf16 GEMM (R11) ===================
constexpr int MD_BIAS = 1, MD_RELU = 2, MD_RES = 4, MD_QKV = 8, MD_SPLIT = 16;

constexpr int NSTG = 3;
constexpr int LDA = 40;
constexpr int LDB = 136;
constexpr int A_BYTES = 128 * LDA * 2;
constexpr int B_BYTES = 32 * LDB * 2;
constexpr int B_OFF   = 2 * A_BYTES;
constexpr int STAGE   = B_OFF + 2 * B_BYTES;
constexpr int GEMM_SMEM = NSTG * STAGE;

template <int MODE>
__global__ void __launch_bounds__(256, 2) gemm_mma(
    const __nv_bfloat16* __restrict__ Ah, const __nv_bfloat16* __restrict__ Al,
    const __nv_bfloat16* __restrict__ Bh, const __nv_bfloat16* __restrict__ Bl,
    const float* __restrict__ bias, const float* __restrict__ res,
    float* __restrict__ C, float* __restrict__ C2, float* __restrict__ C3,
    __nv_bfloat16* __restrict__ Chi, __nv_bfloat16* __restrict__ Clo,
    int N, int K)
{
    extern __shared__ char dsm[];
    const uint32_t smemU = smem_u32(dsm);

    const int tid  = threadIdx.x;
    const int lane = tid & 31;
    const int wid  = tid >> 5;
    const int wm   = wid >> 2;
    const int wn   = wid & 3;
    const int m0   = blockIdx.y * 128;
    const int n0   = blockIdx.x * 128;
    const int NC   = K >> 5;

    auto issue_stage = [&](int c) {
        const uint32_t sb = smemU + (uint32_t)(c % NSTG) * STAGE;
        const int k0 = c << 5;
#pragma unroll
        for (int i = 0; i < 2; i++) {
            int ch = tid + i * 256;
            int arow = ch >> 2, aseg = ch & 3;
            uint32_t ad = sb + ((uint32_t)arow * LDA + (uint32_t)aseg * 8u) * 2u;
            cp16(ad, Ah + (size_t)(m0 + arow) * K + k0 + aseg * 8);
            cp16(ad + A_BYTES, Al + (size_t)(m0 + arow) * K + k0 + aseg * 8);
        }
#pragma unroll
        for (int i = 0; i < 2; i++) {
            int ch = tid + i * 256;
            int brow = ch >> 4, bseg = ch & 15;
            uint32_t bd = sb + (uint32_t)B_OFF + ((uint32_t)brow * LDB + (uint32_t)bseg * 8u) * 2u;
            cp16(bd, Bh + (size_t)(k0 + brow) * N + n0 + bseg * 8);
            cp16(bd + B_BYTES, Bl + (size_t)(k0 + brow) * N + n0 + bseg * 8);
        }
        cp_commit();
    };

    issue_stage(0);
    issue_stage(1);

    float acc[4][4][4];
#pragma unroll
    for (int mt = 0; mt < 4; mt++)
#pragma unroll
        for (int nt = 0; nt < 4; nt++)
#pragma unroll
            for (int e = 0; e < 4; e++) acc[mt][nt][e] = 0.f;

    const uint32_t aCmp0 = smemU + ((uint32_t)(wm * 64 + (lane & 15)) * LDA +
                                    (uint32_t)(lane >> 4) * 8) * 2u;
    const uint32_t bCmp0 = smemU + (uint32_t)B_OFF +
                           ((uint32_t)(lane & 15) * LDB + (uint32_t)(wn * 32)) * 2u +
                           (uint32_t)(lane >> 4) * 16u;

    for (int c = 0; c < NC; c++) {
        cp_wait<1>();
        __syncthreads();
        if (c + 2 < NC) issue_stage(c + 2);

        const uint32_t so = (uint32_t)(c % NSTG) * STAGE;
        const uint32_t aC = aCmp0 + so;
        const uint32_t bC = bCmp0 + so;
#pragma unroll
        for (int ks = 0; ks < 2; ks++) {
            uint32_t Bhf[4][2], Blf[4][2];
#pragma unroll
            for (int np = 0; np < 2; np++) {
                uint32_t bd = bC + (uint32_t)ks * (16 * LDB * 2) + (uint32_t)np * 32u;
                uint32_t t4[4];
                ldsm_x4_t(t4, bd);
                Bhf[2 * np][0] = t4[0]; Bhf[2 * np][1] = t4[1];
                Bhf[2 * np + 1][0] = t4[2]; Bhf[2 * np + 1][1] = t4[3];
                ldsm_x4_t(t4, bd + B_BYTES);
                Blf[2 * np][0] = t4[0]; Blf[2 * np][1] = t4[1];
                Blf[2 * np + 1][0] = t4[2]; Blf[2 * np + 1][1] = t4[3];
            }
#pragma unroll
            for (int mt = 0; mt < 4; mt++) {
                uint32_t Ahf[4], Alf[4];
                uint32_t ad = aC + (uint32_t)mt * (16 * LDA * 2) + (uint32_t)ks * 32u;
                ldsm_x4(Ahf, ad);
                ldsm_x4(Alf, ad + A_BYTES);
#pragma unroll
                for (int nt = 0; nt < 4; nt++) {
                    mma16816(acc[mt][nt], Ahf, Bhf[nt][0], Bhf[nt][1]);
                    mma16816(acc[mt][nt], Ahf, Blf[nt][0], Blf[nt][1]);
                    mma16816(acc[mt][nt], Alf, Bhf[nt][0], Bhf[nt][1]);
                }
            }
        }
    }

    // -------- epilogue --------
    const int rbase = m0 + wm * 64;
    const int cbase = n0 + wn * 32;
#pragma unroll
    for (int mt = 0; mt < 4; mt++)
#pragma unroll
        for (int nt = 0; nt < 4; nt++) {
#pragma unroll
            for (int half = 0; half < 2; half++) {
                int r = rbase + mt * 16 + (lane >> 2) + half * 8;
                int cc = cbase + nt * 8 + (lane & 3) * 2;
                float2 v;
                v.x = acc[mt][nt][half * 2 + 0];
                v.y = acc[mt][nt][half * 2 + 1];
                if (MODE & MD_BIAS) {
                    float2 bb = *reinterpret_cast<const float2*>(bias + cc);
                    v.x += bb.x; v.y += bb.y;
                }
                if (MODE & MD_RELU) {
                    v.x = fmaxf(v.x, 0.f); v.y = fmaxf(v.y, 0.f);
                }
                if (MODE & MD_RES) {
                    float2 rr = *reinterpret_cast<const float2*>(res + (size_t)r * N + cc);
                    v.x += rr.x; v.y += rr.y;
                }
                if (MODE & MD_SPLIT) {
                    __nv_bfloat16 hx = __float2bfloat16(v.x), hy = __float2bfloat16(v.y);
                    size_t idx = ((size_t)r * N + cc) >> 1;
                    reinterpret_cast<uint32_t*>(Chi)[idx] = pack_bf2(v.x, v.y);
                    reinterpret_cast<uint32_t*>(Clo)[idx] =
                        pack_bf2(v.x - __bfloat162float(hx), v.y - __bfloat162float(hy));
                } else if (MODE & MD_QKV) {
                    // fused QKV -> bf16 hi/lo in [B,H,S,HD]; q pre-scaled.
                    int which = cc >> 10;
                    int c1 = cc & 1023;
                    float* dstf = which == 0 ? C : (which == 1 ? C2 : C3);
                    __nv_bfloat16* dh = reinterpret_cast<__nv_bfloat16*>(dstf);
                    if (which == 0) { v.x *= SCL2; v.y *= SCL2; }
                    int b_ = r >> 11, s_ = r & (Ss - 1);
                    int h_ = c1 >> 6, d_ = c1 & 63;
                    size_t idx = (((size_t)(b_ * Hh + h_) * Ss + s_) * HDd + d_) >> 1;
                    __nv_bfloat16 hx = __float2bfloat16(v.x), hy = __float2bfloat16(v.y);
                    reinterpret_cast<uint32_t*>(dh)[idx] = pack_bf2(v.x, v.y);
                    reinterpret_cast<uint32_t*>(dh + (size_t)Mm * Dd)[idx] =
                        pack_bf2(v.x - __bfloat162float(hx), v.y - __bfloat162float(hy));
                } else {
                    *reinterpret_cast<float2*>(C + (size_t)r * N + cc) = v;
                }
            }
        }
}

// ========================= attention v2 =====================================
// q,k,v pre-split bf16 hi/lo in [B,H,S,64]; q pre-scaled by SCL2.
// CTA = 256 q rows, 8 warps, warp = 32 q rows (2 m16 tiles, shared K/V frags).
// 2-stage cp.async K/V ring (Kh|Kl|Vh|Vl, 64 keys x 72-elem rows).
constexpr int AALD  = 72;
constexpr int AKMAT = 64 * AALD * 2;      // 9216
constexpr int AST   = 4 * AKMAT;          // 36864 per stage
constexpr int AQOFF = 2 * AST;            // 73728
constexpr int AQMAT = 256 * AALD * 2;     // 36864
constexpr int ATT_SMEM = AQOFF + 2 * AQMAT;   // 147456

__global__ void __launch_bounds__(256, 1) attn_mma(
    const __nv_bfloat16* __restrict__ qhp, const __nv_bfloat16* __restrict__ khp,
    const __nv_bfloat16* __restrict__ vhp, __nv_bfloat16* __restrict__ oh,
    __nv_bfloat16* __restrict__ ol)
{
    extern __shared__ char sm[];
    const uint32_t S0 = smem_u32(sm);
    const int tid = threadIdx.x, lane = tid & 31, w = tid >> 5;
    const int bh = blockIdx.y, q0 = blockIdx.x * 256;
    const int b_ = bh >> 4, h_ = bh & 15;
    const size_t LO = (size_t)Mm * Dd;

    const __nv_bfloat16* qbh = qhp + ((size_t)bh * Ss + q0) * HDd;
    const __nv_bfloat16* qbl = qbh + LO;
    const __nv_bfloat16* kbh = khp + (size_t)bh * Ss * HDd;
    const __nv_bfloat16* kbl = kbh + LO;
    const __nv_bfloat16* vbh = vhp + (size_t)bh * Ss * HDd;
    const __nv_bfloat16* vbl = vbh + LO;

    auto issue_kv = [&](int t) {
        uint32_t sb = S0 + (uint32_t)(t & 1) * AST;
        int k0 = t * 64;
#pragma unroll
        for (int i = 0; i < 2; i++) {
            int ch = tid + i * 256;              // 512 chunks per matrix
            int r = ch >> 3, s = ch & 7;
            uint32_t off = (uint32_t)r * 144u + (uint32_t)s * 16u;
            const size_t so_ = (size_t)(k0 + r) * HDd + s * 8;
            cp16(sb + off,             kbh + so_);
            cp16(sb + AKMAT + off,     kbl + so_);
            cp16(sb + 2 * AKMAT + off, vbh + so_);
            cp16(sb + 3 * AKMAT + off, vbl + so_);
        }
        cp_commit();
    };

    // Q staging (one-time) + first K/V stage
    {
#pragma unroll
        for (int i = 0; i < 8; i++) {
            int ch = tid + i * 256;              // 2048 chunks per matrix
            int r = ch >> 3, s = ch & 7;
            uint32_t off = (uint32_t)r * 144u + (uint32_t)s * 16u;
            const size_t so_ = (size_t)r * HDd + s * 8;
            cp16(S0 + AQOFF + off,         qbh + so_);
            cp16(S0 + AQOFF + AQMAT + off, qbl + so_);
        }
        cp_commit();
    }
    issue_kv(0);
    cp_wait<0>();
    __syncthreads();

    // persistent Q fragments: 2 m-tiles x 4 k-steps, hi+lo
    uint32_t Qh[2][4][4], Ql[2][4][4];
#pragma unroll
    for (int mi = 0; mi < 2; mi++) {
        uint32_t base = S0 + AQOFF +
            (((uint32_t)(w * 32 + mi * 16 + (lane & 15))) * AALD +
             (uint32_t)(lane >> 4) * 8u) * 2u;
#pragma unroll
        for (int ks = 0; ks < 4; ks++) {
            ldsm_x4(Qh[mi][ks], base + (uint32_t)ks * 32u);
            ldsm_x4(Ql[mi][ks], base + (uint32_t)AQMAT + (uint32_t)ks * 32u);
        }
    }

    float oa[2][8][4];
#pragma unroll
    for (int mi = 0; mi < 2; mi++)
#pragma unroll
        for (int nt = 0; nt < 8; nt++)
#pragma unroll
            for (int e = 0; e < 4; e++) oa[mi][nt][e] = 0.f;
    float mrow[2][2] = {{-1e30f, -1e30f}, {-1e30f, -1e30f}};
    float lrow[2][2] = {{0.f, 0.f}, {0.f, 0.f}};

    for (int t = 0; t < Ss / 64; t++) {
        if (t > 0) { cp_wait<0>(); __syncthreads(); }
        if (t + 1 < Ss / 64) issue_kv(t + 1);
        const uint32_t sbU = S0 + (uint32_t)(t & 1) * AST;

        // ---- S = Q K^T (3-pass), K frags shared across both m-tiles ----
        float sc[2][8][4];
#pragma unroll
        for (int mi = 0; mi < 2; mi++)
#pragma unroll
            for (int nt = 0; nt < 8; nt++)
#pragma unroll
                for (int e = 0; e < 4; e++) sc[mi][nt][e] = 0.f;

        const uint32_t kfb = sbU + (uint32_t)(lane >> 4) * (uint32_t)AKMAT +
            (((uint32_t)(lane & 7)) * AALD + (uint32_t)((lane >> 3) & 1) * 8u) * 2u;
#pragma unroll
        for (int nt = 0; nt < 8; nt++) {
#pragma unroll
            for (int ks = 0; ks < 4; ks++) {
                uint32_t kf[4];
                ldsm_x4(kf, kfb + ((uint32_t)nt * 8u * AALD + (uint32_t)ks * 16u) * 2u);
#pragma unroll
                for (int mi = 0; mi < 2; mi++) {
                    mma16816(sc[mi][nt], Qh[mi][ks], kf[0], kf[1]);
                    mma16816(sc[mi][nt], Qh[mi][ks], kf[2], kf[3]);
                    mma16816(sc[mi][nt], Ql[mi][ks], kf[0], kf[1]);
                }
            }
        }

        // ---- online softmax per m-tile (log2 domain; q pre-scaled) ----
#pragma unroll
        for (int mi = 0; mi < 2; mi++) {
            float mt0 = sc[mi][0][0], mt1 = sc[mi][0][2];
#pragma unroll
            for (int nt = 0; nt < 8; nt++) {
                mt0 = fmaxf(mt0, fmaxf(sc[mi][nt][0], sc[mi][nt][1]));
                mt1 = fmaxf(mt1, fmaxf(sc[mi][nt][2], sc[mi][nt][3]));
            }
            mt0 = fmaxf(mt0, __shfl_xor_sync(0xffffffffu, mt0, 1));
            mt0 = fmaxf(mt0, __shfl_xor_sync(0xffffffffu, mt0, 2));
            mt1 = fmaxf(mt1, __shfl_xor_sync(0xffffffffu, mt1, 1));
            mt1 = fmaxf(mt1, __shfl_xor_sync(0xffffffffu, mt1, 2));
            float mn0 = fmaxf(mrow[mi][0], mt0), mn1 = fmaxf(mrow[mi][1], mt1);
            float c0 = ex2(mrow[mi][0] - mn0), c1 = ex2(mrow[mi][1] - mn1);
            mrow[mi][0] = mn0; mrow[mi][1] = mn1;

            float ls0 = 0.f, ls1 = 0.f;
#pragma unroll
            for (int nt = 0; nt < 8; nt++) {
                sc[mi][nt][0] = ex2(sc[mi][nt][0] - mn0);
                sc[mi][nt][1] = ex2(sc[mi][nt][1] - mn0);
                sc[mi][nt][2] = ex2(sc[mi][nt][2] - mn1);
                sc[mi][nt][3] = ex2(sc[mi][nt][3] - mn1);
                ls0 += sc[mi][nt][0] + sc[mi][nt][1];
                ls1 += sc[mi][nt][2] + sc[mi][nt][3];
            }
            ls0 += __shfl_xor_sync(0xffffffffu, ls0, 1);
            ls0 += __shfl_xor_sync(0xffffffffu, ls0, 2);
            ls1 += __shfl_xor_sync(0xffffffffu, ls1, 1);
            ls1 += __shfl_xor_sync(0xffffffffu, ls1, 2);
            lrow[mi][0] = lrow[mi][0] * c0 + ls0;
            lrow[mi][1] = lrow[mi][1] * c1 + ls1;
#pragma unroll
            for (int nt = 0; nt < 8; nt++) {
                oa[mi][nt][0] *= c0; oa[mi][nt][1] *= c0;
                oa[mi][nt][2] *= c1; oa[mi][nt][3] *= c1;
            }
        }

        // ---- O += P V (3-pass), V frags shared across both m-tiles ----
        const uint32_t vfb = sbU + 2u * (uint32_t)AKMAT +
            (uint32_t)(lane >> 4) * (uint32_t)AKMAT +
            ((uint32_t)(lane & 15)) * (uint32_t)AALD * 2u;
#pragma unroll
        for (int kk = 0; kk < 4; kk++) {
            uint32_t Ph[2][4], Pl[2][4];
#pragma unroll
            for (int mi = 0; mi < 2; mi++) {
#pragma unroll
                for (int half = 0; half < 2; half++) {
                    float p0 = sc[mi][2 * kk + half][0], p1 = sc[mi][2 * kk + half][1];
                    float p2 = sc[mi][2 * kk + half][2], p3 = sc[mi][2 * kk + half][3];
                    __nv_bfloat16 h0 = __float2bfloat16(p0), h1 = __float2bfloat16(p1);
                    __nv_bfloat16 h2 = __float2bfloat16(p2), h3 = __float2bfloat16(p3);
                    Ph[mi][2 * half + 0] = pack_bf2(p0, p1);
                    Ph[mi][2 * half + 1] = pack_bf2(p2, p3);
                    Pl[mi][2 * half + 0] = pack_bf2(p0 - __bfloat162float(h0),
                                                    p1 - __bfloat162float(h1));
                    Pl[mi][2 * half + 1] = pack_bf2(p2 - __bfloat162float(h2),
                                                    p3 - __bfloat162float(h3));
                }
            }
#pragma unroll
            for (int nt = 0; nt < 8; nt++) {
                uint32_t vf[4];
                ldsm_x4_t(vf, vfb + ((uint32_t)kk * 16u * AALD + (uint32_t)nt * 8u) * 2u);
#pragma unroll
                for (int mi = 0; mi < 2; mi++) {
                    mma16816(oa[mi][nt], Ph[mi], vf[0], vf[1]);
                    mma16816(oa[mi][nt], Ph[mi], vf[2], vf[3]);
                    mma16816(oa[mi][nt], Pl[mi], vf[0], vf[1]);
                }
            }
        }
    }

    // ---- epilogue: normalize, split to hi/lo bf16, write [B,S,D] ----
#pragma unroll
    for (int mi = 0; mi < 2; mi++) {
        float il0 = 1.0f / lrow[mi][0], il1 = 1.0f / lrow[mi][1];
        int sr0 = q0 + w * 32 + mi * 16 + (lane >> 2);
        int sr1 = sr0 + 8;
#pragma unroll
        for (int nt = 0; nt < 8; nt++) {
            int col = h_ * HDd + nt * 8 + (lane & 3) * 2;
            float a0 = oa[mi][nt][0] * il0, a1 = oa[mi][nt][1] * il0;
            float a2 = oa[mi][nt][2] * il1, a3 = oa[mi][nt][3] * il1;
            __nv_bfloat16 h0 = __float2bfloat16(a0), h1 = __float2bfloat16(a1);
            __nv_bfloat16 h2 = __float2bfloat16(a2), h3 = __float2bfloat16(a3);
            size_t i0 = (((size_t)(b_ * Ss + sr0)) * Dd + col) >> 1;
            size_t i1 = (((size_t)(b_ * Ss + sr1)) * Dd + col) >> 1;
            reinterpret_cast<uint32_t*>(oh)[i0] = pack_bf2(a0, a1);
            reinterpret_cast<uint32_t*>(ol)[i0] =
                pack_bf2(a0 - __bfloat162float(h0), a1 - __bfloat162float(h1));
            reinterpret_cast<uint32_t*>(oh)[i1] = pack_bf2(a2, a3);
            reinterpret_cast<uint32_t*>(ol)[i1] =
                pack_bf2(a2 - __bfloat162float(h2), a3 - __bfloat162float(h3));
        }
    }
}

// ========================= launch ===========================
extern "C" void kernel_launch(void* const* d_in, const int* in_sizes, int n_in,
                              void* d_out, int out_size)
{
    const float* x     = (const float*)d_in[0];
    const float* ln1_g = (const float*)d_in[1];
    const float* ln1_b = (const float*)d_in[2];
    const float* ln2_g = (const float*)d_in[3];
    const float* ln2_b = (const float*)d_in[4];
    const float* Wq    = (const float*)d_in[5];
    const float* Wk    = (const float*)d_in[6];
    const float* Wv    = (const float*)d_in[7];
    const float* Wo    = (const float*)d_in[8];
    const float* W1    = (const float*)d_in[9];
    const float* b1    = (const float*)d_in[10];
    const float* W2    = (const float*)d_in[11];
    const float* b2    = (const float*)d_in[12];
    float* out = (float*)d_out;

    float *x2;
    __nv_bfloat16 *qh, *kh, *vh, *xh, *xl, *oh, *ol, *fh, *fl, *wh, *wl;
    cudaGetSymbolAddress((void**)&x2,  g_x2);
    cudaGetSymbolAddress((void**)&qh,  g_qh);
    cudaGetSymbolAddress((void**)&kh,  g_kh);
    cudaGetSymbolAddress((void**)&vh,  g_vh);
    cudaGetSymbolAddress((void**)&xh,  g_xh);
    cudaGetSymbolAddress((void**)&xl,  g_xl);
    cudaGetSymbolAddress((void**)&oh,  g_oh);
    cudaGetSymbolAddress((void**)&ol,  g_ol);
    cudaGetSymbolAddress((void**)&fh,  g_fh);
    cudaGetSymbolAddress((void**)&fl,  g_fl);
    cudaGetSymbolAddress((void**)&wh,  g_wh);
    cudaGetSymbolAddress((void**)&wl,  g_wl);

    cudaFuncSetAttribute(gemm_mma<MD_QKV>, cudaFuncAttributeMaxDynamicSharedMemorySize, GEMM_SMEM);
    cudaFuncSetAttribute(gemm_mma<MD_RES>, cudaFuncAttributeMaxDynamicSharedMemorySize, GEMM_SMEM);
    cudaFuncSetAttribute(gemm_mma<MD_BIAS | MD_RELU | MD_SPLIT>, cudaFuncAttributeMaxDynamicSharedMemorySize, GEMM_SMEM);
    cudaFuncSetAttribute(gemm_mma<MD_BIAS | MD_RELU | MD_RES>, cudaFuncAttributeMaxDynamicSharedMemorySize, GEMM_SMEM);
    cudaFuncSetAttribute(attn_mma, cudaFuncAttributeMaxDynamicSharedMemorySize, ATT_SMEM);

    dim3 blk(256);
    dim3 gQKV(3072 / 128, Mm / 128);
    dim3 gD(Dd / 128, Mm / 128);
    dim3 gF(FFf / 128, Mm / 128);
    const int QD4 = Dd * Dd / 4, FD4 = Dd * FFf / 4;

    split_strided_kernel<<<QD4 / 256, blk>>>(Wq, wh + WQKV, wl + WQKV, 0,    QD4);
    split_strided_kernel<<<QD4 / 256, blk>>>(Wk, wh + WQKV, wl + WQKV, 1024, QD4);
    split_strided_kernel<<<QD4 / 256, blk>>>(Wv, wh + WQKV, wl + WQKV, 2048, QD4);
    split_kernel<<<QD4 / 256, blk>>>(Wo, wh + WOO, wl + WOO, QD4);
    split_kernel<<<FD4 / 256, blk>>>(W1, wh + W1O, wl + W1O, FD4);
    split_kernel<<<FD4 / 256, blk>>>(W2, wh + W2O, wl + W2O, FD4);

    // h = LN1(x) -> hi/lo
    ln_split_kernel<<<Mm, blk>>>(x, ln1_g, ln1_b, xh, xl);
    // q|k|v = h @ Wqkv -> bf16 hi/lo [B,H,S,HD] (q pre-scaled by SCL2)
    gemm_mma<MD_QKV><<<gQKV, blk, GEMM_SMEM>>>(xh, xl, wh + WQKV, wl + WQKV,
        nullptr, nullptr, (float*)qh, (float*)kh, (float*)vh, nullptr, nullptr, 3072, Dd);
    // attention -> hi/lo o
    attn_mma<<<dim3(Ss / 256, Bb * Hh), blk, ATT_SMEM>>>(qh, kh, vh, oh, ol);
    // x2 = x + o @ Wo
    gemm_mma<MD_RES><<<gD, blk, GEMM_SMEM>>>(oh, ol, wh + WOO, wl + WOO,
        nullptr, x, x2, nullptr, nullptr, nullptr, nullptr, Dd, Dd);
    // h = LN2(x2) -> hi/lo
    ln_split_kernel<<<Mm, blk>>>(x2, ln2_g, ln2_b, xh, xl);
    // ff1 = relu(h @ W1 + b1) -> hi/lo
    gemm_mma<MD_BIAS | MD_RELU | MD_SPLIT><<<gF, blk, GEMM_SMEM>>>(xh, xl,
        wh + W1O, wl + W1O, b1, nullptr, nullptr, nullptr, nullptr, fh, fl, FFf, Dd);
    // out = x2 + relu(ff1 @ W2 + b2)
    gemm_mma<MD_BIAS | MD_RELU | MD_RES><<<gD, blk, GEMM_SMEM>>>(fh, fl,
        wh + W2O, wl + W2O, b2, x2, out, nullptr, nullptr, nullptr, nullptr, Dd, FFf);
}

// round 14
// speedup vs baseline: 3.5833x; 1.2570x over previous
#include <cuda_runtime.h>
#include <cuda_fp16.h>
#include <cstdint>

// ---------------------------------------------------------------------------
// TransformerLayer: B=4, S=2048, D=1024, H=16, HD=64, FF=4096, fp32 I/O.
// Round 13: 2-pass split-fp16 GEMMs (A = fp16 hi+lo ~22-bit, B = single rn
// fp16, D = Ah*B + Al*B). 33% fewer MMAs, 17% less smem traffic vs 3-pass
// bf16. Attention keeps 3-pass structure, retyped fp16. Layout/pipeline
// unchanged from R11/R12 (128x128 tile, NSTG=3, 2 CTAs/SM, fused QKV).
// ---------------------------------------------------------------------------

constexpr int Bb = 4, Ss = 2048, Dd = 1024, Hh = 16, HDd = 64, FFf = 4096;
constexpr int Mm = Bb * Ss;            // 8192 rows
constexpr float EPS = 1e-5f;
constexpr float SCL2 = 0.125f * 1.4426950408889634f;

// fp32 scratch
__device__ float g_x2 [Mm * Dd];
// fp16 hi/lo activation scratch (q/k/v hold hi then lo, each Mm*Dd)
__device__ __half g_qh[2 * (size_t)Mm * Dd];
__device__ __half g_kh[2 * (size_t)Mm * Dd];
__device__ __half g_vh[2 * (size_t)Mm * Dd];
__device__ __half g_xh[(size_t)Mm * Dd];
__device__ __half g_xl[(size_t)Mm * Dd];
__device__ __half g_oh[(size_t)Mm * Dd];
__device__ __half g_ol[(size_t)Mm * Dd];
__device__ __half g_fh[(size_t)Mm * FFf];
__device__ __half g_fl[(size_t)Mm * FFf];
// fp16 weights (single, rn). Layout: [0,3M) fused Wqkv [1024,3072]; Wo, W1, W2.
constexpr size_t WQKV = 0, WOO = 3u << 20;
constexpr size_t W1O = 4u << 20, W2O = 8u << 20, WTOT = 12u << 20;
__device__ __half g_w[WTOT];

// ========================= small PTX helpers ===========================
__device__ __forceinline__ uint32_t smem_u32(const void* p) {
    uint32_t a;
    asm("{ .reg .u64 t; cvta.to.shared.u64 t, %1; cvt.u32.u64 %0, t; }" : "=r"(a) : "l"(p));
    return a;
}
__device__ __forceinline__ void ldsm_x4(uint32_t (&r)[4], uint32_t addr) {
    asm volatile("ldmatrix.sync.aligned.m8n8.x4.shared.b16 {%0,%1,%2,%3}, [%4];"
        : "=r"(r[0]), "=r"(r[1]), "=r"(r[2]), "=r"(r[3]) : "r"(addr));
}
__device__ __forceinline__ void ldsm_x4_t(uint32_t (&r)[4], uint32_t addr) {
    asm volatile("ldmatrix.sync.aligned.m8n8.x4.trans.shared.b16 {%0,%1,%2,%3}, [%4];"
        : "=r"(r[0]), "=r"(r[1]), "=r"(r[2]), "=r"(r[3]) : "r"(addr));
}
__device__ __forceinline__ void mma_h(float (&c)[4], const uint32_t (&a)[4],
                                      uint32_t b0, uint32_t b1) {
    asm volatile("mma.sync.aligned.m16n8k16.row.col.f32.f16.f16.f32 "
        "{%0,%1,%2,%3}, {%4,%5,%6,%7}, {%8,%9}, {%0,%1,%2,%3};"
        : "+f"(c[0]), "+f"(c[1]), "+f"(c[2]), "+f"(c[3])
        : "r"(a[0]), "r"(a[1]), "r"(a[2]), "r"(a[3]), "r"(b0), "r"(b1));
}
__device__ __forceinline__ uint32_t pack_h2(float a, float b) {
    __half2 h = __floats2half2_rn(a, b);
    return *reinterpret_cast<uint32_t*>(&h);
}
__device__ __forceinline__ float ex2(float x) {
    float y;
    asm("ex2.approx.ftz.f32 %0, %1;" : "=f"(y) : "f"(x));
    return y;
}
__device__ __forceinline__ void cp16(uint32_t dst, const void* src) {
    asm volatile("cp.async.cg.shared.global [%0], [%1], 16;" :: "r"(dst), "l"(src) : "memory");
}
__device__ __forceinline__ void cp_commit() { asm volatile("cp.async.commit_group;" ::: "memory"); }
template <int N>
__device__ __forceinline__ void cp_wait() {
    asm volatile("cp.async.wait_group %0;" :: "n"(N) : "memory");
}

// ========================= LayerNorm (writes hi/lo fp16) ====================
__global__ void __launch_bounds__(256) ln_split_kernel(
    const float* __restrict__ x, const float* __restrict__ g,
    const float* __restrict__ b, __half* __restrict__ oh,
    __half* __restrict__ ol)
{
    int row = blockIdx.x;
    int t = threadIdx.x;
    const float4 v = reinterpret_cast<const float4*>(x + (size_t)row * Dd)[t];
    float s  = v.x + v.y + v.z + v.w;
    float ss = v.x * v.x + v.y * v.y + v.z * v.z + v.w * v.w;
#pragma unroll
    for (int o = 16; o > 0; o >>= 1) {
        s  += __shfl_xor_sync(0xffffffffu, s,  o);
        ss += __shfl_xor_sync(0xffffffffu, ss, o);
    }
    __shared__ float red[16];
    int w = t >> 5;
    if ((t & 31) == 0) { red[w] = s; red[8 + w] = ss; }
    __syncthreads();
    float st = 0.f, sst = 0.f;
#pragma unroll
    for (int i = 0; i < 8; i++) { st += red[i]; sst += red[8 + i]; }
    float mu  = st  * (1.0f / Dd);
    float var = sst * (1.0f / Dd) - mu * mu;
    float inv = rsqrtf(var + EPS);
    float4 gg = reinterpret_cast<const float4*>(g)[t];
    float4 bb = reinterpret_cast<const float4*>(b)[t];
    float f[4];
    f[0] = (v.x - mu) * inv * gg.x + bb.x;
    f[1] = (v.y - mu) * inv * gg.y + bb.y;
    f[2] = (v.z - mu) * inv * gg.z + bb.z;
    f[3] = (v.w - mu) * inv * gg.w + bb.w;
    uint32_t hw[2], lw[2];
#pragma unroll
    for (int e = 0; e < 2; e++) {
        float a = f[2 * e], c = f[2 * e + 1];
        __half ha = __float2half_rn(a), hc = __float2half_rn(c);
        hw[e] = pack_h2(a, c);
        lw[e] = pack_h2(a - __half2float(ha), c - __half2float(hc));
    }
    size_t idx = (size_t)row * (Dd / 4) + t;
    reinterpret_cast<uint2*>(oh)[idx] = make_uint2(hw[0], hw[1]);
    reinterpret_cast<uint2*>(ol)[idx] = make_uint2(lw[0], lw[1]);
}

// ========================= weight fp32 -> single fp16 =======================
__global__ void __launch_bounds__(256) wsplit_kernel(
    const float* __restrict__ x, __half* __restrict__ w, int n4)
{
    int i = blockIdx.x * 256 + threadIdx.x;
    if (i >= n4) return;
    float4 v = reinterpret_cast<const float4*>(x)[i];
    reinterpret_cast<uint2*>(w)[i] =
        make_uint2(pack_h2(v.x, v.y), pack_h2(v.z, v.w));
}

// strided: src [K,1024] -> dst rows stride 3072, column offset coloff
__global__ void __launch_bounds__(256) wsplit_strided_kernel(
    const float* __restrict__ x, __half* __restrict__ w, int coloff, int n4)
{
    int i = blockIdx.x * 256 + threadIdx.x;
    if (i >= n4) return;
    float4 v = reinterpret_cast<const float4*>(x)[i];
    int row = (i * 4) >> 10;
    int col = (i * 4) & 1023;
    size_t di = ((size_t)row * 3072 + coloff + col) >> 2;
    reinterpret_cast<uint2*>(w)[di] =
        make_uint2(pack_h2(v.x, v.y), pack_h2(v.z, v.w));
}

// ========================= cp.async 2-pass split-fp16 GEMM ==================
// C[M,N] = A[M,K] @ W[K,N]; A fp16 hi/lo, W single fp16. D = Ah*W + Al*W.
// CTA tile 128x128x32; 8 warps 2(m)x4(n), warp 64x32. NSTG=3, one barrier
// per chunk, 2 CTAs/SM.
constexpr int MD_BIAS = 1, MD_RELU = 2, MD_RES = 4, MD_QKV = 8, MD_SPLIT = 16;

constexpr int NSTG = 3;
constexpr int LDA = 40;                         // 80 B rows
constexpr int LDB = 136;                        // 272 B rows
constexpr int A_BYTES = 128 * LDA * 2;          // 10240 per matrix
constexpr int B_BYTES = 32 * LDB * 2;           // 8704 (single matrix)
constexpr int B_OFF   = 2 * A_BYTES;            // 20480
constexpr int STAGE   = B_OFF + B_BYTES;        // 29184
constexpr int GEMM_SMEM = NSTG * STAGE;         // 87552 (2 CTAs = 175104)

template <int MODE>
__global__ void __launch_bounds__(256, 2) gemm_mma(
    const __half* __restrict__ Ah, const __half* __restrict__ Al,
    const __half* __restrict__ Bw,
    const float* __restrict__ bias, const float* __restrict__ res,
    float* __restrict__ C, float* __restrict__ C2, float* __restrict__ C3,
    __half* __restrict__ Chi, __half* __restrict__ Clo,
    int N, int K)
{
    extern __shared__ char dsm[];
    const uint32_t smemU = smem_u32(dsm);

    const int tid  = threadIdx.x;
    const int lane = tid & 31;
    const int wid  = tid >> 5;
    const int wm   = wid >> 2;
    const int wn   = wid & 3;
    const int m0   = blockIdx.y * 128;
    const int n0   = blockIdx.x * 128;
    const int NC   = K >> 5;

    auto issue_stage = [&](int c) {
        const uint32_t sb = smemU + (uint32_t)(c % NSTG) * STAGE;
        const int k0 = c << 5;
#pragma unroll
        for (int i = 0; i < 2; i++) {
            int ch = tid + i * 256;
            int arow = ch >> 2, aseg = ch & 3;
            uint32_t ad = sb + ((uint32_t)arow * LDA + (uint32_t)aseg * 8u) * 2u;
            cp16(ad, Ah + (size_t)(m0 + arow) * K + k0 + aseg * 8);
            cp16(ad + A_BYTES, Al + (size_t)(m0 + arow) * K + k0 + aseg * 8);
        }
#pragma unroll
        for (int i = 0; i < 2; i++) {
            int ch = tid + i * 256;
            int brow = ch >> 4, bseg = ch & 15;
            uint32_t bd = sb + (uint32_t)B_OFF + ((uint32_t)brow * LDB + (uint32_t)bseg * 8u) * 2u;
            cp16(bd, Bw + (size_t)(k0 + brow) * N + n0 + bseg * 8);
        }
        cp_commit();
    };

    issue_stage(0);
    issue_stage(1);

    float acc[4][4][4];
#pragma unroll
    for (int mt = 0; mt < 4; mt++)
#pragma unroll
        for (int nt = 0; nt < 4; nt++)
#pragma unroll
            for (int e = 0; e < 4; e++) acc[mt][nt][e] = 0.f;

    const uint32_t aCmp0 = smemU + ((uint32_t)(wm * 64 + (lane & 15)) * LDA +
                                    (uint32_t)(lane >> 4) * 8) * 2u;
    const uint32_t bCmp0 = smemU + (uint32_t)B_OFF +
                           ((uint32_t)(lane & 15) * LDB + (uint32_t)(wn * 32)) * 2u +
                           (uint32_t)(lane >> 4) * 16u;

    for (int c = 0; c < NC; c++) {
        cp_wait<1>();
        __syncthreads();
        if (c + 2 < NC) issue_stage(c + 2);

        const uint32_t so = (uint32_t)(c % NSTG) * STAGE;
        const uint32_t aC = aCmp0 + so;
        const uint32_t bC = bCmp0 + so;
#pragma unroll
        for (int ks = 0; ks < 2; ks++) {
            uint32_t Bf[4][2];
#pragma unroll
            for (int np = 0; np < 2; np++) {
                uint32_t bd = bC + (uint32_t)ks * (16 * LDB * 2) + (uint32_t)np * 32u;
                uint32_t t4[4];
                ldsm_x4_t(t4, bd);
                Bf[2 * np][0] = t4[0]; Bf[2 * np][1] = t4[1];
                Bf[2 * np + 1][0] = t4[2]; Bf[2 * np + 1][1] = t4[3];
            }
#pragma unroll
            for (int mt = 0; mt < 4; mt++) {
                uint32_t Ahf[4], Alf[4];
                uint32_t ad = aC + (uint32_t)mt * (16 * LDA * 2) + (uint32_t)ks * 32u;
                ldsm_x4(Ahf, ad);
                ldsm_x4(Alf, ad + A_BYTES);
#pragma unroll
                for (int nt = 0; nt < 4; nt++) {
                    mma_h(acc[mt][nt], Ahf, Bf[nt][0], Bf[nt][1]);
                    mma_h(acc[mt][nt], Alf, Bf[nt][0], Bf[nt][1]);
                }
            }
        }
    }

    // -------- epilogue --------
    const int rbase = m0 + wm * 64;
    const int cbase = n0 + wn * 32;
#pragma unroll
    for (int mt = 0; mt < 4; mt++)
#pragma unroll
        for (int nt = 0; nt < 4; nt++) {
#pragma unroll
            for (int half = 0; half < 2; half++) {
                int r = rbase + mt * 16 + (lane >> 2) + half * 8;
                int cc = cbase + nt * 8 + (lane & 3) * 2;
                float2 v;
                v.x = acc[mt][nt][half * 2 + 0];
                v.y = acc[mt][nt][half * 2 + 1];
                if (MODE & MD_BIAS) {
                    float2 bb = *reinterpret_cast<const float2*>(bias + cc);
                    v.x += bb.x; v.y += bb.y;
                }
                if (MODE & MD_RELU) {
                    v.x = fmaxf(v.x, 0.f); v.y = fmaxf(v.y, 0.f);
                }
                if (MODE & MD_RES) {
                    float2 rr = *reinterpret_cast<const float2*>(res + (size_t)r * N + cc);
                    v.x += rr.x; v.y += rr.y;
                }
                if (MODE & MD_SPLIT) {
                    __half hx = __float2half_rn(v.x), hy = __float2half_rn(v.y);
                    size_t idx = ((size_t)r * N + cc) >> 1;
                    reinterpret_cast<uint32_t*>(Chi)[idx] = pack_h2(v.x, v.y);
                    reinterpret_cast<uint32_t*>(Clo)[idx] =
                        pack_h2(v.x - __half2float(hx), v.y - __half2float(hy));
                } else if (MODE & MD_QKV) {
                    // fused QKV -> fp16 hi/lo in [B,H,S,HD]; q pre-scaled.
                    int which = cc >> 10;
                    int c1 = cc & 1023;
                    float* dstf = which == 0 ? C : (which == 1 ? C2 : C3);
                    __half* dh = reinterpret_cast<__half*>(dstf);
                    if (which == 0) { v.x *= SCL2; v.y *= SCL2; }
                    int b_ = r >> 11, s_ = r & (Ss - 1);
                    int h_ = c1 >> 6, d_ = c1 & 63;
                    size_t idx = (((size_t)(b_ * Hh + h_) * Ss + s_) * HDd + d_) >> 1;
                    __half hx = __float2half_rn(v.x), hy = __float2half_rn(v.y);
                    reinterpret_cast<uint32_t*>(dh)[idx] = pack_h2(v.x, v.y);
                    reinterpret_cast<uint32_t*>(dh + (size_t)Mm * Dd)[idx] =
                        pack_h2(v.x - __half2float(hx), v.y - __half2float(hy));
                } else {
                    *reinterpret_cast<float2*>(C + (size_t)r * N + cc) = v;
                }
            }
        }
}

// ========================= attention (R12 structure, fp16) ==================
// q,k,v fp16 hi/lo in [B,H,S,64]; q pre-scaled by SCL2.
// CTA = 256 q rows, 8 warps, warp = 32 q rows (2 m16 tiles, shared K/V frags).
// 2-stage cp.async K/V ring (Kh|Kl|Vh|Vl, 64 keys x 72-elem rows).
constexpr int AALD  = 72;
constexpr int AKMAT = 64 * AALD * 2;      // 9216
constexpr int AST   = 4 * AKMAT;          // 36864 per stage
constexpr int AQOFF = 2 * AST;            // 73728
constexpr int AQMAT = 256 * AALD * 2;     // 36864
constexpr int ATT_SMEM = AQOFF + 2 * AQMAT;   // 147456

__global__ void __launch_bounds__(256, 1) attn_mma(
    const __half* __restrict__ qhp, const __half* __restrict__ khp,
    const __half* __restrict__ vhp, __half* __restrict__ oh,
    __half* __restrict__ ol)
{
    extern __shared__ char sm[];
    const uint32_t S0 = smem_u32(sm);
    const int tid = threadIdx.x, lane = tid & 31, w = tid >> 5;
    const int bh = blockIdx.y, q0 = blockIdx.x * 256;
    const int b_ = bh >> 4, h_ = bh & 15;
    const size_t LO = (size_t)Mm * Dd;

    const __half* qbh = qhp + ((size_t)bh * Ss + q0) * HDd;
    const __half* kbh = khp + (size_t)bh * Ss * HDd;
    const __half* vbh = vhp + (size_t)bh * Ss * HDd;

    auto issue_kv = [&](int t) {
        uint32_t sb = S0 + (uint32_t)(t & 1) * AST;
        int k0 = t * 64;
#pragma unroll
        for (int i = 0; i < 2; i++) {
            int ch = tid + i * 256;
            int r = ch >> 3, s = ch & 7;
            uint32_t off = (uint32_t)r * 144u + (uint32_t)s * 16u;
            const size_t so_ = (size_t)(k0 + r) * HDd + s * 8;
            cp16(sb + off,             kbh + so_);
            cp16(sb + AKMAT + off,     kbh + LO + so_);
            cp16(sb + 2 * AKMAT + off, vbh + so_);
            cp16(sb + 3 * AKMAT + off, vbh + LO + so_);
        }
        cp_commit();
    };

    {
#pragma unroll
        for (int i = 0; i < 8; i++) {
            int ch = tid + i * 256;
            int r = ch >> 3, s = ch & 7;
            uint32_t off = (uint32_t)r * 144u + (uint32_t)s * 16u;
            const size_t so_ = (size_t)r * HDd + s * 8;
            cp16(S0 + AQOFF + off,         qbh + so_);
            cp16(S0 + AQOFF + AQMAT + off, qbh + LO + so_);
        }
        cp_commit();
    }
    issue_kv(0);
    cp_wait<0>();
    __syncthreads();

    uint32_t Qh[2][4][4], Ql[2][4][4];
#pragma unroll
    for (int mi = 0; mi < 2; mi++) {
        uint32_t base = S0 + AQOFF +
            (((uint32_t)(w * 32 + mi * 16 + (lane & 15))) * AALD +
             (uint32_t)(lane >> 4) * 8u) * 2u;
#pragma unroll
        for (int ks = 0; ks < 4; ks++) {
            ldsm_x4(Qh[mi][ks], base + (uint32_t)ks * 32u);
            ldsm_x4(Ql[mi][ks], base + (uint32_t)AQMAT + (uint32_t)ks * 32u);
        }
    }

    float oa[2][8][4];
#pragma unroll
    for (int mi = 0; mi < 2; mi++)
#pragma unroll
        for (int nt = 0; nt < 8; nt++)
#pragma unroll
            for (int e = 0; e < 4; e++) oa[mi][nt][e] = 0.f;
    float mrow[2][2] = {{-1e30f, -1e30f}, {-1e30f, -1e30f}};
    float lrow[2][2] = {{0.f, 0.f}, {0.f, 0.f}};

    for (int t = 0; t < Ss / 64; t++) {
        if (t > 0) { cp_wait<0>(); __syncthreads(); }
        if (t + 1 < Ss / 64) issue_kv(t + 1);
        const uint32_t sbU = S0 + (uint32_t)(t & 1) * AST;

        float sc[2][8][4];
#pragma unroll
        for (int mi = 0; mi < 2; mi++)
#pragma unroll
            for (int nt = 0; nt < 8; nt++)
#pragma unroll
                for (int e = 0; e < 4; e++) sc[mi][nt][e] = 0.f;

        const uint32_t kfb = sbU + (uint32_t)(lane >> 4) * (uint32_t)AKMAT +
            (((uint32_t)(lane & 7)) * AALD + (uint32_t)((lane >> 3) & 1) * 8u) * 2u;
#pragma unroll
        for (int nt = 0; nt < 8; nt++) {
#pragma unroll
            for (int ks = 0; ks < 4; ks++) {
                uint32_t kf[4];
                ldsm_x4(kf, kfb + ((uint32_t)nt * 8u * AALD + (uint32_t)ks * 16u) * 2u);
#pragma unroll
                for (int mi = 0; mi < 2; mi++) {
                    mma_h(sc[mi][nt], Qh[mi][ks], kf[0], kf[1]);
                    mma_h(sc[mi][nt], Qh[mi][ks], kf[2], kf[3]);
                    mma_h(sc[mi][nt], Ql[mi][ks], kf[0], kf[1]);
                }
            }
        }

#pragma unroll
        for (int mi = 0; mi < 2; mi++) {
            float mt0 = sc[mi][0][0], mt1 = sc[mi][0][2];
#pragma unroll
            for (int nt = 0; nt < 8; nt++) {
                mt0 = fmaxf(mt0, fmaxf(sc[mi][nt][0], sc[mi][nt][1]));
                mt1 = fmaxf(mt1, fmaxf(sc[mi][nt][2], sc[mi][nt][3]));
            }
            mt0 = fmaxf(mt0, __shfl_xor_sync(0xffffffffu, mt0, 1));
            mt0 = fmaxf(mt0, __shfl_xor_sync(0xffffffffu, mt0, 2));
            mt1 = fmaxf(mt1, __shfl_xor_sync(0xffffffffu, mt1, 1));
            mt1 = fmaxf(mt1, __shfl_xor_sync(0xffffffffu, mt1, 2));
            float mn0 = fmaxf(mrow[mi][0], mt0), mn1 = fmaxf(mrow[mi][1], mt1);
            float c0 = ex2(mrow[mi][0] - mn0), c1 = ex2(mrow[mi][1] - mn1);
            mrow[mi][0] = mn0; mrow[mi][1] = mn1;

            float ls0 = 0.f, ls1 = 0.f;
#pragma unroll
            for (int nt = 0; nt < 8; nt++) {
                sc[mi][nt][0] = ex2(sc[mi][nt][0] - mn0);
                sc[mi][nt][1] = ex2(sc[mi][nt][1] - mn0);
                sc[mi][nt][2] = ex2(sc[mi][nt][2] - mn1);
                sc[mi][nt][3] = ex2(sc[mi][nt][3] - mn1);
                ls0 += sc[mi][nt][0] + sc[mi][nt][1];
                ls1 += sc[mi][nt][2] + sc[mi][nt][3];
            }
            ls0 += __shfl_xor_sync(0xffffffffu, ls0, 1);
            ls0 += __shfl_xor_sync(0xffffffffu, ls0, 2);
            ls1 += __shfl_xor_sync(0xffffffffu, ls1, 1);
            ls1 += __shfl_xor_sync(0xffffffffu, ls1, 2);
            lrow[mi][0] = lrow[mi][0] * c0 + ls0;
            lrow[mi][1] = lrow[mi][1] * c1 + ls1;
#pragma unroll
            for (int nt = 0; nt < 8; nt++) {
                oa[mi][nt][0] *= c0; oa[mi][nt][1] *= c0;
                oa[mi][nt][2] *= c1; oa[mi][nt][3] *= c1;
            }
        }

        const uint32_t vfb = sbU + 2u * (uint32_t)AKMAT +
            (uint32_t)(lane >> 4) * (uint32_t)AKMAT +
            ((uint32_t)(lane & 15)) * (uint32_t)AALD * 2u;
#pragma unroll
        for (int kk = 0; kk < 4; kk++) {
            uint32_t Ph[2][4], Pl[2][4];
#pragma unroll
            for (int mi = 0; mi < 2; mi++) {
#pragma unroll
                for (int half = 0; half < 2; half++) {
                    float p0 = sc[mi][2 * kk + half][0], p1 = sc[mi][2 * kk + half][1];
                    float p2 = sc[mi][2 * kk + half][2], p3 = sc[mi][2 * kk + half][3];
                    __half h0 = __float2half_rn(p0), h1 = __float2half_rn(p1);
                    __half h2 = __float2half_rn(p2), h3 = __float2half_rn(p3);
                    Ph[mi][2 * half + 0] = pack_h2(p0, p1);
                    Ph[mi][2 * half + 1] = pack_h2(p2, p3);
                    Pl[mi][2 * half + 0] = pack_h2(p0 - __half2float(h0),
                                                   p1 - __half2float(h1));
                    Pl[mi][2 * half + 1] = pack_h2(p2 - __half2float(h2),
                                                   p3 - __half2float(h3));
                }
            }
#pragma unroll
            for (int nt = 0; nt < 8; nt++) {
                uint32_t vf[4];
                ldsm_x4_t(vf, vfb + ((uint32_t)kk * 16u * AALD + (uint32_t)nt * 8u) * 2u);
#pragma unroll
                for (int mi = 0; mi < 2; mi++) {
                    mma_h(oa[mi][nt], Ph[mi], vf[0], vf[1]);
                    mma_h(oa[mi][nt], Ph[mi], vf[2], vf[3]);
                    mma_h(oa[mi][nt], Pl[mi], vf[0], vf[1]);
                }
            }
        }
    }

    // ---- epilogue: normalize, split to hi/lo fp16, write [B,S,D] ----
#pragma unroll
    for (int mi = 0; mi < 2; mi++) {
        float il0 = 1.0f / lrow[mi][0], il1 = 1.0f / lrow[mi][1];
        int sr0 = q0 + w * 32 + mi * 16 + (lane >> 2);
        int sr1 = sr0 + 8;
#pragma unroll
        for (int nt = 0; nt < 8; nt++) {
            int col = h_ * HDd + nt * 8 + (lane & 3) * 2;
            float a0 = oa[mi][nt][0] * il0, a1 = oa[mi][nt][1] * il0;
            float a2 = oa[mi][nt][2] * il1, a3 = oa[mi][nt][3] * il1;
            __half h0 = __float2half_rn(a0), h1 = __float2half_rn(a1);
            __half h2 = __float2half_rn(a2), h3 = __float2half_rn(a3);
            size_t i0 = (((size_t)(b_ * Ss + sr0)) * Dd + col) >> 1;
            size_t i1 = (((size_t)(b_ * Ss + sr1)) * Dd + col) >> 1;
            reinterpret_cast<uint32_t*>(oh)[i0] = pack_h2(a0, a1);
            reinterpret_cast<uint32_t*>(ol)[i0] =
                pack_h2(a0 - __half2float(h0), a1 - __half2float(h1));
            reinterpret_cast<uint32_t*>(oh)[i1] = pack_h2(a2, a3);
            reinterpret_cast<uint32_t*>(ol)[i1] =
                pack_h2(a2 - __half2float(h2), a3 - __half2float(h3));
        }
    }
}

// ========================= launch ===========================
extern "C" void kernel_launch(void* const* d_in, const int* in_sizes, int n_in,
                              void* d_out, int out_size)
{
    const float* x     = (const float*)d_in[0];
    const float* ln1_g = (const float*)d_in[1];
    const float* ln1_b = (const float*)d_in[2];
    const float* ln2_g = (const float*)d_in[3];
    const float* ln2_b = (const float*)d_in[4];
    const float* Wq    = (const float*)d_in[5];
    const float* Wk    = (const float*)d_in[6];
    const float* Wv    = (const float*)d_in[7];
    const float* Wo    = (const float*)d_in[8];
    const float* W1    = (const float*)d_in[9];
    const float* b1    = (const float*)d_in[10];
    const float* W2    = (const float*)d_in[11];
    const float* b2    = (const float*)d_in[12];
    float* out = (float*)d_out;

    float *x2;
    __half *qh, *kh, *vh, *xh, *xl, *oh, *ol, *fh, *fl, *wgt;
    cudaGetSymbolAddress((void**)&x2,  g_x2);
    cudaGetSymbolAddress((void**)&qh,  g_qh);
    cudaGetSymbolAddress((void**)&kh,  g_kh);
    cudaGetSymbolAddress((void**)&vh,  g_vh);
    cudaGetSymbolAddress((void**)&xh,  g_xh);
    cudaGetSymbolAddress((void**)&xl,  g_xl);
    cudaGetSymbolAddress((void**)&oh,  g_oh);
    cudaGetSymbolAddress((void**)&ol,  g_ol);
    cudaGetSymbolAddress((void**)&fh,  g_fh);
    cudaGetSymbolAddress((void**)&fl,  g_fl);
    cudaGetSymbolAddress((void**)&wgt, g_w);

    cudaFuncSetAttribute(gemm_mma<MD_QKV>, cudaFuncAttributeMaxDynamicSharedMemorySize, GEMM_SMEM);
    cudaFuncSetAttribute(gemm_mma<MD_RES>, cudaFuncAttributeMaxDynamicSharedMemorySize, GEMM_SMEM);
    cudaFuncSetAttribute(gemm_mma<MD_BIAS | MD_RELU | MD_SPLIT>, cudaFuncAttributeMaxDynamicSharedMemorySize, GEMM_SMEM);
    cudaFuncSetAttribute(gemm_mma<MD_BIAS | MD_RELU | MD_RES>, cudaFuncAttributeMaxDynamicSharedMemorySize, GEMM_SMEM);
    cudaFuncSetAttribute(attn_mma, cudaFuncAttributeMaxDynamicSharedMemorySize, ATT_SMEM);

    dim3 blk(256);
    dim3 gQKV(3072 / 128, Mm / 128);
    dim3 gD(Dd / 128, Mm / 128);
    dim3 gF(FFf / 128, Mm / 128);
    const int QD4 = Dd * Dd / 4, FD4 = Dd * FFf / 4;

    // weight conversions (single fp16)
    wsplit_strided_kernel<<<QD4 / 256, blk>>>(Wq, wgt + WQKV, 0,    QD4);
    wsplit_strided_kernel<<<QD4 / 256, blk>>>(Wk, wgt + WQKV, 1024, QD4);
    wsplit_strided_kernel<<<QD4 / 256, blk>>>(Wv, wgt + WQKV, 2048, QD4);
    wsplit_kernel<<<QD4 / 256, blk>>>(Wo, wgt + WOO, QD4);
    wsplit_kernel<<<FD4 / 256, blk>>>(W1, wgt + W1O, FD4);
    wsplit_kernel<<<FD4 / 256, blk>>>(W2, wgt + W2O, FD4);

    // h = LN1(x) -> hi/lo
    ln_split_kernel<<<Mm, blk>>>(x, ln1_g, ln1_b, xh, xl);
    // q|k|v = h @ Wqkv -> fp16 hi/lo [B,H,S,HD] (q pre-scaled by SCL2)
    gemm_mma<MD_QKV><<<gQKV, blk, GEMM_SMEM>>>(xh, xl, wgt + WQKV,
        nullptr, nullptr, (float*)qh, (float*)kh, (float*)vh, nullptr, nullptr, 3072, Dd);
    // attention -> hi/lo o
    attn_mma<<<dim3(Ss / 256, Bb * Hh), blk, ATT_SMEM>>>(qh, kh, vh, oh, ol);
    // x2 = x + o @ Wo
    gemm_mma<MD_RES><<<gD, blk, GEMM_SMEM>>>(oh, ol, wgt + WOO,
        nullptr, x, x2, nullptr, nullptr, nullptr, nullptr, Dd, Dd);
    // h = LN2(x2) -> hi/lo
    ln_split_kernel<<<Mm, blk>>>(x2, ln2_g, ln2_b, xh, xl);
    // ff1 = relu(h @ W1 + b1) -> hi/lo
    gemm_mma<MD_BIAS | MD_RELU | MD_SPLIT><<<gF, blk, GEMM_SMEM>>>(xh, xl,
        wgt + W1O, b1, nullptr, nullptr, nullptr, nullptr, fh, fl, FFf, Dd);
    // out = x2 + relu(ff1 @ W2 + b2)
    gemm_mma<MD_BIAS | MD_RELU | MD_RES><<<gD, blk, GEMM_SMEM>>>(fh, fl,
        wgt + W2O, b2, x2, out, nullptr, nullptr, nullptr, nullptr, Dd, FFf);
}

// round 15
// speedup vs baseline: 4.3904x; 1.2252x over previous
#include <cuda_runtime.h>
#include <cuda_fp16.h>
#include <cstdint>

// ---------------------------------------------------------------------------
// TransformerLayer: B=4, S=2048, D=1024, H=16, HD=64, FF=4096, fp32 I/O.
// Round 14: attention all-single-fp16 (1-pass QK, 1-pass PV); q/k/v stored
// single fp16 by the QKV GEMM. GEMMs unchanged from R13 (2-pass split-fp16).
// ---------------------------------------------------------------------------

constexpr int Bb = 4, Ss = 2048, Dd = 1024, Hh = 16, HDd = 64, FFf = 4096;
constexpr int Mm = Bb * Ss;            // 8192 rows
constexpr float EPS = 1e-5f;
constexpr float SCL2 = 0.125f * 1.4426950408889634f;

// fp32 scratch
__device__ float g_x2 [Mm * Dd];
// fp16 activation scratch
__device__ __half g_qh[(size_t)Mm * Dd];
__device__ __half g_kh[(size_t)Mm * Dd];
__device__ __half g_vh[(size_t)Mm * Dd];
__device__ __half g_xh[(size_t)Mm * Dd];
__device__ __half g_xl[(size_t)Mm * Dd];
__device__ __half g_oh[(size_t)Mm * Dd];
__device__ __half g_ol[(size_t)Mm * Dd];
__device__ __half g_fh[(size_t)Mm * FFf];
__device__ __half g_fl[(size_t)Mm * FFf];
// fp16 weights (single, rn). Layout: [0,3M) fused Wqkv [1024,3072]; Wo, W1, W2.
constexpr size_t WQKV = 0, WOO = 3u << 20;
constexpr size_t W1O = 4u << 20, W2O = 8u << 20, WTOT = 12u << 20;
__device__ __half g_w[WTOT];

// ========================= small PTX helpers ===========================
__device__ __forceinline__ uint32_t smem_u32(const void* p) {
    uint32_t a;
    asm("{ .reg .u64 t; cvta.to.shared.u64 t, %1; cvt.u32.u64 %0, t; }" : "=r"(a) : "l"(p));
    return a;
}
__device__ __forceinline__ void ldsm_x4(uint32_t (&r)[4], uint32_t addr) {
    asm volatile("ldmatrix.sync.aligned.m8n8.x4.shared.b16 {%0,%1,%2,%3}, [%4];"
        : "=r"(r[0]), "=r"(r[1]), "=r"(r[2]), "=r"(r[3]) : "r"(addr));
}
__device__ __forceinline__ void ldsm_x4_t(uint32_t (&r)[4], uint32_t addr) {
    asm volatile("ldmatrix.sync.aligned.m8n8.x4.trans.shared.b16 {%0,%1,%2,%3}, [%4];"
        : "=r"(r[0]), "=r"(r[1]), "=r"(r[2]), "=r"(r[3]) : "r"(addr));
}
__device__ __forceinline__ void mma_h(float (&c)[4], const uint32_t (&a)[4],
                                      uint32_t b0, uint32_t b1) {
    asm volatile("mma.sync.aligned.m16n8k16.row.col.f32.f16.f16.f32 "
        "{%0,%1,%2,%3}, {%4,%5,%6,%7}, {%8,%9}, {%0,%1,%2,%3};"
        : "+f"(c[0]), "+f"(c[1]), "+f"(c[2]), "+f"(c[3])
        : "r"(a[0]), "r"(a[1]), "r"(a[2]), "r"(a[3]), "r"(b0), "r"(b1));
}
__device__ __forceinline__ uint32_t pack_h2(float a, float b) {
    __half2 h = __floats2half2_rn(a, b);
    return *reinterpret_cast<uint32_t*>(&h);
}
__device__ __forceinline__ float ex2(float x) {
    float y;
    asm("ex2.approx.ftz.f32 %0, %1;" : "=f"(y) : "f"(x));
    return y;
}
__device__ __forceinline__ void cp16(uint32_t dst, const void* src) {
    asm volatile("cp.async.cg.shared.global [%0], [%1], 16;" :: "r"(dst), "l"(src) : "memory");
}
__device__ __forceinline__ void cp_commit() { asm volatile("cp.async.commit_group;" ::: "memory"); }
template <int N>
__device__ __forceinline__ void cp_wait() {
    asm volatile("cp.async.wait_group %0;" :: "n"(N) : "memory");
}

// ========================= LayerNorm (writes hi/lo fp16) ====================
__global__ void __launch_bounds__(256) ln_split_kernel(
    const float* __restrict__ x, const float* __restrict__ g,
    const float* __restrict__ b, __half* __restrict__ oh,
    __half* __restrict__ ol)
{
    int row = blockIdx.x;
    int t = threadIdx.x;
    const float4 v = reinterpret_cast<const float4*>(x + (size_t)row * Dd)[t];
    float s  = v.x + v.y + v.z + v.w;
    float ss = v.x * v.x + v.y * v.y + v.z * v.z + v.w * v.w;
#pragma unroll
    for (int o = 16; o > 0; o >>= 1) {
        s  += __shfl_xor_sync(0xffffffffu, s,  o);
        ss += __shfl_xor_sync(0xffffffffu, ss, o);
    }
    __shared__ float red[16];
    int w = t >> 5;
    if ((t & 31) == 0) { red[w] = s; red[8 + w] = ss; }
    __syncthreads();
    float st = 0.f, sst = 0.f;
#pragma unroll
    for (int i = 0; i < 8; i++) { st += red[i]; sst += red[8 + i]; }
    float mu  = st  * (1.0f / Dd);
    float var = sst * (1.0f / Dd) - mu * mu;
    float inv = rsqrtf(var + EPS);
    float4 gg = reinterpret_cast<const float4*>(g)[t];
    float4 bb = reinterpret_cast<const float4*>(b)[t];
    float f[4];
    f[0] = (v.x - mu) * inv * gg.x + bb.x;
    f[1] = (v.y - mu) * inv * gg.y + bb.y;
    f[2] = (v.z - mu) * inv * gg.z + bb.z;
    f[3] = (v.w - mu) * inv * gg.w + bb.w;
    uint32_t hw[2], lw[2];
#pragma unroll
    for (int e = 0; e < 2; e++) {
        float a = f[2 * e], c = f[2 * e + 1];
        __half ha = __float2half_rn(a), hc = __float2half_rn(c);
        hw[e] = pack_h2(a, c);
        lw[e] = pack_h2(a - __half2float(ha), c - __half2float(hc));
    }
    size_t idx = (size_t)row * (Dd / 4) + t;
    reinterpret_cast<uint2*>(oh)[idx] = make_uint2(hw[0], hw[1]);
    reinterpret_cast<uint2*>(ol)[idx] = make_uint2(lw[0], lw[1]);
}

// ========================= weight fp32 -> single fp16 =======================
__global__ void __launch_bounds__(256) wsplit_kernel(
    const float* __restrict__ x, __half* __restrict__ w, int n4)
{
    int i = blockIdx.x * 256 + threadIdx.x;
    if (i >= n4) return;
    float4 v = reinterpret_cast<const float4*>(x)[i];
    reinterpret_cast<uint2*>(w)[i] =
        make_uint2(pack_h2(v.x, v.y), pack_h2(v.z, v.w));
}

// strided: src [K,1024] -> dst rows stride 3072, column offset coloff
__global__ void __launch_bounds__(256) wsplit_strided_kernel(
    const float* __restrict__ x, __half* __restrict__ w, int coloff, int n4)
{
    int i = blockIdx.x * 256 + threadIdx.x;
    if (i >= n4) return;
    float4 v = reinterpret_cast<const float4*>(x)[i];
    int row = (i * 4) >> 10;
    int col = (i * 4) & 1023;
    size_t di = ((size_t)row * 3072 + coloff + col) >> 2;
    reinterpret_cast<uint2*>(w)[di] =
        make_uint2(pack_h2(v.x, v.y), pack_h2(v.z, v.w));
}

// ========================= cp.async 2-pass split-fp16 GEMM (R13) ============
constexpr int MD_BIAS = 1, MD_RELU = 2, MD_RES = 4, MD_QKV = 8, MD_SPLIT = 16;

constexpr int NSTG = 3;
constexpr int LDA = 40;
constexpr int LDB = 136;
constexpr int A_BYTES = 128 * LDA * 2;
constexpr int B_BYTES = 32 * LDB * 2;
constexpr int B_OFF   = 2 * A_BYTES;
constexpr int STAGE   = B_OFF + B_BYTES;
constexpr int GEMM_SMEM = NSTG * STAGE;

template <int MODE>
__global__ void __launch_bounds__(256, 2) gemm_mma(
    const __half* __restrict__ Ah, const __half* __restrict__ Al,
    const __half* __restrict__ Bw,
    const float* __restrict__ bias, const float* __restrict__ res,
    float* __restrict__ C, float* __restrict__ C2, float* __restrict__ C3,
    __half* __restrict__ Chi, __half* __restrict__ Clo,
    int N, int K)
{
    extern __shared__ char dsm[];
    const uint32_t smemU = smem_u32(dsm);

    const int tid  = threadIdx.x;
    const int lane = tid & 31;
    const int wid  = tid >> 5;
    const int wm   = wid >> 2;
    const int wn   = wid & 3;
    const int m0   = blockIdx.y * 128;
    const int n0   = blockIdx.x * 128;
    const int NC   = K >> 5;

    auto issue_stage = [&](int c) {
        const uint32_t sb = smemU + (uint32_t)(c % NSTG) * STAGE;
        const int k0 = c << 5;
#pragma unroll
        for (int i = 0; i < 2; i++) {
            int ch = tid + i * 256;
            int arow = ch >> 2, aseg = ch & 3;
            uint32_t ad = sb + ((uint32_t)arow * LDA + (uint32_t)aseg * 8u) * 2u;
            cp16(ad, Ah + (size_t)(m0 + arow) * K + k0 + aseg * 8);
            cp16(ad + A_BYTES, Al + (size_t)(m0 + arow) * K + k0 + aseg * 8);
        }
#pragma unroll
        for (int i = 0; i < 2; i++) {
            int ch = tid + i * 256;
            int brow = ch >> 4, bseg = ch & 15;
            uint32_t bd = sb + (uint32_t)B_OFF + ((uint32_t)brow * LDB + (uint32_t)bseg * 8u) * 2u;
            cp16(bd, Bw + (size_t)(k0 + brow) * N + n0 + bseg * 8);
        }
        cp_commit();
    };

    issue_stage(0);
    issue_stage(1);

    float acc[4][4][4];
#pragma unroll
    for (int mt = 0; mt < 4; mt++)
#pragma unroll
        for (int nt = 0; nt < 4; nt++)
#pragma unroll
            for (int e = 0; e < 4; e++) acc[mt][nt][e] = 0.f;

    const uint32_t aCmp0 = smemU + ((uint32_t)(wm * 64 + (lane & 15)) * LDA +
                                    (uint32_t)(lane >> 4) * 8) * 2u;
    const uint32_t bCmp0 = smemU + (uint32_t)B_OFF +
                           ((uint32_t)(lane & 15) * LDB + (uint32_t)(wn * 32)) * 2u +
                           (uint32_t)(lane >> 4) * 16u;

    for (int c = 0; c < NC; c++) {
        cp_wait<1>();
        __syncthreads();
        if (c + 2 < NC) issue_stage(c + 2);

        const uint32_t so = (uint32_t)(c % NSTG) * STAGE;
        const uint32_t aC = aCmp0 + so;
        const uint32_t bC = bCmp0 + so;
#pragma unroll
        for (int ks = 0; ks < 2; ks++) {
            uint32_t Bf[4][2];
#pragma unroll
            for (int np = 0; np < 2; np++) {
                uint32_t bd = bC + (uint32_t)ks * (16 * LDB * 2) + (uint32_t)np * 32u;
                uint32_t t4[4];
                ldsm_x4_t(t4, bd);
                Bf[2 * np][0] = t4[0]; Bf[2 * np][1] = t4[1];
                Bf[2 * np + 1][0] = t4[2]; Bf[2 * np + 1][1] = t4[3];
            }
#pragma unroll
            for (int mt = 0; mt < 4; mt++) {
                uint32_t Ahf[4], Alf[4];
                uint32_t ad = aC + (uint32_t)mt * (16 * LDA * 2) + (uint32_t)ks * 32u;
                ldsm_x4(Ahf, ad);
                ldsm_x4(Alf, ad + A_BYTES);
#pragma unroll
                for (int nt = 0; nt < 4; nt++) {
                    mma_h(acc[mt][nt], Ahf, Bf[nt][0], Bf[nt][1]);
                    mma_h(acc[mt][nt], Alf, Bf[nt][0], Bf[nt][1]);
                }
            }
        }
    }

    // -------- epilogue --------
    const int rbase = m0 + wm * 64;
    const int cbase = n0 + wn * 32;
#pragma unroll
    for (int mt = 0; mt < 4; mt++)
#pragma unroll
        for (int nt = 0; nt < 4; nt++) {
#pragma unroll
            for (int half = 0; half < 2; half++) {
                int r = rbase + mt * 16 + (lane >> 2) + half * 8;
                int cc = cbase + nt * 8 + (lane & 3) * 2;
                float2 v;
                v.x = acc[mt][nt][half * 2 + 0];
                v.y = acc[mt][nt][half * 2 + 1];
                if (MODE & MD_BIAS) {
                    float2 bb = *reinterpret_cast<const float2*>(bias + cc);
                    v.x += bb.x; v.y += bb.y;
                }
                if (MODE & MD_RELU) {
                    v.x = fmaxf(v.x, 0.f); v.y = fmaxf(v.y, 0.f);
                }
                if (MODE & MD_RES) {
                    float2 rr = *reinterpret_cast<const float2*>(res + (size_t)r * N + cc);
                    v.x += rr.x; v.y += rr.y;
                }
                if (MODE & MD_SPLIT) {
                    __half hx = __float2half_rn(v.x), hy = __float2half_rn(v.y);
                    size_t idx = ((size_t)r * N + cc) >> 1;
                    reinterpret_cast<uint32_t*>(Chi)[idx] = pack_h2(v.x, v.y);
                    reinterpret_cast<uint32_t*>(Clo)[idx] =
                        pack_h2(v.x - __half2float(hx), v.y - __half2float(hy));
                } else if (MODE & MD_QKV) {
                    // fused QKV -> single fp16 [B,H,S,HD]; q pre-scaled.
                    int which = cc >> 10;
                    int c1 = cc & 1023;
                    float* dstf = which == 0 ? C : (which == 1 ? C2 : C3);
                    __half* dh = reinterpret_cast<__half*>(dstf);
                    if (which == 0) { v.x *= SCL2; v.y *= SCL2; }
                    int b_ = r >> 11, s_ = r & (Ss - 1);
                    int h_ = c1 >> 6, d_ = c1 & 63;
                    size_t idx = (((size_t)(b_ * Hh + h_) * Ss + s_) * HDd + d_) >> 1;
                    reinterpret_cast<uint32_t*>(dh)[idx] = pack_h2(v.x, v.y);
                } else {
                    *reinterpret_cast<float2*>(C + (size_t)r * N + cc) = v;
                }
            }
        }
}

// ========================= attention v3: all single fp16 ====================
// q,k,v single fp16 in [B,H,S,64]; q pre-scaled by SCL2.
// CTA = 256 q rows, 8 warps, warp = 32 q rows (2 m16 tiles).
// 1-pass QK, 1-pass PV. 2-stage cp.async K|V ring.
constexpr int AALD  = 72;
constexpr int AKMAT = 64 * AALD * 2;      // 9216 (K); V at +AKMAT
constexpr int AST   = 2 * AKMAT;          // 18432 per stage
constexpr int AQOFF = 2 * AST;            // 36864
constexpr int AQMAT = 256 * AALD * 2;     // 36864
constexpr int ATT_SMEM = AQOFF + AQMAT;   // 73728

__global__ void __launch_bounds__(256, 1) attn_mma(
    const __half* __restrict__ qhp, const __half* __restrict__ khp,
    const __half* __restrict__ vhp, __half* __restrict__ oh,
    __half* __restrict__ ol)
{
    extern __shared__ char sm[];
    const uint32_t S0 = smem_u32(sm);
    const int tid = threadIdx.x, lane = tid & 31, w = tid >> 5;
    const int bh = blockIdx.y, q0 = blockIdx.x * 256;
    const int b_ = bh >> 4, h_ = bh & 15;

    const __half* qb = qhp + ((size_t)bh * Ss + q0) * HDd;
    const __half* kb = khp + (size_t)bh * Ss * HDd;
    const __half* vb = vhp + (size_t)bh * Ss * HDd;

    auto issue_kv = [&](int t) {
        uint32_t sb = S0 + (uint32_t)(t & 1) * AST;
        int k0 = t * 64;
#pragma unroll
        for (int i = 0; i < 2; i++) {
            int ch = tid + i * 256;              // 512 chunks per matrix
            int r = ch >> 3, s = ch & 7;
            uint32_t off = (uint32_t)r * 144u + (uint32_t)s * 16u;
            const size_t so_ = (size_t)(k0 + r) * HDd + s * 8;
            cp16(sb + off,         kb + so_);
            cp16(sb + AKMAT + off, vb + so_);
        }
        cp_commit();
    };

    // Q staging (one-time) + first K/V stage
    {
#pragma unroll
        for (int i = 0; i < 8; i++) {
            int ch = tid + i * 256;              // 2048 chunks
            int r = ch >> 3, s = ch & 7;
            uint32_t off = (uint32_t)r * 144u + (uint32_t)s * 16u;
            cp16(S0 + AQOFF + off, qb + (size_t)r * HDd + s * 8);
        }
        cp_commit();
    }
    issue_kv(0);
    cp_wait<0>();
    __syncthreads();

    // persistent Q fragments: 2 m-tiles x 4 k-steps
    uint32_t Qf[2][4][4];
#pragma unroll
    for (int mi = 0; mi < 2; mi++) {
        uint32_t base = S0 + AQOFF +
            (((uint32_t)(w * 32 + mi * 16 + (lane & 15))) * AALD +
             (uint32_t)(lane >> 4) * 8u) * 2u;
#pragma unroll
        for (int ks = 0; ks < 4; ks++)
            ldsm_x4(Qf[mi][ks], base + (uint32_t)ks * 32u);
    }

    float oa[2][8][4];
#pragma unroll
    for (int mi = 0; mi < 2; mi++)
#pragma unroll
        for (int nt = 0; nt < 8; nt++)
#pragma unroll
            for (int e = 0; e < 4; e++) oa[mi][nt][e] = 0.f;
    float mrow[2][2] = {{-1e30f, -1e30f}, {-1e30f, -1e30f}};
    float lrow[2][2] = {{0.f, 0.f}, {0.f, 0.f}};

    for (int t = 0; t < Ss / 64; t++) {
        if (t > 0) { cp_wait<0>(); __syncthreads(); }
        if (t + 1 < Ss / 64) issue_kv(t + 1);
        const uint32_t sbU = S0 + (uint32_t)(t & 1) * AST;

        // ---- S = Q K^T (1 pass). ldsm.x4 -> frags for nt and nt+1 ----
        float sc[2][8][4];
#pragma unroll
        for (int mi = 0; mi < 2; mi++)
#pragma unroll
            for (int nt = 0; nt < 8; nt++)
#pragma unroll
                for (int e = 0; e < 4; e++) sc[mi][nt][e] = 0.f;

        // lanes 0-15: tile nt rows; lanes 16-31: tile nt+1 rows (+8 rows)
        const uint32_t kfb = sbU +
            (((uint32_t)(lane & 7)) * AALD + (uint32_t)((lane >> 3) & 1) * 8u) * 2u +
            (uint32_t)(lane >> 4) * (8u * AALD * 2u);
#pragma unroll
        for (int nt = 0; nt < 8; nt += 2) {
#pragma unroll
            for (int ks = 0; ks < 4; ks++) {
                uint32_t kf[4];
                ldsm_x4(kf, kfb + ((uint32_t)nt * 8u * AALD + (uint32_t)ks * 16u) * 2u);
#pragma unroll
                for (int mi = 0; mi < 2; mi++) {
                    mma_h(sc[mi][nt],     Qf[mi][ks], kf[0], kf[1]);
                    mma_h(sc[mi][nt + 1], Qf[mi][ks], kf[2], kf[3]);
                }
            }
        }

        // ---- online softmax per m-tile (log2 domain; q pre-scaled) ----
#pragma unroll
        for (int mi = 0; mi < 2; mi++) {
            float mt0 = sc[mi][0][0], mt1 = sc[mi][0][2];
#pragma unroll
            for (int nt = 0; nt < 8; nt++) {
                mt0 = fmaxf(mt0, fmaxf(sc[mi][nt][0], sc[mi][nt][1]));
                mt1 = fmaxf(mt1, fmaxf(sc[mi][nt][2], sc[mi][nt][3]));
            }
            mt0 = fmaxf(mt0, __shfl_xor_sync(0xffffffffu, mt0, 1));
            mt0 = fmaxf(mt0, __shfl_xor_sync(0xffffffffu, mt0, 2));
            mt1 = fmaxf(mt1, __shfl_xor_sync(0xffffffffu, mt1, 1));
            mt1 = fmaxf(mt1, __shfl_xor_sync(0xffffffffu, mt1, 2));
            float mn0 = fmaxf(mrow[mi][0], mt0), mn1 = fmaxf(mrow[mi][1], mt1);
            float c0 = ex2(mrow[mi][0] - mn0), c1 = ex2(mrow[mi][1] - mn1);
            mrow[mi][0] = mn0; mrow[mi][1] = mn1;

            float ls0 = 0.f, ls1 = 0.f;
#pragma unroll
            for (int nt = 0; nt < 8; nt++) {
                sc[mi][nt][0] = ex2(sc[mi][nt][0] - mn0);
                sc[mi][nt][1] = ex2(sc[mi][nt][1] - mn0);
                sc[mi][nt][2] = ex2(sc[mi][nt][2] - mn1);
                sc[mi][nt][3] = ex2(sc[mi][nt][3] - mn1);
                ls0 += sc[mi][nt][0] + sc[mi][nt][1];
                ls1 += sc[mi][nt][2] + sc[mi][nt][3];
            }
            ls0 += __shfl_xor_sync(0xffffffffu, ls0, 1);
            ls0 += __shfl_xor_sync(0xffffffffu, ls0, 2);
            ls1 += __shfl_xor_sync(0xffffffffu, ls1, 1);
            ls1 += __shfl_xor_sync(0xffffffffu, ls1, 2);
            lrow[mi][0] = lrow[mi][0] * c0 + ls0;
            lrow[mi][1] = lrow[mi][1] * c1 + ls1;
#pragma unroll
            for (int nt = 0; nt < 8; nt++) {
                oa[mi][nt][0] *= c0; oa[mi][nt][1] *= c0;
                oa[mi][nt][2] *= c1; oa[mi][nt][3] *= c1;
            }
        }

        // ---- O += P V (1 pass). trans ldsm -> frags for nt and nt+1 ----
        const uint32_t vfb = sbU + (uint32_t)AKMAT +
            ((uint32_t)(lane & 15)) * (uint32_t)AALD * 2u +
            (uint32_t)(lane >> 4) * 16u;
#pragma unroll
        for (int kk = 0; kk < 4; kk++) {
            uint32_t Pf[2][4];
#pragma unroll
            for (int mi = 0; mi < 2; mi++) {
#pragma unroll
                for (int half = 0; half < 2; half++) {
                    Pf[mi][2 * half + 0] = pack_h2(sc[mi][2 * kk + half][0],
                                                   sc[mi][2 * kk + half][1]);
                    Pf[mi][2 * half + 1] = pack_h2(sc[mi][2 * kk + half][2],
                                                   sc[mi][2 * kk + half][3]);
                }
            }
#pragma unroll
            for (int nt = 0; nt < 8; nt += 2) {
                uint32_t vf[4];
                ldsm_x4_t(vf, vfb + ((uint32_t)kk * 16u * AALD + (uint32_t)nt * 8u) * 2u);
#pragma unroll
                for (int mi = 0; mi < 2; mi++) {
                    mma_h(oa[mi][nt],     Pf[mi], vf[0], vf[1]);
                    mma_h(oa[mi][nt + 1], Pf[mi], vf[2], vf[3]);
                }
            }
        }
    }

    // ---- epilogue: normalize, split to hi/lo fp16, write [B,S,D] ----
#pragma unroll
    for (int mi = 0; mi < 2; mi++) {
        float il0 = 1.0f / lrow[mi][0], il1 = 1.0f / lrow[mi][1];
        int sr0 = q0 + w * 32 + mi * 16 + (lane >> 2);
        int sr1 = sr0 + 8;
#pragma unroll
        for (int nt = 0; nt < 8; nt++) {
            int col = h_ * HDd + nt * 8 + (lane & 3) * 2;
            float a0 = oa[mi][nt][0] * il0, a1 = oa[mi][nt][1] * il0;
            float a2 = oa[mi][nt][2] * il1, a3 = oa[mi][nt][3] * il1;
            __half h0 = __float2half_rn(a0), h1 = __float2half_rn(a1);
            __half h2 = __float2half_rn(a2), h3 = __float2half_rn(a3);
            size_t i0 = (((size_t)(b_ * Ss + sr0)) * Dd + col) >> 1;
            size_t i1 = (((size_t)(b_ * Ss + sr1)) * Dd + col) >> 1;
            reinterpret_cast<uint32_t*>(oh)[i0] = pack_h2(a0, a1);
            reinterpret_cast<uint32_t*>(ol)[i0] =
                pack_h2(a0 - __half2float(h0), a1 - __half2float(h1));
            reinterpret_cast<uint32_t*>(oh)[i1] = pack_h2(a2, a3);
            reinterpret_cast<uint32_t*>(ol)[i1] =
                pack_h2(a2 - __half2float(h2), a3 - __half2float(h3));
        }
    }
}

// ========================= launch ===========================
extern "C" void kernel_launch(void* const* d_in, const int* in_sizes, int n_in,
                              void* d_out, int out_size)
{
    const float* x     = (const float*)d_in[0];
    const float* ln1_g = (const float*)d_in[1];
    const float* ln1_b = (const float*)d_in[2];
    const float* ln2_g = (const float*)d_in[3];
    const float* ln2_b = (const float*)d_in[4];
    const float* Wq    = (const float*)d_in[5];
    const float* Wk    = (const float*)d_in[6];
    const float* Wv    = (const float*)d_in[7];
    const float* Wo    = (const float*)d_in[8];
    const float* W1    = (const float*)d_in[9];
    const float* b1    = (const float*)d_in[10];
    const float* W2    = (const float*)d_in[11];
    const float* b2    = (const float*)d_in[12];
    float* out = (float*)d_out;

    float *x2;
    __half *qh, *kh, *vh, *xh, *xl, *oh, *ol, *fh, *fl, *wgt;
    cudaGetSymbolAddress((void**)&x2,  g_x2);
    cudaGetSymbolAddress((void**)&qh,  g_qh);
    cudaGetSymbolAddress((void**)&kh,  g_kh);
    cudaGetSymbolAddress((void**)&vh,  g_vh);
    cudaGetSymbolAddress((void**)&xh,  g_xh);
    cudaGetSymbolAddress((void**)&xl,  g_xl);
    cudaGetSymbolAddress((void**)&oh,  g_oh);
    cudaGetSymbolAddress((void**)&ol,  g_ol);
    cudaGetSymbolAddress((void**)&fh,  g_fh);
    cudaGetSymbolAddress((void**)&fl,  g_fl);
    cudaGetSymbolAddress((void**)&wgt, g_w);

    cudaFuncSetAttribute(gemm_mma<MD_QKV>, cudaFuncAttributeMaxDynamicSharedMemorySize, GEMM_SMEM);
    cudaFuncSetAttribute(gemm_mma<MD_RES>, cudaFuncAttributeMaxDynamicSharedMemorySize, GEMM_SMEM);
    cudaFuncSetAttribute(gemm_mma<MD_BIAS | MD_RELU | MD_SPLIT>, cudaFuncAttributeMaxDynamicSharedMemorySize, GEMM_SMEM);
    cudaFuncSetAttribute(gemm_mma<MD_BIAS | MD_RELU | MD_RES>, cudaFuncAttributeMaxDynamicSharedMemorySize, GEMM_SMEM);
    cudaFuncSetAttribute(attn_mma, cudaFuncAttributeMaxDynamicSharedMemorySize, ATT_SMEM);

    dim3 blk(256);
    dim3 gQKV(3072 / 128, Mm / 128);
    dim3 gD(Dd / 128, Mm / 128);
    dim3 gF(FFf / 128, Mm / 128);
    const int QD4 = Dd * Dd / 4, FD4 = Dd * FFf / 4;

    // weight conversions (single fp16)
    wsplit_strided_kernel<<<QD4 / 256, blk>>>(Wq, wgt + WQKV, 0,    QD4);
    wsplit_strided_kernel<<<QD4 / 256, blk>>>(Wk, wgt + WQKV, 1024, QD4);
    wsplit_strided_kernel<<<QD4 / 256, blk>>>(Wv, wgt + WQKV, 2048, QD4);
    wsplit_kernel<<<QD4 / 256, blk>>>(Wo, wgt + WOO, QD4);
    wsplit_kernel<<<FD4 / 256, blk>>>(W1, wgt + W1O, FD4);
    wsplit_kernel<<<FD4 / 256, blk>>>(W2, wgt + W2O, FD4);

    // h = LN1(x) -> hi/lo
    ln_split_kernel<<<Mm, blk>>>(x, ln1_g, ln1_b, xh, xl);
    // q|k|v = h @ Wqkv -> single fp16 [B,H,S,HD] (q pre-scaled by SCL2)
    gemm_mma<MD_QKV><<<gQKV, blk, GEMM_SMEM>>>(xh, xl, wgt + WQKV,
        nullptr, nullptr, (float*)qh, (float*)kh, (float*)vh, nullptr, nullptr, 3072, Dd);
    // attention -> hi/lo o
    attn_mma<<<dim3(Ss / 256, Bb * Hh), blk, ATT_SMEM>>>(qh, kh, vh, oh, ol);
    // x2 = x + o @ Wo
    gemm_mma<MD_RES><<<gD, blk, GEMM_SMEM>>>(oh, ol, wgt + WOO,
        nullptr, x, x2, nullptr, nullptr, nullptr, nullptr, Dd, Dd);
    // h = LN2(x2) -> hi/lo
    ln_split_kernel<<<Mm, blk>>>(x2, ln2_g, ln2_b, xh, xl);
    // ff1 = relu(h @ W1 + b1) -> hi/lo
    gemm_mma<MD_BIAS | MD_RELU | MD_SPLIT><<<gF, blk, GEMM_SMEM>>>(xh, xl,
        wgt + W1O, b1, nullptr, nullptr, nullptr, nullptr, fh, fl, FFf, Dd);
    // out = x2 + relu(ff1 @ W2 + b2)
    gemm_mma<MD_BIAS | MD_RELU | MD_RES><<<gD, blk, GEMM_SMEM>>>(fh, fl,
        wgt + W2O, b2, x2, out, nullptr, nullptr, nullptr, nullptr, Dd, FFf);
}

// round 16
// speedup vs baseline: 7.1370x; 1.6256x over previous
#include <cuda_runtime.h>
#include <cuda_fp16.h>
#include <cstdint>

// ---------------------------------------------------------------------------
// TransformerLayer: B=4, S=2048, D=1024, H=16, HD=64, FF=4096, fp32 I/O.
// Round 15: 1-pass single-fp16 everywhere. Activations AND weights stored as
// single rn fp16 (error budget measured: weight-rn dominates at ~1.3e-4 and
// splits bought nothing). GEMM: 128x128x32 tile, NSTG=3, 2 CTAs/SM, one
// barrier/chunk, fused QKV. Attention: R14 single-fp16 flash (o now single).
// ---------------------------------------------------------------------------

constexpr int Bb = 4, Ss = 2048, Dd = 1024, Hh = 16, HDd = 64, FFf = 4096;
constexpr int Mm = Bb * Ss;            // 8192 rows
constexpr float EPS = 1e-5f;
constexpr float SCL2 = 0.125f * 1.4426950408889634f;

// fp32 scratch
__device__ float g_x2 [Mm * Dd];
// fp16 activation scratch (all single)
__device__ __half g_qh[(size_t)Mm * Dd];
__device__ __half g_kh[(size_t)Mm * Dd];
__device__ __half g_vh[(size_t)Mm * Dd];
__device__ __half g_xh[(size_t)Mm * Dd];
__device__ __half g_oh[(size_t)Mm * Dd];
__device__ __half g_fh[(size_t)Mm * FFf];
// fp16 weights (single, rn). Layout: [0,3M) fused Wqkv [1024,3072]; Wo, W1, W2.
constexpr size_t WQKV = 0, WOO = 3u << 20;
constexpr size_t W1O = 4u << 20, W2O = 8u << 20, WTOT = 12u << 20;
__device__ __half g_w[WTOT];

// ========================= small PTX helpers ===========================
__device__ __forceinline__ uint32_t smem_u32(const void* p) {
    uint32_t a;
    asm("{ .reg .u64 t; cvta.to.shared.u64 t, %1; cvt.u32.u64 %0, t; }" : "=r"(a) : "l"(p));
    return a;
}
__device__ __forceinline__ void ldsm_x4(uint32_t (&r)[4], uint32_t addr) {
    asm volatile("ldmatrix.sync.aligned.m8n8.x4.shared.b16 {%0,%1,%2,%3}, [%4];"
        : "=r"(r[0]), "=r"(r[1]), "=r"(r[2]), "=r"(r[3]) : "r"(addr));
}
__device__ __forceinline__ void ldsm_x4_t(uint32_t (&r)[4], uint32_t addr) {
    asm volatile("ldmatrix.sync.aligned.m8n8.x4.trans.shared.b16 {%0,%1,%2,%3}, [%4];"
        : "=r"(r[0]), "=r"(r[1]), "=r"(r[2]), "=r"(r[3]) : "r"(addr));
}
__device__ __forceinline__ void mma_h(float (&c)[4], const uint32_t (&a)[4],
                                      uint32_t b0, uint32_t b1) {
    asm volatile("mma.sync.aligned.m16n8k16.row.col.f32.f16.f16.f32 "
        "{%0,%1,%2,%3}, {%4,%5,%6,%7}, {%8,%9}, {%0,%1,%2,%3};"
        : "+f"(c[0]), "+f"(c[1]), "+f"(c[2]), "+f"(c[3])
        : "r"(a[0]), "r"(a[1]), "r"(a[2]), "r"(a[3]), "r"(b0), "r"(b1));
}
__device__ __forceinline__ uint32_t pack_h2(float a, float b) {
    __half2 h = __floats2half2_rn(a, b);
    return *reinterpret_cast<uint32_t*>(&h);
}
__device__ __forceinline__ float ex2(float x) {
    float y;
    asm("ex2.approx.ftz.f32 %0, %1;" : "=f"(y) : "f"(x));
    return y;
}
__device__ __forceinline__ void cp16(uint32_t dst, const void* src) {
    asm volatile("cp.async.cg.shared.global [%0], [%1], 16;" :: "r"(dst), "l"(src) : "memory");
}
__device__ __forceinline__ void cp_commit() { asm volatile("cp.async.commit_group;" ::: "memory"); }
template <int N>
__device__ __forceinline__ void cp_wait() {
    asm volatile("cp.async.wait_group %0;" :: "n"(N) : "memory");
}

// ========================= LayerNorm (writes single fp16) ===================
__global__ void __launch_bounds__(256) ln_h_kernel(
    const float* __restrict__ x, const float* __restrict__ g,
    const float* __restrict__ b, __half* __restrict__ oh)
{
    int row = blockIdx.x;
    int t = threadIdx.x;
    const float4 v = reinterpret_cast<const float4*>(x + (size_t)row * Dd)[t];
    float s  = v.x + v.y + v.z + v.w;
    float ss = v.x * v.x + v.y * v.y + v.z * v.z + v.w * v.w;
#pragma unroll
    for (int o = 16; o > 0; o >>= 1) {
        s  += __shfl_xor_sync(0xffffffffu, s,  o);
        ss += __shfl_xor_sync(0xffffffffu, ss, o);
    }
    __shared__ float red[16];
    int w = t >> 5;
    if ((t & 31) == 0) { red[w] = s; red[8 + w] = ss; }
    __syncthreads();
    float st = 0.f, sst = 0.f;
#pragma unroll
    for (int i = 0; i < 8; i++) { st += red[i]; sst += red[8 + i]; }
    float mu  = st  * (1.0f / Dd);
    float var = sst * (1.0f / Dd) - mu * mu;
    float inv = rsqrtf(var + EPS);
    float4 gg = reinterpret_cast<const float4*>(g)[t];
    float4 bb = reinterpret_cast<const float4*>(b)[t];
    float f0 = (v.x - mu) * inv * gg.x + bb.x;
    float f1 = (v.y - mu) * inv * gg.y + bb.y;
    float f2 = (v.z - mu) * inv * gg.z + bb.z;
    float f3 = (v.w - mu) * inv * gg.w + bb.w;
    reinterpret_cast<uint2*>(oh)[(size_t)row * (Dd / 4) + t] =
        make_uint2(pack_h2(f0, f1), pack_h2(f2, f3));
}

// ========================= weight fp32 -> single fp16 =======================
__global__ void __launch_bounds__(256) wsplit_kernel(
    const float* __restrict__ x, __half* __restrict__ w, int n4)
{
    int i = blockIdx.x * 256 + threadIdx.x;
    if (i >= n4) return;
    float4 v = reinterpret_cast<const float4*>(x)[i];
    reinterpret_cast<uint2*>(w)[i] =
        make_uint2(pack_h2(v.x, v.y), pack_h2(v.z, v.w));
}

// strided: src [K,1024] -> dst rows stride 3072, column offset coloff
__global__ void __launch_bounds__(256) wsplit_strided_kernel(
    const float* __restrict__ x, __half* __restrict__ w, int coloff, int n4)
{
    int i = blockIdx.x * 256 + threadIdx.x;
    if (i >= n4) return;
    float4 v = reinterpret_cast<const float4*>(x)[i];
    int row = (i * 4) >> 10;
    int col = (i * 4) & 1023;
    size_t di = ((size_t)row * 3072 + coloff + col) >> 2;
    reinterpret_cast<uint2*>(w)[di] =
        make_uint2(pack_h2(v.x, v.y), pack_h2(v.z, v.w));
}

// ========================= cp.async 1-pass fp16 GEMM ========================
// C[M,N] = A[M,K] @ W[K,N]; both single rn fp16. One MMA pass.
// CTA tile 128x128x32; 8 warps 2(m)x4(n), warp 64x32. NSTG=3, one barrier
// per chunk, 2 CTAs/SM.
constexpr int MD_BIAS = 1, MD_RELU = 2, MD_RES = 4, MD_QKV = 8, MD_SPLIT = 16;

constexpr int NSTG = 3;
constexpr int LDA = 40;                         // 80 B rows
constexpr int LDB = 136;                        // 272 B rows
constexpr int A_BYTES = 128 * LDA * 2;          // 10240
constexpr int B_BYTES = 32 * LDB * 2;           // 8704
constexpr int B_OFF   = A_BYTES;                // 10240
constexpr int STAGE   = A_BYTES + B_BYTES;      // 18944
constexpr int GEMM_SMEM = NSTG * STAGE;         // 56832 (2 CTAs = 113664)

template <int MODE>
__global__ void __launch_bounds__(256, 2) gemm_mma(
    const __half* __restrict__ Ah, const __half* __restrict__ Bw,
    const float* __restrict__ bias, const float* __restrict__ res,
    float* __restrict__ C, float* __restrict__ C2, float* __restrict__ C3,
    __half* __restrict__ Chi, int N, int K)
{
    extern __shared__ char dsm[];
    const uint32_t smemU = smem_u32(dsm);

    const int tid  = threadIdx.x;
    const int lane = tid & 31;
    const int wid  = tid >> 5;
    const int wm   = wid >> 2;
    const int wn   = wid & 3;
    const int m0   = blockIdx.y * 128;
    const int n0   = blockIdx.x * 128;
    const int NC   = K >> 5;

    auto issue_stage = [&](int c) {
        const uint32_t sb = smemU + (uint32_t)(c % NSTG) * STAGE;
        const int k0 = c << 5;
#pragma unroll
        for (int i = 0; i < 2; i++) {
            int ch = tid + i * 256;
            int arow = ch >> 2, aseg = ch & 3;
            uint32_t ad = sb + ((uint32_t)arow * LDA + (uint32_t)aseg * 8u) * 2u;
            cp16(ad, Ah + (size_t)(m0 + arow) * K + k0 + aseg * 8);
        }
#pragma unroll
        for (int i = 0; i < 2; i++) {
            int ch = tid + i * 256;
            int brow = ch >> 4, bseg = ch & 15;
            uint32_t bd = sb + (uint32_t)B_OFF + ((uint32_t)brow * LDB + (uint32_t)bseg * 8u) * 2u;
            cp16(bd, Bw + (size_t)(k0 + brow) * N + n0 + bseg * 8);
        }
        cp_commit();
    };

    issue_stage(0);
    issue_stage(1);

    float acc[4][4][4];
#pragma unroll
    for (int mt = 0; mt < 4; mt++)
#pragma unroll
        for (int nt = 0; nt < 4; nt++)
#pragma unroll
            for (int e = 0; e < 4; e++) acc[mt][nt][e] = 0.f;

    const uint32_t aCmp0 = smemU + ((uint32_t)(wm * 64 + (lane & 15)) * LDA +
                                    (uint32_t)(lane >> 4) * 8) * 2u;
    const uint32_t bCmp0 = smemU + (uint32_t)B_OFF +
                           ((uint32_t)(lane & 15) * LDB + (uint32_t)(wn * 32)) * 2u +
                           (uint32_t)(lane >> 4) * 16u;

    for (int c = 0; c < NC; c++) {
        cp_wait<1>();
        __syncthreads();
        if (c + 2 < NC) issue_stage(c + 2);

        const uint32_t so = (uint32_t)(c % NSTG) * STAGE;
        const uint32_t aC = aCmp0 + so;
        const uint32_t bC = bCmp0 + so;
#pragma unroll
        for (int ks = 0; ks < 2; ks++) {
            uint32_t Bf[4][2];
#pragma unroll
            for (int np = 0; np < 2; np++) {
                uint32_t bd = bC + (uint32_t)ks * (16 * LDB * 2) + (uint32_t)np * 32u;
                uint32_t t4[4];
                ldsm_x4_t(t4, bd);
                Bf[2 * np][0] = t4[0]; Bf[2 * np][1] = t4[1];
                Bf[2 * np + 1][0] = t4[2]; Bf[2 * np + 1][1] = t4[3];
            }
#pragma unroll
            for (int mt = 0; mt < 4; mt++) {
                uint32_t Af[4];
                uint32_t ad = aC + (uint32_t)mt * (16 * LDA * 2) + (uint32_t)ks * 32u;
                ldsm_x4(Af, ad);
#pragma unroll
                for (int nt = 0; nt < 4; nt++)
                    mma_h(acc[mt][nt], Af, Bf[nt][0], Bf[nt][1]);
            }
        }
    }

    // -------- epilogue --------
    const int rbase = m0 + wm * 64;
    const int cbase = n0 + wn * 32;
#pragma unroll
    for (int mt = 0; mt < 4; mt++)
#pragma unroll
        for (int nt = 0; nt < 4; nt++) {
#pragma unroll
            for (int half = 0; half < 2; half++) {
                int r = rbase + mt * 16 + (lane >> 2) + half * 8;
                int cc = cbase + nt * 8 + (lane & 3) * 2;
                float2 v;
                v.x = acc[mt][nt][half * 2 + 0];
                v.y = acc[mt][nt][half * 2 + 1];
                if (MODE & MD_BIAS) {
                    float2 bb = *reinterpret_cast<const float2*>(bias + cc);
                    v.x += bb.x; v.y += bb.y;
                }
                if (MODE & MD_RELU) {
                    v.x = fmaxf(v.x, 0.f); v.y = fmaxf(v.y, 0.f);
                }
                if (MODE & MD_RES) {
                    float2 rr = *reinterpret_cast<const float2*>(res + (size_t)r * N + cc);
                    v.x += rr.x; v.y += rr.y;
                }
                if (MODE & MD_SPLIT) {
                    size_t idx = ((size_t)r * N + cc) >> 1;
                    reinterpret_cast<uint32_t*>(Chi)[idx] = pack_h2(v.x, v.y);
                } else if (MODE & MD_QKV) {
                    // fused QKV -> single fp16 [B,H,S,HD]; q pre-scaled.
                    int which = cc >> 10;
                    int c1 = cc & 1023;
                    float* dstf = which == 0 ? C : (which == 1 ? C2 : C3);
                    __half* dh = reinterpret_cast<__half*>(dstf);
                    if (which == 0) { v.x *= SCL2; v.y *= SCL2; }
                    int b_ = r >> 11, s_ = r & (Ss - 1);
                    int h_ = c1 >> 6, d_ = c1 & 63;
                    size_t idx = (((size_t)(b_ * Hh + h_) * Ss + s_) * HDd + d_) >> 1;
                    reinterpret_cast<uint32_t*>(dh)[idx] = pack_h2(v.x, v.y);
                } else {
                    *reinterpret_cast<float2*>(C + (size_t)r * N + cc) = v;
                }
            }
        }
}

// ========================= attention: single fp16 (R14) =====================
// q,k,v single fp16 in [B,H,S,64]; q pre-scaled by SCL2. o written single.
// CTA = 256 q rows, 8 warps, warp = 32 q rows (2 m16 tiles).
// 1-pass QK, 1-pass PV. 2-stage cp.async K|V ring.
constexpr int AALD  = 72;
constexpr int AKMAT = 64 * AALD * 2;      // 9216 (K); V at +AKMAT
constexpr int AST   = 2 * AKMAT;          // 18432 per stage
constexpr int AQOFF = 2 * AST;            // 36864
constexpr int AQMAT = 256 * AALD * 2;     // 36864
constexpr int ATT_SMEM = AQOFF + AQMAT;   // 73728

__global__ void __launch_bounds__(256, 1) attn_mma(
    const __half* __restrict__ qhp, const __half* __restrict__ khp,
    const __half* __restrict__ vhp, __half* __restrict__ oh)
{
    extern __shared__ char sm[];
    const uint32_t S0 = smem_u32(sm);
    const int tid = threadIdx.x, lane = tid & 31, w = tid >> 5;
    const int bh = blockIdx.y, q0 = blockIdx.x * 256;
    const int b_ = bh >> 4, h_ = bh & 15;

    const __half* qb = qhp + ((size_t)bh * Ss + q0) * HDd;
    const __half* kb = khp + (size_t)bh * Ss * HDd;
    const __half* vb = vhp + (size_t)bh * Ss * HDd;

    auto issue_kv = [&](int t) {
        uint32_t sb = S0 + (uint32_t)(t & 1) * AST;
        int k0 = t * 64;
#pragma unroll
        for (int i = 0; i < 2; i++) {
            int ch = tid + i * 256;
            int r = ch >> 3, s = ch & 7;
            uint32_t off = (uint32_t)r * 144u + (uint32_t)s * 16u;
            const size_t so_ = (size_t)(k0 + r) * HDd + s * 8;
            cp16(sb + off,         kb + so_);
            cp16(sb + AKMAT + off, vb + so_);
        }
        cp_commit();
    };

    {
#pragma unroll
        for (int i = 0; i < 8; i++) {
            int ch = tid + i * 256;
            int r = ch >> 3, s = ch & 7;
            uint32_t off = (uint32_t)r * 144u + (uint32_t)s * 16u;
            cp16(S0 + AQOFF + off, qb + (size_t)r * HDd + s * 8);
        }
        cp_commit();
    }
    issue_kv(0);
    cp_wait<0>();
    __syncthreads();

    uint32_t Qf[2][4][4];
#pragma unroll
    for (int mi = 0; mi < 2; mi++) {
        uint32_t base = S0 + AQOFF +
            (((uint32_t)(w * 32 + mi * 16 + (lane & 15))) * AALD +
             (uint32_t)(lane >> 4) * 8u) * 2u;
#pragma unroll
        for (int ks = 0; ks < 4; ks++)
            ldsm_x4(Qf[mi][ks], base + (uint32_t)ks * 32u);
    }

    float oa[2][8][4];
#pragma unroll
    for (int mi = 0; mi < 2; mi++)
#pragma unroll
        for (int nt = 0; nt < 8; nt++)
#pragma unroll
            for (int e = 0; e < 4; e++) oa[mi][nt][e] = 0.f;
    float mrow[2][2] = {{-1e30f, -1e30f}, {-1e30f, -1e30f}};
    float lrow[2][2] = {{0.f, 0.f}, {0.f, 0.f}};

    for (int t = 0; t < Ss / 64; t++) {
        if (t > 0) { cp_wait<0>(); __syncthreads(); }
        if (t + 1 < Ss / 64) issue_kv(t + 1);
        const uint32_t sbU = S0 + (uint32_t)(t & 1) * AST;

        float sc[2][8][4];
#pragma unroll
        for (int mi = 0; mi < 2; mi++)
#pragma unroll
            for (int nt = 0; nt < 8; nt++)
#pragma unroll
                for (int e = 0; e < 4; e++) sc[mi][nt][e] = 0.f;

        const uint32_t kfb = sbU +
            (((uint32_t)(lane & 7)) * AALD + (uint32_t)((lane >> 3) & 1) * 8u) * 2u +
            (uint32_t)(lane >> 4) * (8u * AALD * 2u);
#pragma unroll
        for (int nt = 0; nt < 8; nt += 2) {
#pragma unroll
            for (int ks = 0; ks < 4; ks++) {
                uint32_t kf[4];
                ldsm_x4(kf, kfb + ((uint32_t)nt * 8u * AALD + (uint32_t)ks * 16u) * 2u);
#pragma unroll
                for (int mi = 0; mi < 2; mi++) {
                    mma_h(sc[mi][nt],     Qf[mi][ks], kf[0], kf[1]);
                    mma_h(sc[mi][nt + 1], Qf[mi][ks], kf[2], kf[3]);
                }
            }
        }

#pragma unroll
        for (int mi = 0; mi < 2; mi++) {
            float mt0 = sc[mi][0][0], mt1 = sc[mi][0][2];
#pragma unroll
            for (int nt = 0; nt < 8; nt++) {
                mt0 = fmaxf(mt0, fmaxf(sc[mi][nt][0], sc[mi][nt][1]));
                mt1 = fmaxf(mt1, fmaxf(sc[mi][nt][2], sc[mi][nt][3]));
            }
            mt0 = fmaxf(mt0, __shfl_xor_sync(0xffffffffu, mt0, 1));
            mt0 = fmaxf(mt0, __shfl_xor_sync(0xffffffffu, mt0, 2));
            mt1 = fmaxf(mt1, __shfl_xor_sync(0xffffffffu, mt1, 1));
            mt1 = fmaxf(mt1, __shfl_xor_sync(0xffffffffu, mt1, 2));
            float mn0 = fmaxf(mrow[mi][0], mt0), mn1 = fmaxf(mrow[mi][1], mt1);
            float c0 = ex2(mrow[mi][0] - mn0), c1 = ex2(mrow[mi][1] - mn1);
            mrow[mi][0] = mn0; mrow[mi][1] = mn1;

            float ls0 = 0.f, ls1 = 0.f;
#pragma unroll
            for (int nt = 0; nt < 8; nt++) {
                sc[mi][nt][0] = ex2(sc[mi][nt][0] - mn0);
                sc[mi][nt][1] = ex2(sc[mi][nt][1] - mn0);
                sc[mi][nt][2] = ex2(sc[mi][nt][2] - mn1);
                sc[mi][nt][3] = ex2(sc[mi][nt][3] - mn1);
                ls0 += sc[mi][nt][0] + sc[mi][nt][1];
                ls1 += sc[mi][nt][2] + sc[mi][nt][3];
            }
            ls0 += __shfl_xor_sync(0xffffffffu, ls0, 1);
            ls0 += __shfl_xor_sync(0xffffffffu, ls0, 2);
            ls1 += __shfl_xor_sync(0xffffffffu, ls1, 1);
            ls1 += __shfl_xor_sync(0xffffffffu, ls1, 2);
            lrow[mi][0] = lrow[mi][0] * c0 + ls0;
            lrow[mi][1] = lrow[mi][1] * c1 + ls1;
#pragma unroll
            for (int nt = 0; nt < 8; nt++) {
                oa[mi][nt][0] *= c0; oa[mi][nt][1] *= c0;
                oa[mi][nt][2] *= c1; oa[mi][nt][3] *= c1;
            }
        }

        const uint32_t vfb = sbU + (uint32_t)AKMAT +
            ((uint32_t)(lane & 15)) * (uint32_t)AALD * 2u +
            (uint32_t)(lane >> 4) * 16u;
#pragma unroll
        for (int kk = 0; kk < 4; kk++) {
            uint32_t Pf[2][4];
#pragma unroll
            for (int mi = 0; mi < 2; mi++) {
#pragma unroll
                for (int half = 0; half < 2; half++) {
                    Pf[mi][2 * half + 0] = pack_h2(sc[mi][2 * kk + half][0],
                                                   sc[mi][2 * kk + half][1]);
                    Pf[mi][2 * half + 1] = pack_h2(sc[mi][2 * kk + half][2],
                                                   sc[mi][2 * kk + half][3]);
                }
            }
#pragma unroll
            for (int nt = 0; nt < 8; nt += 2) {
                uint32_t vf[4];
                ldsm_x4_t(vf, vfb + ((uint32_t)kk * 16u * AALD + (uint32_t)nt * 8u) * 2u);
#pragma unroll
                for (int mi = 0; mi < 2; mi++) {
                    mma_h(oa[mi][nt],     Pf[mi], vf[0], vf[1]);
                    mma_h(oa[mi][nt + 1], Pf[mi], vf[2], vf[3]);
                }
            }
        }
    }

    // ---- epilogue: normalize, write single fp16 [B,S,D] ----
#pragma unroll
    for (int mi = 0; mi < 2; mi++) {
        float il0 = 1.0f / lrow[mi][0], il1 = 1.0f / lrow[mi][1];
        int sr0 = q0 + w * 32 + mi * 16 + (lane >> 2);
        int sr1 = sr0 + 8;
#pragma unroll
        for (int nt = 0; nt < 8; nt++) {
            int col = h_ * HDd + nt * 8 + (lane & 3) * 2;
            size_t i0 = (((size_t)(b_ * Ss + sr0)) * Dd + col) >> 1;
            size_t i1 = (((size_t)(b_ * Ss + sr1)) * Dd + col) >> 1;
            reinterpret_cast<uint32_t*>(oh)[i0] =
                pack_h2(oa[mi][nt][0] * il0, oa[mi][nt][1] * il0);
            reinterpret_cast<uint32_t*>(oh)[i1] =
                pack_h2(oa[mi][nt][2] * il1, oa[mi][nt][3] * il1);
        }
    }
}

// ========================= launch ===========================
extern "C" void kernel_launch(void* const* d_in, const int* in_sizes, int n_in,
                              void* d_out, int out_size)
{
    const float* x     = (const float*)d_in[0];
    const float* ln1_g = (const float*)d_in[1];
    const float* ln1_b = (const float*)d_in[2];
    const float* ln2_g = (const float*)d_in[3];
    const float* ln2_b = (const float*)d_in[4];
    const float* Wq    = (const float*)d_in[5];
    const float* Wk    = (const float*)d_in[6];
    const float* Wv    = (const float*)d_in[7];
    const float* Wo    = (const float*)d_in[8];
    const float* W1    = (const float*)d_in[9];
    const float* b1    = (const float*)d_in[10];
    const float* W2    = (const float*)d_in[11];
    const float* b2    = (const float*)d_in[12];
    float* out = (float*)d_out;

    float *x2;
    __half *qh, *kh, *vh, *xh, *oh, *fh, *wgt;
    cudaGetSymbolAddress((void**)&x2,  g_x2);
    cudaGetSymbolAddress((void**)&qh,  g_qh);
    cudaGetSymbolAddress((void**)&kh,  g_kh);
    cudaGetSymbolAddress((void**)&vh,  g_vh);
    cudaGetSymbolAddress((void**)&xh,  g_xh);
    cudaGetSymbolAddress((void**)&oh,  g_oh);
    cudaGetSymbolAddress((void**)&fh,  g_fh);
    cudaGetSymbolAddress((void**)&wgt, g_w);

    cudaFuncSetAttribute(gemm_mma<MD_QKV>, cudaFuncAttributeMaxDynamicSharedMemorySize, GEMM_SMEM);
    cudaFuncSetAttribute(gemm_mma<MD_RES>, cudaFuncAttributeMaxDynamicSharedMemorySize, GEMM_SMEM);
    cudaFuncSetAttribute(gemm_mma<MD_BIAS | MD_RELU | MD_SPLIT>, cudaFuncAttributeMaxDynamicSharedMemorySize, GEMM_SMEM);
    cudaFuncSetAttribute(gemm_mma<MD_BIAS | MD_RELU | MD_RES>, cudaFuncAttributeMaxDynamicSharedMemorySize, GEMM_SMEM);
    cudaFuncSetAttribute(attn_mma, cudaFuncAttributeMaxDynamicSharedMemorySize, ATT_SMEM);

    dim3 blk(256);
    dim3 gQKV(3072 / 128, Mm / 128);
    dim3 gD(Dd / 128, Mm / 128);
    dim3 gF(FFf / 128, Mm / 128);
    const int QD4 = Dd * Dd / 4, FD4 = Dd * FFf / 4;

    // weight conversions (single fp16)
    wsplit_strided_kernel<<<QD4 / 256, blk>>>(Wq, wgt + WQKV, 0,    QD4);
    wsplit_strided_kernel<<<QD4 / 256, blk>>>(Wk, wgt + WQKV, 1024, QD4);
    wsplit_strided_kernel<<<QD4 / 256, blk>>>(Wv, wgt + WQKV, 2048, QD4);
    wsplit_kernel<<<QD4 / 256, blk>>>(Wo, wgt + WOO, QD4);
    wsplit_kernel<<<FD4 / 256, blk>>>(W1, wgt + W1O, FD4);
    wsplit_kernel<<<FD4 / 256, blk>>>(W2, wgt + W2O, FD4);

    // h = LN1(x) -> single fp16
    ln_h_kernel<<<Mm, blk>>>(x, ln1_g, ln1_b, xh);
    // q|k|v = h @ Wqkv -> single fp16 [B,H,S,HD] (q pre-scaled by SCL2)
    gemm_mma<MD_QKV><<<gQKV, blk, GEMM_SMEM>>>(xh, wgt + WQKV,
        nullptr, nullptr, (float*)qh, (float*)kh, (float*)vh, nullptr, 3072, Dd);
    // attention -> single fp16 o
    attn_mma<<<dim3(Ss / 256, Bb * Hh), blk, ATT_SMEM>>>(qh, kh, vh, oh);
    // x2 = x + o @ Wo  (fp32)
    gemm_mma<MD_RES><<<gD, blk, GEMM_SMEM>>>(oh, wgt + WOO,
        nullptr, x, x2, nullptr, nullptr, nullptr, Dd, Dd);
    // h = LN2(x2) -> single fp16
    ln_h_kernel<<<Mm, blk>>>(x2, ln2_g, ln2_b, xh);
    // ff1 = relu(h @ W1 + b1) -> single fp16
    gemm_mma<MD_BIAS | MD_RELU | MD_SPLIT><<<gF, blk, GEMM_SMEM>>>(xh,
        wgt + W1O, b1, nullptr, nullptr, nullptr, nullptr, fh, FFf, Dd);
    // out = x2 + relu(ff1 @ W2 + b2)  (fp32)
    gemm_mma<MD_BIAS | MD_RELU | MD_RES><<<gD, blk, GEMM_SMEM>>>(fh,
        wgt + W2O, b2, x2, out, nullptr, nullptr, nullptr, Dd, FFf);
}